// round 1
// baseline (speedup 1.0000x reference)
#include <cuda_runtime.h>

#define BB 8
#define CC 256
#define HWN 1024
#define NI 8
#define NH 4
#define HD 64
#define NB (NI*BB)   // 64 (instance,batch) pairs

// Scratch (static device globals; no allocations anywhere)
__device__ float g_w3[3*CC*CC];          // concat(w_q,w_k,w_v) [768][256]
__device__ float g_b3[3*CC];
__device__ float g_mask[BB*NI*HWN];      // [b][i][n] softmaxed instance masks
__device__ float g_qkv[NB*3*CC*HWN];     // [(i*B+b)][row 0..767][n]  (~201MB)
__device__ float g_att[NB*CC*HWN];       // per-instance attention output (~67MB)

// ---------------------------------------------------------------------------
// 1) instance conv + softmax over instance axis
// ---------------------------------------------------------------------------
__global__ __launch_bounds__(256) void mask_kernel(
    const float* __restrict__ x, const float* __restrict__ w_inst,
    const float* __restrict__ b_inst)
{
    __shared__ float ws[NI*CC];
    int tid = threadIdx.x;
    for (int k = tid; k < NI*CC; k += 256) ws[k] = w_inst[k];
    __syncthreads();

    int gid = blockIdx.x*256 + tid;          // 0..8191 = B*HW
    int b = gid >> 10, n = gid & 1023;
    float acc[NI];
    #pragma unroll
    for (int i = 0; i < NI; i++) acc[i] = 0.f;
    const float* xp = x + (size_t)b*CC*HWN + n;
    for (int c = 0; c < CC; c++) {
        float xv = xp[c*HWN];
        #pragma unroll
        for (int i = 0; i < NI; i++) acc[i] = fmaf(ws[i*CC + c], xv, acc[i]);
    }
    float m = -1e30f;
    #pragma unroll
    for (int i = 0; i < NI; i++) { acc[i] += b_inst[i]; m = fmaxf(m, acc[i]); }
    float s = 0.f;
    #pragma unroll
    for (int i = 0; i < NI; i++) { acc[i] = __expf(acc[i] - m); s += acc[i]; }
    float inv = 1.f / s;
    #pragma unroll
    for (int i = 0; i < NI; i++) g_mask[(b*NI + i)*HWN + n] = acc[i]*inv;
}

// ---------------------------------------------------------------------------
// 2a) concat weights/biases into one [768,256] matrix
// ---------------------------------------------------------------------------
__global__ __launch_bounds__(256) void prep_kernel(
    const float* __restrict__ wq, const float* __restrict__ bq,
    const float* __restrict__ wk, const float* __restrict__ bk,
    const float* __restrict__ wv, const float* __restrict__ bv)
{
    int idx = blockIdx.x*256 + threadIdx.x;
    if (idx < CC*CC) {
        g_w3[idx]           = wq[idx];
        g_w3[CC*CC + idx]   = wk[idx];
        g_w3[2*CC*CC + idx] = wv[idx];
    }
    if (idx < CC) { g_b3[idx] = bq[idx]; g_b3[CC+idx] = bk[idx]; g_b3[2*CC+idx] = bv[idx]; }
}

// ---------------------------------------------------------------------------
// 2b) QKV GEMM: per (i,b): [768,256] @ (x * mask)[256,1024] + bias
//     64x64x16 tile, 256 threads, 4x4 micro
// ---------------------------------------------------------------------------
__global__ __launch_bounds__(256) void qkv_gemm(const float* __restrict__ x)
{
    __shared__ float As[16][65];   // [c_local][o_local]
    __shared__ float Bs[16][64];   // [c_local][n_local]
    __shared__ float ms[64];

    int ib = blockIdx.z;                  // i*8 + b
    int b  = ib & 7;
    int i  = ib >> 3;
    int n0 = blockIdx.x * 64;
    int o0 = blockIdx.y * 64;
    int tid = threadIdx.x;
    int tx = tid & 15, ty = tid >> 4;

    if (tid < 64) ms[tid] = g_mask[(b*NI + i)*HWN + n0 + tid];
    __syncthreads();

    float acc[4][4];
    #pragma unroll
    for (int u = 0; u < 4; u++)
        #pragma unroll
        for (int w = 0; w < 4; w++) acc[u][w] = 0.f;

    const float* xb = x + (size_t)b*CC*HWN;

    for (int kt = 0; kt < CC; kt += 16) {
        #pragma unroll
        for (int r = 0; r < 4; r++) {
            int idx = r*256 + tid;
            int ol = idx >> 4, cl = idx & 15;
            As[cl][ol] = g_w3[(o0 + ol)*CC + kt + cl];
        }
        #pragma unroll
        for (int r = 0; r < 4; r++) {
            int idx = r*256 + tid;
            int cl = idx >> 6, nl = idx & 63;
            Bs[cl][nl] = xb[(kt + cl)*HWN + n0 + nl] * ms[nl];
        }
        __syncthreads();
        #pragma unroll
        for (int kk = 0; kk < 16; kk++) {
            float a0 = As[kk][ty*4+0], a1 = As[kk][ty*4+1];
            float a2 = As[kk][ty*4+2], a3 = As[kk][ty*4+3];
            float4 bv = *(const float4*)&Bs[kk][tx*4];
            acc[0][0] = fmaf(a0, bv.x, acc[0][0]); acc[0][1] = fmaf(a0, bv.y, acc[0][1]);
            acc[0][2] = fmaf(a0, bv.z, acc[0][2]); acc[0][3] = fmaf(a0, bv.w, acc[0][3]);
            acc[1][0] = fmaf(a1, bv.x, acc[1][0]); acc[1][1] = fmaf(a1, bv.y, acc[1][1]);
            acc[1][2] = fmaf(a1, bv.z, acc[1][2]); acc[1][3] = fmaf(a1, bv.w, acc[1][3]);
            acc[2][0] = fmaf(a2, bv.x, acc[2][0]); acc[2][1] = fmaf(a2, bv.y, acc[2][1]);
            acc[2][2] = fmaf(a2, bv.z, acc[2][2]); acc[2][3] = fmaf(a2, bv.w, acc[2][3]);
            acc[3][0] = fmaf(a3, bv.x, acc[3][0]); acc[3][1] = fmaf(a3, bv.y, acc[3][1]);
            acc[3][2] = fmaf(a3, bv.z, acc[3][2]); acc[3][3] = fmaf(a3, bv.w, acc[3][3]);
        }
        __syncthreads();
    }

    #pragma unroll
    for (int u = 0; u < 4; u++) {
        int o = o0 + ty*4 + u;
        float bias = g_b3[o];
        float4 v;
        v.x = acc[u][0] + bias; v.y = acc[u][1] + bias;
        v.z = acc[u][2] + bias; v.w = acc[u][3] + bias;
        *(float4*)&g_qkv[((size_t)ib*768 + o)*HWN + n0 + tx*4] = v;
    }
}

// ---------------------------------------------------------------------------
// 3) l2-normalize q and k rows (rows o in [0,512) per ib), length 1024
// ---------------------------------------------------------------------------
__global__ __launch_bounds__(256) void l2norm_kernel()
{
    int row = blockIdx.x;                 // NB*512 rows
    int ib = row >> 9, o = row & 511;
    float* p = &g_qkv[((size_t)ib*768 + o)*HWN];
    int tid = threadIdx.x;
    float4 v = ((float4*)p)[tid];
    float ss = v.x*v.x + v.y*v.y + v.z*v.z + v.w*v.w;
    #pragma unroll
    for (int off = 16; off; off >>= 1) ss += __shfl_xor_sync(0xffffffffu, ss, off);
    __shared__ float wsum[8];
    if ((tid & 31) == 0) wsum[tid >> 5] = ss;
    __syncthreads();
    float tot = wsum[0]+wsum[1]+wsum[2]+wsum[3]+wsum[4]+wsum[5]+wsum[6]+wsum[7];
    float inv = 1.f / fmaxf(sqrtf(tot), 1e-12f);
    v.x *= inv; v.y *= inv; v.z *= inv; v.w *= inv;
    ((float4*)p)[tid] = v;
}

// ---------------------------------------------------------------------------
// 4) flash attention per (ib, head, 64-token i-tile), fp32, 48KB static smem
//    V tile uses XOR swizzle for conflict-free strided reads.
// ---------------------------------------------------------------------------
__device__ __forceinline__ int VSW(int c, int t) {
    return t ^ (c & 31) ^ ((c & 32) >> 1);
}

__global__ __launch_bounds__(256) void flash_kernel()
{
    __shared__ float q_s[64*64];    // [c][ti]
    __shared__ float kp_s[64*64];   // k tile [c][tj], later P [ti][tj]
    __shared__ float v_s[64*64];    // [c][tj] XOR-swizzled

    int bx = blockIdx.x;
    int it = bx & 15;
    int h  = (bx >> 4) & 3;
    int ib = bx >> 6;
    int i0 = it * 64;

    const float* qg = &g_qkv[((size_t)ib*768 +        h*HD)*HWN];
    const float* kg = &g_qkv[((size_t)ib*768 + 256  + h*HD)*HWN];
    const float* vg = &g_qkv[((size_t)ib*768 + 512  + h*HD)*HWN];

    int tid = threadIdx.x;
    int tx = tid & 15, ty = tid >> 4;

    #pragma unroll
    for (int r = 0; r < 16; r++) {
        int idx = r*256 + tid;
        int c = idx >> 6, t = idx & 63;
        q_s[c*64 + t] = qg[c*HWN + i0 + t];
    }

    float o[4][4];
    float mrun[4], lrun[4];
    #pragma unroll
    for (int u = 0; u < 4; u++) {
        mrun[u] = -1e30f; lrun[u] = 0.f;
        #pragma unroll
        for (int w = 0; w < 4; w++) o[u][w] = 0.f;
    }
    const float scale = 0.125f;   // 1/sqrt(64)

    for (int j0 = 0; j0 < HWN; j0 += 64) {
        __syncthreads();  // previous-tile P/V reads done (and Q visible on iter 0)
        #pragma unroll
        for (int r = 0; r < 16; r++) {
            int idx = r*256 + tid;
            int c = idx >> 6, t = idx & 63;
            kp_s[c*64 + t]        = kg[c*HWN + j0 + t];
            v_s[c*64 + VSW(c, t)] = vg[c*HWN + j0 + t];
        }
        __syncthreads();

        // S = scale * Q^T K
        float s[4][4];
        #pragma unroll
        for (int u = 0; u < 4; u++)
            #pragma unroll
            for (int w = 0; w < 4; w++) s[u][w] = 0.f;
        #pragma unroll 8
        for (int c = 0; c < 64; c++) {
            float4 qv = *(const float4*)&q_s[c*64 + ty*4];
            float4 kv = *(const float4*)&kp_s[c*64 + tx*4];
            s[0][0] = fmaf(qv.x, kv.x, s[0][0]); s[0][1] = fmaf(qv.x, kv.y, s[0][1]);
            s[0][2] = fmaf(qv.x, kv.z, s[0][2]); s[0][3] = fmaf(qv.x, kv.w, s[0][3]);
            s[1][0] = fmaf(qv.y, kv.x, s[1][0]); s[1][1] = fmaf(qv.y, kv.y, s[1][1]);
            s[1][2] = fmaf(qv.y, kv.z, s[1][2]); s[1][3] = fmaf(qv.y, kv.w, s[1][3]);
            s[2][0] = fmaf(qv.z, kv.x, s[2][0]); s[2][1] = fmaf(qv.z, kv.y, s[2][1]);
            s[2][2] = fmaf(qv.z, kv.z, s[2][2]); s[2][3] = fmaf(qv.z, kv.w, s[2][3]);
            s[3][0] = fmaf(qv.w, kv.x, s[3][0]); s[3][1] = fmaf(qv.w, kv.y, s[3][1]);
            s[3][2] = fmaf(qv.w, kv.z, s[3][2]); s[3][3] = fmaf(qv.w, kv.w, s[3][3]);
        }

        // online softmax per row (row owned by 16-lane group sharing ty)
        #pragma unroll
        for (int u = 0; u < 4; u++) {
            #pragma unroll
            for (int w = 0; w < 4; w++) s[u][w] *= scale;
            float mt = fmaxf(fmaxf(s[u][0], s[u][1]), fmaxf(s[u][2], s[u][3]));
            #pragma unroll
            for (int off = 1; off < 16; off <<= 1)
                mt = fmaxf(mt, __shfl_xor_sync(0xffffffffu, mt, off));
            float mnew = fmaxf(mrun[u], mt);
            float al = __expf(mrun[u] - mnew);
            mrun[u] = mnew;
            float rs = 0.f;
            #pragma unroll
            for (int w = 0; w < 4; w++) { s[u][w] = __expf(s[u][w] - mnew); rs += s[u][w]; }
            #pragma unroll
            for (int off = 1; off < 16; off <<= 1)
                rs += __shfl_xor_sync(0xffffffffu, rs, off);
            lrun[u] = lrun[u]*al + rs;
            #pragma unroll
            for (int w = 0; w < 4; w++) o[u][w] *= al;
        }

        __syncthreads();  // all K reads done before P overwrites kp_s
        #pragma unroll
        for (int u = 0; u < 4; u++)
            #pragma unroll
            for (int w = 0; w < 4; w++)
                kp_s[(ty*4 + u)*64 + tx*4 + w] = s[u][w];
        __syncthreads();

        // O += P @ V^T   (o[ti][c], contraction over tj)
        #pragma unroll 8
        for (int t = 0; t < 64; t++) {
            float p0 = kp_s[(ty*4+0)*64 + t];
            float p1 = kp_s[(ty*4+1)*64 + t];
            float p2 = kp_s[(ty*4+2)*64 + t];
            float p3 = kp_s[(ty*4+3)*64 + t];
            float v0 = v_s[(tx*4+0)*64 + VSW(tx*4+0, t)];
            float v1 = v_s[(tx*4+1)*64 + VSW(tx*4+1, t)];
            float v2 = v_s[(tx*4+2)*64 + VSW(tx*4+2, t)];
            float v3 = v_s[(tx*4+3)*64 + VSW(tx*4+3, t)];
            o[0][0] = fmaf(p0, v0, o[0][0]); o[0][1] = fmaf(p0, v1, o[0][1]);
            o[0][2] = fmaf(p0, v2, o[0][2]); o[0][3] = fmaf(p0, v3, o[0][3]);
            o[1][0] = fmaf(p1, v0, o[1][0]); o[1][1] = fmaf(p1, v1, o[1][1]);
            o[1][2] = fmaf(p1, v2, o[1][2]); o[1][3] = fmaf(p1, v3, o[1][3]);
            o[2][0] = fmaf(p2, v0, o[2][0]); o[2][1] = fmaf(p2, v1, o[2][1]);
            o[2][2] = fmaf(p2, v2, o[2][2]); o[2][3] = fmaf(p2, v3, o[2][3]);
            o[3][0] = fmaf(p3, v0, o[3][0]); o[3][1] = fmaf(p3, v1, o[3][1]);
            o[3][2] = fmaf(p3, v2, o[3][2]); o[3][3] = fmaf(p3, v3, o[3][3]);
        }
    }

    // stage normalized output through smem for coalesced global write
    __syncthreads();
    #pragma unroll
    for (int u = 0; u < 4; u++) {
        float inv = 1.f / lrun[u];
        #pragma unroll
        for (int w = 0; w < 4; w++) {
            int c = tx*4 + w, t = ty*4 + u;
            v_s[c*64 + VSW(c, t)] = o[u][w] * inv;
        }
    }
    __syncthreads();
    float* og = &g_att[((size_t)ib*CC + h*HD)*HWN];
    #pragma unroll
    for (int r = 0; r < 16; r++) {
        int idx = r*256 + tid;
        int c = idx >> 6, t = idx & 63;
        og[c*HWN + i0 + t] = v_s[c*64 + VSW(c, t)];
    }
}

// ---------------------------------------------------------------------------
// 5) out[b,c,n] = sum_i att[i,b,c,n] * mask[b,i,n]  (deterministic order)
// ---------------------------------------------------------------------------
__global__ __launch_bounds__(256) void out_kernel(float* __restrict__ out)
{
    int idx = blockIdx.x*256 + threadIdx.x;   // < B*C*HW = 2^21
    int b = idx >> 18;                        // C*HW = 262144
    int rem = idx & 262143;
    int n = rem & 1023;
    float acc = 0.f;
    #pragma unroll
    for (int i = 0; i < NI; i++) {
        acc = fmaf(g_att[(size_t)(i*BB + b)*262144 + rem],
                   g_mask[(b*NI + i)*HWN + n], acc);
    }
    out[idx] = acc;
}

// ---------------------------------------------------------------------------
extern "C" void kernel_launch(void* const* d_in, const int* in_sizes, int n_in,
                              void* d_out, int out_size)
{
    const float* x      = (const float*)d_in[0];
    const float* w_inst = (const float*)d_in[1];
    const float* b_inst = (const float*)d_in[2];
    const float* w_q    = (const float*)d_in[3];
    const float* b_q    = (const float*)d_in[4];
    const float* w_k    = (const float*)d_in[5];
    const float* b_k    = (const float*)d_in[6];
    const float* w_v    = (const float*)d_in[7];
    const float* b_v    = (const float*)d_in[8];
    float* out = (float*)d_out;

    mask_kernel<<<32, 256>>>(x, w_inst, b_inst);
    prep_kernel<<<(CC*CC + 255)/256, 256>>>(w_q, b_q, w_k, b_k, w_v, b_v);
    qkv_gemm<<<dim3(16, 12, NB), 256>>>(x);
    l2norm_kernel<<<NB*512, 256>>>();
    flash_kernel<<<NB*NH*16, 256>>>();
    out_kernel<<<(BB*CC*HWN)/256, 256>>>(out);
}

// round 3
// speedup vs baseline: 1.1707x; 1.1707x over previous
#include <cuda_runtime.h>
#include <cuda_bf16.h>
#include <cstdint>

#define BB 8
#define CC 256
#define HWN 1024
#define NI 8
#define NH 4
#define HD 64
#define NB (NI*BB)   // 64 (instance,batch) pairs

// Scratch (static device globals; no allocations anywhere)
__device__ float g_w3[3*CC*CC];          // concat(w_q,w_k,w_v) [768][256]
__device__ float g_b3[3*CC];
__device__ float g_mask[BB*NI*HWN];      // [b][i][n] softmaxed instance masks
__device__ float g_qkv[NB*3*CC*HWN];     // [(i*B+b)][row 0..767][n]  (~201MB)
__device__ float g_att[NB*CC*HWN];       // per-instance attention output (~67MB)

// ===========================================================================
// mma.sync / ldmatrix helpers (baseline PTX — works at compute_103 target)
// ===========================================================================
__device__ __forceinline__ uint32_t smem_to_u32(const void* p) {
    uint32_t a;
    asm("{ .reg .u64 t; cvta.to.shared.u64 t, %1; cvt.u32.u64 %0, t; }"
        : "=r"(a) : "l"(p));
    return a;
}
__device__ __forceinline__ void ldsm4(uint32_t* r, uint32_t addr) {
    asm volatile("ldmatrix.sync.aligned.m8n8.x4.shared.b16 {%0,%1,%2,%3}, [%4];"
        : "=r"(r[0]), "=r"(r[1]), "=r"(r[2]), "=r"(r[3]) : "r"(addr));
}
__device__ __forceinline__ void ldsm4t(uint32_t* r, uint32_t addr) {
    asm volatile("ldmatrix.sync.aligned.m8n8.x4.trans.shared.b16 {%0,%1,%2,%3}, [%4];"
        : "=r"(r[0]), "=r"(r[1]), "=r"(r[2]), "=r"(r[3]) : "r"(addr));
}
__device__ __forceinline__ void mma_bf16(float* c, const uint32_t* a, const uint32_t* b) {
    asm volatile(
        "mma.sync.aligned.m16n8k16.row.col.f32.bf16.bf16.f32 "
        "{%0,%1,%2,%3}, {%4,%5,%6,%7}, {%8,%9}, {%0,%1,%2,%3};"
        : "+f"(c[0]), "+f"(c[1]), "+f"(c[2]), "+f"(c[3])
        : "r"(a[0]), "r"(a[1]), "r"(a[2]), "r"(a[3]), "r"(b[0]), "r"(b[1]));
}
__device__ __forceinline__ uint32_t pack2bf(float a, float b) {
    __nv_bfloat162 t = __floats2bfloat162_rn(a, b);
    return *(uint32_t*)&t;
}

// ---------------------------------------------------------------------------
// 1) instance conv + softmax over instance axis
// ---------------------------------------------------------------------------
__global__ __launch_bounds__(256) void mask_kernel(
    const float* __restrict__ x, const float* __restrict__ w_inst,
    const float* __restrict__ b_inst)
{
    __shared__ float ws[NI*CC];
    int tid = threadIdx.x;
    for (int k = tid; k < NI*CC; k += 256) ws[k] = w_inst[k];
    __syncthreads();

    int gid = blockIdx.x*256 + tid;          // 0..8191 = B*HW
    int b = gid >> 10, n = gid & 1023;
    float acc[NI];
    #pragma unroll
    for (int i = 0; i < NI; i++) acc[i] = 0.f;
    const float* xp = x + (size_t)b*CC*HWN + n;
    for (int c = 0; c < CC; c++) {
        float xv = xp[c*HWN];
        #pragma unroll
        for (int i = 0; i < NI; i++) acc[i] = fmaf(ws[i*CC + c], xv, acc[i]);
    }
    float m = -1e30f;
    #pragma unroll
    for (int i = 0; i < NI; i++) { acc[i] += b_inst[i]; m = fmaxf(m, acc[i]); }
    float s = 0.f;
    #pragma unroll
    for (int i = 0; i < NI; i++) { acc[i] = __expf(acc[i] - m); s += acc[i]; }
    float inv = 1.f / s;
    #pragma unroll
    for (int i = 0; i < NI; i++) g_mask[(b*NI + i)*HWN + n] = acc[i]*inv;
}

// ---------------------------------------------------------------------------
// 2a) concat weights/biases into one [768,256] matrix
// ---------------------------------------------------------------------------
__global__ __launch_bounds__(256) void prep_kernel(
    const float* __restrict__ wq, const float* __restrict__ bq,
    const float* __restrict__ wk, const float* __restrict__ bk,
    const float* __restrict__ wv, const float* __restrict__ bv)
{
    int idx = blockIdx.x*256 + threadIdx.x;
    if (idx < CC*CC) {
        g_w3[idx]           = wq[idx];
        g_w3[CC*CC + idx]   = wk[idx];
        g_w3[2*CC*CC + idx] = wv[idx];
    }
    if (idx < CC) { g_b3[idx] = bq[idx]; g_b3[CC+idx] = bk[idx]; g_b3[2*CC+idx] = bv[idx]; }
}

// ---------------------------------------------------------------------------
// 2b) QKV GEMM via mma.sync bf16 hi/lo split.
//     Per CTA: D[128 o, 128 n] = W[128,256] @ (x*mask)[256,128] + bias
//     A = W, native [o][k] rows (128B, swizzled). ldmatrix non-trans.
//     B = masked X, native [c][n] rows (256B, swizzled). ldmatrix .trans
//     gives the col-major k x n fragment directly (no transpose pass).
// ---------------------------------------------------------------------------
#define QKV_SMEM_BYTES 65536   // AH 16K | AL 16K | BH 16K | BL 16K

__global__ __launch_bounds__(256) void qkv_mma(const float* __restrict__ x)
{
    extern __shared__ char sm[];
    __shared__ float s_msk[128];
    __shared__ float s_bias[128];

    const uint32_t AH = 0, AL = 16384, BH = 32768, BL = 49152;
    uint32_t sbase = smem_to_u32(sm);

    int tid = threadIdx.x;
    int wid = tid >> 5, lane = tid & 31;
    int n0 = blockIdx.x * 128;
    int o0 = blockIdx.y * 128;
    int ib = blockIdx.z;
    int b = ib & 7, inst = ib >> 3;

    if (tid < 128) s_msk[tid] = g_mask[(b*NI + inst)*HWN + n0 + tid];
    else           s_bias[tid-128] = g_b3[o0 + tid - 128];

    float acc[2][8][4];
    #pragma unroll
    for (int mt = 0; mt < 2; mt++)
        #pragma unroll
        for (int nt = 0; nt < 8; nt++)
            #pragma unroll
            for (int q = 0; q < 4; q++) acc[mt][nt][q] = 0.f;

    const int m0w = (wid & 3) * 32;
    const int n0w = (wid >> 2) * 64;

    #pragma unroll 1
    for (int kc = 0; kc < 4; kc++) {
        __syncthreads();   // prev-chunk fragment reads done (iter0: s_msk/s_bias ready)

        // ---- A tile: W[o0+m][kc*64 + c], hi/lo split, swizzled [m][k] rows (128B)
        const float* wp = g_w3 + (size_t)o0*CC + kc*64;
        #pragma unroll
        for (int i = 0; i < 8; i++) {
            int e = i*256 + tid;
            int m = e >> 4, c = (e & 15) * 4;
            float4 w4 = *(const float4*)&wp[(size_t)m*CC + c];
            __nv_bfloat16 h0 = __float2bfloat16_rn(w4.x);
            __nv_bfloat16 h1 = __float2bfloat16_rn(w4.y);
            __nv_bfloat16 h2 = __float2bfloat16_rn(w4.z);
            __nv_bfloat16 h3 = __float2bfloat16_rn(w4.w);
            uint2 hi, lo;
            hi.x = pack2bf(__bfloat162float(h0), __bfloat162float(h1));
            hi.y = pack2bf(__bfloat162float(h2), __bfloat162float(h3));
            // re-pack exact hi bits (pack2bf re-rounds; values already exact bf16)
            lo.x = pack2bf(w4.x - __bfloat162float(h0), w4.y - __bfloat162float(h1));
            lo.y = pack2bf(w4.z - __bfloat162float(h2), w4.w - __bfloat162float(h3));
            uint32_t off = (uint32_t)m*128 + (((uint32_t)c*2) ^ (((uint32_t)m & 7) << 4));
            *(uint2*)(sm + AH + off) = hi;
            *(uint2*)(sm + AL + off) = lo;
        }
        // ---- B tile: (x*mask)[kc*64 + c][n0 + n], hi/lo split, swizzled [c][n] rows (256B)
        const float* xp = x + ((size_t)b*CC + kc*64)*HWN + n0;
        #pragma unroll
        for (int i = 0; i < 8; i++) {
            int e = i*256 + tid;
            int c = e >> 5, n4 = (e & 31) * 4;
            float4 v = *(const float4*)&xp[(size_t)c*HWN + n4];
            v.x *= s_msk[n4+0]; v.y *= s_msk[n4+1];
            v.z *= s_msk[n4+2]; v.w *= s_msk[n4+3];
            __nv_bfloat16 h0 = __float2bfloat16_rn(v.x);
            __nv_bfloat16 h1 = __float2bfloat16_rn(v.y);
            __nv_bfloat16 h2 = __float2bfloat16_rn(v.z);
            __nv_bfloat16 h3 = __float2bfloat16_rn(v.w);
            uint2 hi, lo;
            hi.x = pack2bf(__bfloat162float(h0), __bfloat162float(h1));
            hi.y = pack2bf(__bfloat162float(h2), __bfloat162float(h3));
            lo.x = pack2bf(v.x - __bfloat162float(h0), v.y - __bfloat162float(h1));
            lo.y = pack2bf(v.z - __bfloat162float(h2), v.w - __bfloat162float(h3));
            uint32_t off = (uint32_t)c*256 + (((uint32_t)n4*2) ^ (((uint32_t)c & 7) << 4));
            *(uint2*)(sm + BH + off) = hi;
            *(uint2*)(sm + BL + off) = lo;
        }
        __syncthreads();

        // ---- 4 k-steps of m16n8k16
        #pragma unroll
        for (int ks = 0; ks < 4; ks++) {
            uint32_t ah[2][4], al[2][4];
            #pragma unroll
            for (int mt = 0; mt < 2; mt++) {
                uint32_t row = m0w + mt*16 + (lane & 7) + ((lane >> 3) & 1) * 8;
                uint32_t kb  = (uint32_t)ks*32 + (lane >> 4) * 16;
                uint32_t off = row*128 + (kb ^ ((row & 7) << 4));
                ldsm4(ah[mt], sbase + AH + off);
                ldsm4(al[mt], sbase + AL + off);
            }
            uint32_t bh[4][4], bl[4][4];
            #pragma unroll
            for (int g = 0; g < 4; g++) {
                uint32_t rowc = (uint32_t)ks*16 + (lane & 7) + ((lane >> 3) & 1) * 8;
                uint32_t nb   = ((uint32_t)n0w + g*16 + (lane >> 4) * 8) * 2;
                uint32_t off  = rowc*256 + (nb ^ ((rowc & 7) << 4));
                ldsm4t(bh[g], sbase + BH + off);
                ldsm4t(bl[g], sbase + BL + off);
            }
            #pragma unroll
            for (int mt = 0; mt < 2; mt++)
                #pragma unroll
                for (int nt = 0; nt < 8; nt++) {
                    uint32_t* fh = &bh[nt >> 1][(nt & 1) * 2];
                    uint32_t* fl = &bl[nt >> 1][(nt & 1) * 2];
                    mma_bf16(acc[mt][nt], ah[mt], fh);
                    mma_bf16(acc[mt][nt], ah[mt], fl);
                    mma_bf16(acc[mt][nt], al[mt], fh);
                }
        }
    }

    // ---- epilogue: bias + direct stores (32B-sector efficient)
    #pragma unroll
    for (int mt = 0; mt < 2; mt++) {
        int o_lo = m0w + mt*16 + (lane >> 2);
        float bias0 = s_bias[o_lo];
        float bias8 = s_bias[o_lo + 8];
        float* base = &g_qkv[((size_t)ib*768 + o0)*HWN + n0];
        #pragma unroll
        for (int nt = 0; nt < 8; nt++) {
            int n_col = n0w + nt*8 + (lane & 3)*2;
            float2 v0 = { acc[mt][nt][0] + bias0, acc[mt][nt][1] + bias0 };
            float2 v1 = { acc[mt][nt][2] + bias8, acc[mt][nt][3] + bias8 };
            *(float2*)&base[(size_t)o_lo*HWN + n_col]       = v0;
            *(float2*)&base[(size_t)(o_lo+8)*HWN + n_col]   = v1;
        }
    }
}

// ---------------------------------------------------------------------------
// 3) l2-normalize q and k rows (rows o in [0,512) per ib), length 1024
// ---------------------------------------------------------------------------
__global__ __launch_bounds__(256) void l2norm_kernel()
{
    int row = blockIdx.x;                 // NB*512 rows
    int ib = row >> 9, o = row & 511;
    float* p = &g_qkv[((size_t)ib*768 + o)*HWN];
    int tid = threadIdx.x;
    float4 v = ((float4*)p)[tid];
    float ss = v.x*v.x + v.y*v.y + v.z*v.z + v.w*v.w;
    #pragma unroll
    for (int off = 16; off; off >>= 1) ss += __shfl_xor_sync(0xffffffffu, ss, off);
    __shared__ float wsum[8];
    if ((tid & 31) == 0) wsum[tid >> 5] = ss;
    __syncthreads();
    float tot = wsum[0]+wsum[1]+wsum[2]+wsum[3]+wsum[4]+wsum[5]+wsum[6]+wsum[7];
    float inv = 1.f / fmaxf(sqrtf(tot), 1e-12f);
    v.x *= inv; v.y *= inv; v.z *= inv; v.w *= inv;
    ((float4*)p)[tid] = v;
}

// ---------------------------------------------------------------------------
// 4) flash attention per (ib, head, 64-token i-tile), fp32, 48KB static smem
// ---------------------------------------------------------------------------
__device__ __forceinline__ int VSW(int c, int t) {
    return t ^ (c & 31) ^ ((c & 32) >> 1);
}

__global__ __launch_bounds__(256) void flash_kernel()
{
    __shared__ float q_s[64*64];    // [c][ti]
    __shared__ float kp_s[64*64];   // k tile [c][tj], later P [ti][tj]
    __shared__ float v_s[64*64];    // [c][tj] XOR-swizzled

    int bx = blockIdx.x;
    int it = bx & 15;
    int h  = (bx >> 4) & 3;
    int ib = bx >> 6;
    int i0 = it * 64;

    const float* qg = &g_qkv[((size_t)ib*768 +        h*HD)*HWN];
    const float* kg = &g_qkv[((size_t)ib*768 + 256  + h*HD)*HWN];
    const float* vg = &g_qkv[((size_t)ib*768 + 512  + h*HD)*HWN];

    int tid = threadIdx.x;
    int tx = tid & 15, ty = tid >> 4;

    #pragma unroll
    for (int r = 0; r < 16; r++) {
        int idx = r*256 + tid;
        int c = idx >> 6, t = idx & 63;
        q_s[c*64 + t] = qg[c*HWN + i0 + t];
    }

    float o[4][4];
    float mrun[4], lrun[4];
    #pragma unroll
    for (int u = 0; u < 4; u++) {
        mrun[u] = -1e30f; lrun[u] = 0.f;
        #pragma unroll
        for (int w = 0; w < 4; w++) o[u][w] = 0.f;
    }
    const float scale = 0.125f;   // 1/sqrt(64)

    for (int j0 = 0; j0 < HWN; j0 += 64) {
        __syncthreads();
        #pragma unroll
        for (int r = 0; r < 16; r++) {
            int idx = r*256 + tid;
            int c = idx >> 6, t = idx & 63;
            kp_s[c*64 + t]        = kg[c*HWN + j0 + t];
            v_s[c*64 + VSW(c, t)] = vg[c*HWN + j0 + t];
        }
        __syncthreads();

        float s[4][4];
        #pragma unroll
        for (int u = 0; u < 4; u++)
            #pragma unroll
            for (int w = 0; w < 4; w++) s[u][w] = 0.f;
        #pragma unroll 8
        for (int c = 0; c < 64; c++) {
            float4 qv = *(const float4*)&q_s[c*64 + ty*4];
            float4 kv = *(const float4*)&kp_s[c*64 + tx*4];
            s[0][0] = fmaf(qv.x, kv.x, s[0][0]); s[0][1] = fmaf(qv.x, kv.y, s[0][1]);
            s[0][2] = fmaf(qv.x, kv.z, s[0][2]); s[0][3] = fmaf(qv.x, kv.w, s[0][3]);
            s[1][0] = fmaf(qv.y, kv.x, s[1][0]); s[1][1] = fmaf(qv.y, kv.y, s[1][1]);
            s[1][2] = fmaf(qv.y, kv.z, s[1][2]); s[1][3] = fmaf(qv.y, kv.w, s[1][3]);
            s[2][0] = fmaf(qv.z, kv.x, s[2][0]); s[2][1] = fmaf(qv.z, kv.y, s[2][1]);
            s[2][2] = fmaf(qv.z, kv.z, s[2][2]); s[2][3] = fmaf(qv.z, kv.w, s[2][3]);
            s[3][0] = fmaf(qv.w, kv.x, s[3][0]); s[3][1] = fmaf(qv.w, kv.y, s[3][1]);
            s[3][2] = fmaf(qv.w, kv.z, s[3][2]); s[3][3] = fmaf(qv.w, kv.w, s[3][3]);
        }

        #pragma unroll
        for (int u = 0; u < 4; u++) {
            #pragma unroll
            for (int w = 0; w < 4; w++) s[u][w] *= scale;
            float mt = fmaxf(fmaxf(s[u][0], s[u][1]), fmaxf(s[u][2], s[u][3]));
            #pragma unroll
            for (int off = 1; off < 16; off <<= 1)
                mt = fmaxf(mt, __shfl_xor_sync(0xffffffffu, mt, off));
            float mnew = fmaxf(mrun[u], mt);
            float al = __expf(mrun[u] - mnew);
            mrun[u] = mnew;
            float rs = 0.f;
            #pragma unroll
            for (int w = 0; w < 4; w++) { s[u][w] = __expf(s[u][w] - mnew); rs += s[u][w]; }
            #pragma unroll
            for (int off = 1; off < 16; off <<= 1)
                rs += __shfl_xor_sync(0xffffffffu, rs, off);
            lrun[u] = lrun[u]*al + rs;
            #pragma unroll
            for (int w = 0; w < 4; w++) o[u][w] *= al;
        }

        __syncthreads();
        #pragma unroll
        for (int u = 0; u < 4; u++)
            #pragma unroll
            for (int w = 0; w < 4; w++)
                kp_s[(ty*4 + u)*64 + tx*4 + w] = s[u][w];
        __syncthreads();

        #pragma unroll 8
        for (int t = 0; t < 64; t++) {
            float p0 = kp_s[(ty*4+0)*64 + t];
            float p1 = kp_s[(ty*4+1)*64 + t];
            float p2 = kp_s[(ty*4+2)*64 + t];
            float p3 = kp_s[(ty*4+3)*64 + t];
            float v0 = v_s[(tx*4+0)*64 + VSW(tx*4+0, t)];
            float v1 = v_s[(tx*4+1)*64 + VSW(tx*4+1, t)];
            float v2 = v_s[(tx*4+2)*64 + VSW(tx*4+2, t)];
            float v3 = v_s[(tx*4+3)*64 + VSW(tx*4+3, t)];
            o[0][0] = fmaf(p0, v0, o[0][0]); o[0][1] = fmaf(p0, v1, o[0][1]);
            o[0][2] = fmaf(p0, v2, o[0][2]); o[0][3] = fmaf(p0, v3, o[0][3]);
            o[1][0] = fmaf(p1, v0, o[1][0]); o[1][1] = fmaf(p1, v1, o[1][1]);
            o[1][2] = fmaf(p1, v2, o[1][2]); o[1][3] = fmaf(p1, v3, o[1][3]);
            o[2][0] = fmaf(p2, v0, o[2][0]); o[2][1] = fmaf(p2, v1, o[2][1]);
            o[2][2] = fmaf(p2, v2, o[2][2]); o[2][3] = fmaf(p2, v3, o[2][3]);
            o[3][0] = fmaf(p3, v0, o[3][0]); o[3][1] = fmaf(p3, v1, o[3][1]);
            o[3][2] = fmaf(p3, v2, o[3][2]); o[3][3] = fmaf(p3, v3, o[3][3]);
        }
    }

    __syncthreads();
    #pragma unroll
    for (int u = 0; u < 4; u++) {
        float inv = 1.f / lrun[u];
        #pragma unroll
        for (int w = 0; w < 4; w++) {
            int c = tx*4 + w, t = ty*4 + u;
            v_s[c*64 + VSW(c, t)] = o[u][w] * inv;
        }
    }
    __syncthreads();
    float* og = &g_att[((size_t)ib*CC + h*HD)*HWN];
    #pragma unroll
    for (int r = 0; r < 16; r++) {
        int idx = r*256 + tid;
        int c = idx >> 6, t = idx & 63;
        og[c*HWN + i0 + t] = v_s[c*64 + VSW(c, t)];
    }
}

// ---------------------------------------------------------------------------
// 5) out[b,c,n] = sum_i att[i,b,c,n] * mask[b,i,n]  (deterministic order)
// ---------------------------------------------------------------------------
__global__ __launch_bounds__(256) void out_kernel(float* __restrict__ out)
{
    int idx = blockIdx.x*256 + threadIdx.x;   // < B*C*HW = 2^21
    int b = idx >> 18;                        // C*HW = 262144
    int rem = idx & 262143;
    int n = rem & 1023;
    float acc = 0.f;
    #pragma unroll
    for (int i = 0; i < NI; i++) {
        acc = fmaf(g_att[(size_t)(i*BB + b)*262144 + rem],
                   g_mask[(b*NI + i)*HWN + n], acc);
    }
    out[idx] = acc;
}

// ---------------------------------------------------------------------------
extern "C" void kernel_launch(void* const* d_in, const int* in_sizes, int n_in,
                              void* d_out, int out_size)
{
    const float* x      = (const float*)d_in[0];
    const float* w_inst = (const float*)d_in[1];
    const float* b_inst = (const float*)d_in[2];
    const float* w_q    = (const float*)d_in[3];
    const float* b_q    = (const float*)d_in[4];
    const float* w_k    = (const float*)d_in[5];
    const float* b_k    = (const float*)d_in[6];
    const float* w_v    = (const float*)d_in[7];
    const float* b_v    = (const float*)d_in[8];
    float* out = (float*)d_out;

    static bool attr_done = false;
    if (!attr_done) {
        cudaFuncSetAttribute(qkv_mma, cudaFuncAttributeMaxDynamicSharedMemorySize,
                             QKV_SMEM_BYTES);
        attr_done = true;
    }

    mask_kernel<<<32, 256>>>(x, w_inst, b_inst);
    prep_kernel<<<(CC*CC + 255)/256, 256>>>(w_q, b_q, w_k, b_k, w_v, b_v);
    qkv_mma<<<dim3(8, 6, NB), 256, QKV_SMEM_BYTES>>>(x);
    l2norm_kernel<<<NB*512, 256>>>();
    flash_kernel<<<NB*NH*16, 256>>>();
    out_kernel<<<(BB*CC*HWN)/256, 256>>>(out);
}

// round 8
// speedup vs baseline: 2.8357x; 2.4222x over previous
#include <cuda_runtime.h>
#include <cuda_bf16.h>
#include <cstdint>

#define BB 8
#define CC 256
#define HWN 1024
#define NI 8
#define NH 4
#define HD 64
#define NB (NI*BB)   // 64 (instance,batch) pairs

// Scratch (static device globals; no allocations anywhere)
__device__ float g_w3[3*CC*CC];          // concat(w_q,w_k,w_v) [768][256]
__device__ float g_b3[3*CC];
__device__ float g_mask[BB*NI*HWN];      // [b][i][n] softmaxed instance masks
__device__ float g_qkv[(size_t)NB*3*CC*HWN];   // fp32 qkv (~201MB)
__device__ __nv_bfloat16 g_qkv_h[(size_t)NB*3*CC*HWN];  // hi bf16 (~100MB)
__device__ __nv_bfloat16 g_qkv_l[(size_t)NB*3*CC*HWN];  // lo bf16 (~100MB)
__device__ float g_att[(size_t)NB*CC*HWN];     // per-instance attention out (~67MB)

// ===========================================================================
// mma.sync / ldmatrix helpers (baseline PTX — works at compute_103 target)
// ===========================================================================
__device__ __forceinline__ uint32_t smem_to_u32(const void* p) {
    uint32_t a;
    asm("{ .reg .u64 t; cvta.to.shared.u64 t, %1; cvt.u32.u64 %0, t; }"
        : "=r"(a) : "l"(p));
    return a;
}
__device__ __forceinline__ void ldsm4(uint32_t* r, uint32_t addr) {
    asm volatile("ldmatrix.sync.aligned.m8n8.x4.shared.b16 {%0,%1,%2,%3}, [%4];"
        : "=r"(r[0]), "=r"(r[1]), "=r"(r[2]), "=r"(r[3]) : "r"(addr));
}
__device__ __forceinline__ void ldsm4t(uint32_t* r, uint32_t addr) {
    asm volatile("ldmatrix.sync.aligned.m8n8.x4.trans.shared.b16 {%0,%1,%2,%3}, [%4];"
        : "=r"(r[0]), "=r"(r[1]), "=r"(r[2]), "=r"(r[3]) : "r"(addr));
}
__device__ __forceinline__ void mma_bf16(float* c, const uint32_t* a, const uint32_t* b) {
    asm volatile(
        "mma.sync.aligned.m16n8k16.row.col.f32.bf16.bf16.f32 "
        "{%0,%1,%2,%3}, {%4,%5,%6,%7}, {%8,%9}, {%0,%1,%2,%3};"
        : "+f"(c[0]), "+f"(c[1]), "+f"(c[2]), "+f"(c[3])
        : "r"(a[0]), "r"(a[1]), "r"(a[2]), "r"(a[3]), "r"(b[0]), "r"(b[1]));
}
__device__ __forceinline__ uint32_t pack2bf(float a, float b) {
    __nv_bfloat162 t = __floats2bfloat162_rn(a, b);
    return *(uint32_t*)&t;
}
__device__ __forceinline__ void split2(float a, float b, uint32_t& hi, uint32_t& lo) {
    __nv_bfloat16 ha = __float2bfloat16_rn(a), hb = __float2bfloat16_rn(b);
    float fa = __bfloat162float(ha), fb = __bfloat162float(hb);
    hi = pack2bf(fa, fb);           // exact (values already bf16-representable)
    lo = pack2bf(a - fa, b - fb);
}

// ---------------------------------------------------------------------------
// 1) instance conv + softmax over instance axis
// ---------------------------------------------------------------------------
__global__ __launch_bounds__(256) void mask_kernel(
    const float* __restrict__ x, const float* __restrict__ w_inst,
    const float* __restrict__ b_inst)
{
    __shared__ float ws[NI*CC];
    int tid = threadIdx.x;
    for (int k = tid; k < NI*CC; k += 256) ws[k] = w_inst[k];
    __syncthreads();

    int gid = blockIdx.x*256 + tid;          // 0..8191 = B*HW
    int b = gid >> 10, n = gid & 1023;
    float acc[NI];
    #pragma unroll
    for (int i = 0; i < NI; i++) acc[i] = 0.f;
    const float* xp = x + (size_t)b*CC*HWN + n;
    for (int c = 0; c < CC; c++) {
        float xv = xp[c*HWN];
        #pragma unroll
        for (int i = 0; i < NI; i++) acc[i] = fmaf(ws[i*CC + c], xv, acc[i]);
    }
    float m = -1e30f;
    #pragma unroll
    for (int i = 0; i < NI; i++) { acc[i] += b_inst[i]; m = fmaxf(m, acc[i]); }
    float s = 0.f;
    #pragma unroll
    for (int i = 0; i < NI; i++) { acc[i] = __expf(acc[i] - m); s += acc[i]; }
    float inv = 1.f / s;
    #pragma unroll
    for (int i = 0; i < NI; i++) g_mask[(b*NI + i)*HWN + n] = acc[i]*inv;
}

// ---------------------------------------------------------------------------
// 2a) concat weights/biases into one [768,256] matrix
// ---------------------------------------------------------------------------
__global__ __launch_bounds__(256) void prep_kernel(
    const float* __restrict__ wq, const float* __restrict__ bq,
    const float* __restrict__ wk, const float* __restrict__ bk,
    const float* __restrict__ wv, const float* __restrict__ bv)
{
    int idx = blockIdx.x*256 + threadIdx.x;
    if (idx < CC*CC) {
        g_w3[idx]           = wq[idx];
        g_w3[CC*CC + idx]   = wk[idx];
        g_w3[2*CC*CC + idx] = wv[idx];
    }
    if (idx < CC) { g_b3[idx] = bq[idx]; g_b3[CC+idx] = bk[idx]; g_b3[2*CC+idx] = bv[idx]; }
}

// ---------------------------------------------------------------------------
// 2b) QKV GEMM via mma.sync bf16 hi/lo split (validated round 3)
// ---------------------------------------------------------------------------
#define QKV_SMEM_BYTES 65536   // AH 16K | AL 16K | BH 16K | BL 16K

__global__ __launch_bounds__(256) void qkv_mma(const float* __restrict__ x)
{
    extern __shared__ char sm[];
    __shared__ float s_msk[128];
    __shared__ float s_bias[128];

    const uint32_t AH = 0, AL = 16384, BH = 32768, BL = 49152;
    uint32_t sbase = smem_to_u32(sm);

    int tid = threadIdx.x;
    int wid = tid >> 5, lane = tid & 31;
    int n0 = blockIdx.x * 128;
    int o0 = blockIdx.y * 128;
    int ib = blockIdx.z;
    int b = ib & 7, inst = ib >> 3;

    if (tid < 128) s_msk[tid] = g_mask[(b*NI + inst)*HWN + n0 + tid];
    else           s_bias[tid-128] = g_b3[o0 + tid - 128];

    float acc[2][8][4];
    #pragma unroll
    for (int mt = 0; mt < 2; mt++)
        #pragma unroll
        for (int nt = 0; nt < 8; nt++)
            #pragma unroll
            for (int q = 0; q < 4; q++) acc[mt][nt][q] = 0.f;

    const int m0w = (wid & 3) * 32;
    const int n0w = (wid >> 2) * 64;

    #pragma unroll 1
    for (int kc = 0; kc < 4; kc++) {
        __syncthreads();

        const float* wp = g_w3 + (size_t)o0*CC + kc*64;
        #pragma unroll
        for (int i = 0; i < 8; i++) {
            int e = i*256 + tid;
            int m = e >> 4, c = (e & 15) * 4;
            float4 w4 = *(const float4*)&wp[(size_t)m*CC + c];
            uint2 hi, lo;
            split2(w4.x, w4.y, hi.x, lo.x);
            split2(w4.z, w4.w, hi.y, lo.y);
            uint32_t off = (uint32_t)m*128 + (((uint32_t)c*2) ^ (((uint32_t)m & 7) << 4));
            *(uint2*)(sm + AH + off) = hi;
            *(uint2*)(sm + AL + off) = lo;
        }
        const float* xp = x + ((size_t)b*CC + kc*64)*HWN + n0;
        #pragma unroll
        for (int i = 0; i < 8; i++) {
            int e = i*256 + tid;
            int c = e >> 5, n4 = (e & 31) * 4;
            float4 v = *(const float4*)&xp[(size_t)c*HWN + n4];
            v.x *= s_msk[n4+0]; v.y *= s_msk[n4+1];
            v.z *= s_msk[n4+2]; v.w *= s_msk[n4+3];
            uint2 hi, lo;
            split2(v.x, v.y, hi.x, lo.x);
            split2(v.z, v.w, hi.y, lo.y);
            uint32_t off = (uint32_t)c*256 + (((uint32_t)n4*2) ^ (((uint32_t)c & 7) << 4));
            *(uint2*)(sm + BH + off) = hi;
            *(uint2*)(sm + BL + off) = lo;
        }
        __syncthreads();

        #pragma unroll
        for (int ks = 0; ks < 4; ks++) {
            uint32_t ah[2][4], al[2][4];
            #pragma unroll
            for (int mt = 0; mt < 2; mt++) {
                uint32_t row = m0w + mt*16 + (lane & 7) + ((lane >> 3) & 1) * 8;
                uint32_t kb  = (uint32_t)ks*32 + (lane >> 4) * 16;
                uint32_t off = row*128 + (kb ^ ((row & 7) << 4));
                ldsm4(ah[mt], sbase + AH + off);
                ldsm4(al[mt], sbase + AL + off);
            }
            uint32_t bh[4][4], bl[4][4];
            #pragma unroll
            for (int g = 0; g < 4; g++) {
                uint32_t rowc = (uint32_t)ks*16 + (lane & 7) + ((lane >> 3) & 1) * 8;
                uint32_t nb   = ((uint32_t)n0w + g*16 + (lane >> 4) * 8) * 2;
                uint32_t off  = rowc*256 + (nb ^ ((rowc & 7) << 4));
                ldsm4t(bh[g], sbase + BH + off);
                ldsm4t(bl[g], sbase + BL + off);
            }
            #pragma unroll
            for (int mt = 0; mt < 2; mt++)
                #pragma unroll
                for (int nt = 0; nt < 8; nt++) {
                    uint32_t* fh = &bh[nt >> 1][(nt & 1) * 2];
                    uint32_t* fl = &bl[nt >> 1][(nt & 1) * 2];
                    mma_bf16(acc[mt][nt], ah[mt], fh);
                    mma_bf16(acc[mt][nt], ah[mt], fl);
                    mma_bf16(acc[mt][nt], al[mt], fh);
                }
        }
    }

    #pragma unroll
    for (int mt = 0; mt < 2; mt++) {
        int o_lo = m0w + mt*16 + (lane >> 2);
        float bias0 = s_bias[o_lo];
        float bias8 = s_bias[o_lo + 8];
        float* base = &g_qkv[((size_t)ib*768 + o0)*HWN + n0];
        #pragma unroll
        for (int nt = 0; nt < 8; nt++) {
            int n_col = n0w + nt*8 + (lane & 3)*2;
            float2 v0 = { acc[mt][nt][0] + bias0, acc[mt][nt][1] + bias0 };
            float2 v1 = { acc[mt][nt][2] + bias8, acc[mt][nt][3] + bias8 };
            *(float2*)&base[(size_t)o_lo*HWN + n_col]       = v0;
            *(float2*)&base[(size_t)(o_lo+8)*HWN + n_col]   = v1;
        }
    }
}

// ---------------------------------------------------------------------------
// 3) l2-normalize q,k rows + emit hi/lo bf16 for ALL 768 rows.
//    q rows (o<256) additionally pre-scaled by 1/sqrt(hd)=0.125 (exact pow2).
// ---------------------------------------------------------------------------
__global__ __launch_bounds__(256) void l2norm_kernel()
{
    int row = blockIdx.x;                 // NB*768 rows
    int ib = row / 768;
    int o = row - ib*768;
    const float* p = &g_qkv[((size_t)ib*768 + o)*HWN];
    int tid = threadIdx.x;
    float4 v = ((const float4*)p)[tid];
    float inv = 1.f;
    if (o < 512) {
        float ss = v.x*v.x + v.y*v.y + v.z*v.z + v.w*v.w;
        #pragma unroll
        for (int off = 16; off; off >>= 1) ss += __shfl_xor_sync(0xffffffffu, ss, off);
        __shared__ float wsum[8];
        if ((tid & 31) == 0) wsum[tid >> 5] = ss;
        __syncthreads();
        float tot = wsum[0]+wsum[1]+wsum[2]+wsum[3]+wsum[4]+wsum[5]+wsum[6]+wsum[7];
        inv = 1.f / fmaxf(sqrtf(tot), 1e-12f);
        if (o < 256) inv *= 0.125f;       // fold attention scale into q
    }
    float s0 = v.x*inv, s1 = v.y*inv, s2 = v.z*inv, s3 = v.w*inv;
    uint2 hh, ll;
    split2(s0, s1, hh.x, ll.x);
    split2(s2, s3, hh.y, ll.y);
    size_t idx = (size_t)row*HWN + tid*4;
    *(uint2*)&g_qkv_h[idx] = hh;
    *(uint2*)&g_qkv_l[idx] = ll;
}

// ---------------------------------------------------------------------------
// 4) flash attention via mma.sync bf16 hi/lo split.
//    CTA = (i-tile of 128 q-tokens, head, ib). 8 warps x 16 q rows.
//    Q,K native [c][tok]; ldmatrix.trans makes A/B frags. V native [d][tok]
//    is ALREADY B-operand orientation -> non-trans ldmatrix (d-row patches).
// ---------------------------------------------------------------------------
#define FL_SMEM 98304   // QH QL KH KL VH VL, 16KB each

__global__ __launch_bounds__(256) void flash_mma()
{
    extern __shared__ char sm[];
    const uint32_t QHo=0, QLo=16384, KHo=32768, KLo=49152, VHo=65536, VLo=81920;
    uint32_t sbase = smem_to_u32(sm);

    int tid = threadIdx.x, wid = tid >> 5, lane = tid & 31;
    int it = blockIdx.x, h = blockIdx.y, ib = blockIdx.z;
    int i0 = it * 128;
    int m0w = wid * 16;

    const __nv_bfloat16* qh = g_qkv_h + ((size_t)ib*768 +       h*HD)*HWN;
    const __nv_bfloat16* ql = g_qkv_l + ((size_t)ib*768 +       h*HD)*HWN;
    const __nv_bfloat16* kh = g_qkv_h + ((size_t)ib*768 + 256 + h*HD)*HWN;
    const __nv_bfloat16* kl = g_qkv_l + ((size_t)ib*768 + 256 + h*HD)*HWN;
    const __nv_bfloat16* vh = g_qkv_h + ((size_t)ib*768 + 512 + h*HD)*HWN;
    const __nv_bfloat16* vl = g_qkv_l + ((size_t)ib*768 + 512 + h*HD)*HWN;

    // Q tile (once): 64 c-rows x 128 tok bf16, swizzled 256B rows
    #pragma unroll
    for (int i = 0; i < 4; i++) {
        int e = i*256 + tid;
        int c = e >> 4, t = (e & 15) * 8;
        uint32_t off = (uint32_t)c*256 + (((uint32_t)t*2) ^ (((uint32_t)c & 7) << 4));
        *(uint4*)(sm + QHo + off) = *(const uint4*)&qh[(size_t)c*HWN + i0 + t];
        *(uint4*)(sm + QLo + off) = *(const uint4*)&ql[(size_t)c*HWN + i0 + t];
    }

    float o[8][4];
    #pragma unroll
    for (int n = 0; n < 8; n++)
        #pragma unroll
        for (int q = 0; q < 4; q++) o[n][q] = 0.f;
    float mr0 = -1e30f, mr1 = -1e30f, lr0 = 0.f, lr1 = 0.f;

    #pragma unroll 1
    for (int j0 = 0; j0 < HWN; j0 += 128) {
        __syncthreads();
        #pragma unroll
        for (int i = 0; i < 4; i++) {
            int e = i*256 + tid;
            int c = e >> 4, t = (e & 15) * 8;
            uint32_t off = (uint32_t)c*256 + (((uint32_t)t*2) ^ (((uint32_t)c & 7) << 4));
            *(uint4*)(sm + KHo + off) = *(const uint4*)&kh[(size_t)c*HWN + j0 + t];
            *(uint4*)(sm + KLo + off) = *(const uint4*)&kl[(size_t)c*HWN + j0 + t];
            *(uint4*)(sm + VHo + off) = *(const uint4*)&vh[(size_t)c*HWN + j0 + t];
            *(uint4*)(sm + VLo + off) = *(const uint4*)&vl[(size_t)c*HWN + j0 + t];
        }
        __syncthreads();

        // ---- S = Q^T K (pre-scaled q), hi/lo split ----
        float s[16][4];
        #pragma unroll
        for (int j = 0; j < 16; j++)
            #pragma unroll
            for (int q = 0; q < 4; q++) s[j][q] = 0.f;

        #pragma unroll
        for (int ks = 0; ks < 4; ks++) {
            uint32_t ah[4], al[4];
            {
                // A-from-trans: k-select bit = lane>>4, m-select bit = lane>>3
                uint32_t c = (uint32_t)ks*16 + (lane & 7) + ((lane >> 4) & 1) * 8;
                uint32_t t = (uint32_t)m0w + ((lane >> 3) & 1) * 8;
                uint32_t off = c*256 + ((t*2) ^ ((c & 7) << 4));
                ldsm4t(ah, sbase + QHo + off);
                ldsm4t(al, sbase + QLo + off);
            }
            #pragma unroll
            for (int g = 0; g < 8; g++) {
                uint32_t bh[4], bl[4];
                // B-from-trans: k-select bit = lane>>3, n-select bit = lane>>4
                uint32_t c = (uint32_t)ks*16 + (lane & 7) + ((lane >> 3) & 1) * 8;
                uint32_t t = (uint32_t)g*16 + ((lane >> 4) & 1) * 8;
                uint32_t off = c*256 + ((t*2) ^ ((c & 7) << 4));
                ldsm4t(bh, sbase + KHo + off);
                ldsm4t(bl, sbase + KLo + off);
                #pragma unroll
                for (int half = 0; half < 2; half++) {
                    float* acc = s[g*2 + half];
                    uint32_t* fh = &bh[half*2];
                    uint32_t* fl = &bl[half*2];
                    mma_bf16(acc, ah, fh);
                    mma_bf16(acc, ah, fl);
                    mma_bf16(acc, al, fh);
                }
            }
        }

        // ---- online softmax (rows r=lane>>2 and r+8; quad reduce) ----
        float mx0 = -1e30f, mx1 = -1e30f;
        #pragma unroll
        for (int j = 0; j < 16; j++) {
            mx0 = fmaxf(mx0, fmaxf(s[j][0], s[j][1]));
            mx1 = fmaxf(mx1, fmaxf(s[j][2], s[j][3]));
        }
        #pragma unroll
        for (int off = 1; off < 4; off <<= 1) {
            mx0 = fmaxf(mx0, __shfl_xor_sync(0xffffffffu, mx0, off));
            mx1 = fmaxf(mx1, __shfl_xor_sync(0xffffffffu, mx1, off));
        }
        float mn0 = fmaxf(mr0, mx0), mn1 = fmaxf(mr1, mx1);
        float al0 = __expf(mr0 - mn0), al1 = __expf(mr1 - mn1);
        mr0 = mn0; mr1 = mn1;
        float rs0 = 0.f, rs1 = 0.f;
        #pragma unroll
        for (int j = 0; j < 16; j++) {
            s[j][0] = __expf(s[j][0] - mn0);
            s[j][1] = __expf(s[j][1] - mn0);
            s[j][2] = __expf(s[j][2] - mn1);
            s[j][3] = __expf(s[j][3] - mn1);
            rs0 += s[j][0] + s[j][1];
            rs1 += s[j][2] + s[j][3];
        }
        #pragma unroll
        for (int off = 1; off < 4; off <<= 1) {
            rs0 += __shfl_xor_sync(0xffffffffu, rs0, off);
            rs1 += __shfl_xor_sync(0xffffffffu, rs1, off);
        }
        lr0 = lr0*al0 + rs0;
        lr1 = lr1*al1 + rs1;
        #pragma unroll
        for (int n = 0; n < 8; n++) {
            o[n][0] *= al0; o[n][1] *= al0;
            o[n][2] *= al1; o[n][3] *= al1;
        }

        // ---- O += P V^T ; P rebuilt from s regs (FA2 repack), hi/lo split ----
        #pragma unroll
        for (int ks = 0; ks < 8; ks++) {
            uint32_t ph[4], pl[4];
            split2(s[2*ks][0],   s[2*ks][1],   ph[0], pl[0]);
            split2(s[2*ks][2],   s[2*ks][3],   ph[1], pl[1]);
            split2(s[2*ks+1][0], s[2*ks+1][1], ph[2], pl[2]);
            split2(s[2*ks+1][2], s[2*ks+1][3], ph[3], pl[3]);
            #pragma unroll
            for (int g = 0; g < 4; g++) {
                uint32_t bh[4], bl[4];
                // B non-trans from [d][j] smem: d-select bit = lane>>4,
                // j-select (16B within row) bit = lane>>3
                uint32_t d  = (uint32_t)g*16 + (lane & 7) + ((lane >> 4) & 1) * 8;
                uint32_t jb = (uint32_t)ks*32 + ((lane >> 3) & 1) * 16;
                uint32_t off = d*256 + (jb ^ ((d & 7) << 4));
                ldsm4(bh, sbase + VHo + off);
                ldsm4(bl, sbase + VLo + off);
                #pragma unroll
                for (int half = 0; half < 2; half++) {
                    float* acc = o[g*2 + half];
                    uint32_t* fh = &bh[half*2];
                    uint32_t* fl = &bl[half*2];
                    mma_bf16(acc, ph, fh);
                    mma_bf16(acc, ph, fl);
                    mma_bf16(acc, pl, fh);
                }
            }
        }
    }

    // ---- epilogue: normalize, stage via swizzled smem, coalesced store ----
    __syncthreads();
    float* outs = (float*)sm;   // [64 d][128 tok] fp32, word-XOR swizzle
    float inv0 = 1.f / lr0, inv1 = 1.f / lr1;
    int r = lane >> 2;
    #pragma unroll
    for (int n = 0; n < 8; n++) {
        int d0 = n*8 + (lane & 3)*2;
        int d1 = d0 + 1;
        int tl = m0w + r, th = tl + 8;
        outs[d0*128 + (tl ^ ((d0 & 7) << 2))] = o[n][0]*inv0;
        outs[d1*128 + (tl ^ ((d1 & 7) << 2))] = o[n][1]*inv0;
        outs[d0*128 + (th ^ ((d0 & 7) << 2))] = o[n][2]*inv1;
        outs[d1*128 + (th ^ ((d1 & 7) << 2))] = o[n][3]*inv1;
    }
    __syncthreads();
    float* og = &g_att[((size_t)ib*CC + h*HD)*HWN + i0];
    #pragma unroll
    for (int i = 0; i < 8; i++) {
        int e = i*256 + tid;
        int d = e >> 5, t4 = (e & 31) * 4;
        float4 val = *(const float4*)&outs[d*128 + (t4 ^ ((d & 7) << 2))];
        *(float4*)&og[(size_t)d*HWN + t4] = val;
    }
}

// ---------------------------------------------------------------------------
// 5) out[b,c,n] = sum_i att[i,b,c,n] * mask[b,i,n]  (deterministic order)
// ---------------------------------------------------------------------------
__global__ __launch_bounds__(256) void out_kernel(float* __restrict__ out)
{
    int idx = blockIdx.x*256 + threadIdx.x;   // < B*C*HW = 2^21
    int b = idx >> 18;                        // C*HW = 262144
    int rem = idx & 262143;
    int n = rem & 1023;
    float acc = 0.f;
    #pragma unroll
    for (int i = 0; i < NI; i++) {
        acc = fmaf(g_att[(size_t)(i*BB + b)*262144 + rem],
                   g_mask[(b*NI + i)*HWN + n], acc);
    }
    out[idx] = acc;
}

// ---------------------------------------------------------------------------
extern "C" void kernel_launch(void* const* d_in, const int* in_sizes, int n_in,
                              void* d_out, int out_size)
{
    const float* x      = (const float*)d_in[0];
    const float* w_inst = (const float*)d_in[1];
    const float* b_inst = (const float*)d_in[2];
    const float* w_q    = (const float*)d_in[3];
    const float* b_q    = (const float*)d_in[4];
    const float* w_k    = (const float*)d_in[5];
    const float* b_k    = (const float*)d_in[6];
    const float* w_v    = (const float*)d_in[7];
    const float* b_v    = (const float*)d_in[8];
    float* out = (float*)d_out;

    static bool attr_done = false;
    if (!attr_done) {
        cudaFuncSetAttribute(qkv_mma, cudaFuncAttributeMaxDynamicSharedMemorySize,
                             QKV_SMEM_BYTES);
        cudaFuncSetAttribute(flash_mma, cudaFuncAttributeMaxDynamicSharedMemorySize,
                             FL_SMEM);
        attr_done = true;
    }

    mask_kernel<<<32, 256>>>(x, w_inst, b_inst);
    prep_kernel<<<(CC*CC + 255)/256, 256>>>(w_q, b_q, w_k, b_k, w_v, b_v);
    qkv_mma<<<dim3(8, 6, NB), 256, QKV_SMEM_BYTES>>>(x);
    l2norm_kernel<<<NB*768, 256>>>();
    flash_mma<<<dim3(8, NH, NB), 256, FL_SMEM>>>();
    out_kernel<<<(BB*CC*HWN)/256, 256>>>(out);
}

// round 10
// speedup vs baseline: 3.7980x; 1.3394x over previous
#include <cuda_runtime.h>
#include <cuda_bf16.h>
#include <cuda_fp16.h>
#include <cstdint>

#define BB 8
#define CC 256
#define HWN 1024
#define NI 8
#define NH 4
#define HD 64
#define NB (NI*BB)   // 64 (instance,batch) pairs

// Scratch (static device globals; no allocations anywhere)
__device__ float g_w3[3*CC*CC];          // concat(w_q,w_k,w_v) [768][256]
__device__ float g_b3[3*CC];
__device__ float g_mask[BB*NI*HWN];      // [b][i][n] softmaxed instance masks
__device__ float g_qkv[(size_t)NB*2*CC*HWN];    // fp32 q,k rows only (~134MB)
__device__ __half g_q16[(size_t)NB*CC*HWN];     // fp16 q (prescaled)  (~33MB)
__device__ __half g_k16[(size_t)NB*CC*HWN];     // fp16 k              (~33MB)
__device__ __half g_v16h[(size_t)NB*CC*HWN];    // fp16 v hi           (~33MB)
__device__ __half g_v16l[(size_t)NB*CC*HWN];    // fp16 v lo           (~33MB)
__device__ float g_att[(size_t)NB*CC*HWN];      // per-instance attention out (~67MB)

// ===========================================================================
// mma.sync / ldmatrix helpers (baseline PTX — works at compute_103 target)
// ===========================================================================
__device__ __forceinline__ uint32_t smem_to_u32(const void* p) {
    uint32_t a;
    asm("{ .reg .u64 t; cvta.to.shared.u64 t, %1; cvt.u32.u64 %0, t; }"
        : "=r"(a) : "l"(p));
    return a;
}
__device__ __forceinline__ void ldsm4(uint32_t* r, uint32_t addr) {
    asm volatile("ldmatrix.sync.aligned.m8n8.x4.shared.b16 {%0,%1,%2,%3}, [%4];"
        : "=r"(r[0]), "=r"(r[1]), "=r"(r[2]), "=r"(r[3]) : "r"(addr));
}
__device__ __forceinline__ void ldsm4t(uint32_t* r, uint32_t addr) {
    asm volatile("ldmatrix.sync.aligned.m8n8.x4.trans.shared.b16 {%0,%1,%2,%3}, [%4];"
        : "=r"(r[0]), "=r"(r[1]), "=r"(r[2]), "=r"(r[3]) : "r"(addr));
}
__device__ __forceinline__ void mma_bf16(float* c, const uint32_t* a, const uint32_t* b) {
    asm volatile(
        "mma.sync.aligned.m16n8k16.row.col.f32.bf16.bf16.f32 "
        "{%0,%1,%2,%3}, {%4,%5,%6,%7}, {%8,%9}, {%0,%1,%2,%3};"
        : "+f"(c[0]), "+f"(c[1]), "+f"(c[2]), "+f"(c[3])
        : "r"(a[0]), "r"(a[1]), "r"(a[2]), "r"(a[3]), "r"(b[0]), "r"(b[1]));
}
__device__ __forceinline__ void mma_f16(float* c, const uint32_t* a, const uint32_t* b) {
    asm volatile(
        "mma.sync.aligned.m16n8k16.row.col.f32.f16.f16.f32 "
        "{%0,%1,%2,%3}, {%4,%5,%6,%7}, {%8,%9}, {%0,%1,%2,%3};"
        : "+f"(c[0]), "+f"(c[1]), "+f"(c[2]), "+f"(c[3])
        : "r"(a[0]), "r"(a[1]), "r"(a[2]), "r"(a[3]), "r"(b[0]), "r"(b[1]));
}
__device__ __forceinline__ uint32_t pack2bf(float a, float b) {
    __nv_bfloat162 t = __floats2bfloat162_rn(a, b);
    return *(uint32_t*)&t;
}
__device__ __forceinline__ void split2(float a, float b, uint32_t& hi, uint32_t& lo) {
    __nv_bfloat16 ha = __float2bfloat16_rn(a), hb = __float2bfloat16_rn(b);
    float fa = __bfloat162float(ha), fb = __bfloat162float(hb);
    hi = pack2bf(fa, fb);
    lo = pack2bf(a - fa, b - fb);
}
__device__ __forceinline__ void split2h(float a, float b, uint32_t& hi, uint32_t& lo) {
    __half2 h = __floats2half2_rn(a, b);
    float fa = __half2float(__low2half(h)), fb = __half2float(__high2half(h));
    hi = *(uint32_t*)&h;
    __half2 l = __floats2half2_rn(a - fa, b - fb);
    lo = *(uint32_t*)&l;
}
__device__ __forceinline__ uint32_t packh2(float a, float b) {
    __half2 h = __floats2half2_rn(a, b);
    return *(uint32_t*)&h;
}
__device__ __forceinline__ float ex2f(float x) {
    float r;
    asm("ex2.approx.f32 %0, %1;" : "=f"(r) : "f"(x));
    return r;
}

// ---------------------------------------------------------------------------
// 1) instance conv + softmax over instance axis
// ---------------------------------------------------------------------------
__global__ __launch_bounds__(256) void mask_kernel(
    const float* __restrict__ x, const float* __restrict__ w_inst,
    const float* __restrict__ b_inst)
{
    __shared__ float ws[NI*CC];
    int tid = threadIdx.x;
    for (int k = tid; k < NI*CC; k += 256) ws[k] = w_inst[k];
    __syncthreads();

    int gid = blockIdx.x*256 + tid;          // 0..8191 = B*HW
    int b = gid >> 10, n = gid & 1023;
    float acc[NI];
    #pragma unroll
    for (int i = 0; i < NI; i++) acc[i] = 0.f;
    const float* xp = x + (size_t)b*CC*HWN + n;
    for (int c = 0; c < CC; c++) {
        float xv = xp[c*HWN];
        #pragma unroll
        for (int i = 0; i < NI; i++) acc[i] = fmaf(ws[i*CC + c], xv, acc[i]);
    }
    float m = -1e30f;
    #pragma unroll
    for (int i = 0; i < NI; i++) { acc[i] += b_inst[i]; m = fmaxf(m, acc[i]); }
    float s = 0.f;
    #pragma unroll
    for (int i = 0; i < NI; i++) { acc[i] = __expf(acc[i] - m); s += acc[i]; }
    float inv = 1.f / s;
    #pragma unroll
    for (int i = 0; i < NI; i++) g_mask[(b*NI + i)*HWN + n] = acc[i]*inv;
}

// ---------------------------------------------------------------------------
// 2a) concat weights/biases into one [768,256] matrix
// ---------------------------------------------------------------------------
__global__ __launch_bounds__(256) void prep_kernel(
    const float* __restrict__ wq, const float* __restrict__ bq,
    const float* __restrict__ wk, const float* __restrict__ bk,
    const float* __restrict__ wv, const float* __restrict__ bv)
{
    int idx = blockIdx.x*256 + threadIdx.x;
    if (idx < CC*CC) {
        g_w3[idx]           = wq[idx];
        g_w3[CC*CC + idx]   = wk[idx];
        g_w3[2*CC*CC + idx] = wv[idx];
    }
    if (idx < CC) { g_b3[idx] = bq[idx]; g_b3[CC+idx] = bk[idx]; g_b3[2*CC+idx] = bv[idx]; }
}

// ---------------------------------------------------------------------------
// 2b) QKV GEMM via mma.sync bf16 hi/lo split (validated round 3).
//     q,k rows (o0<512) -> fp32 g_qkv; v rows (o0>=512) -> fp16 hi/lo direct.
// ---------------------------------------------------------------------------
#define QKV_SMEM_BYTES 65536   // AH 16K | AL 16K | BH 16K | BL 16K

__global__ __launch_bounds__(256) void qkv_mma(const float* __restrict__ x)
{
    extern __shared__ char sm[];
    __shared__ float s_msk[128];
    __shared__ float s_bias[128];

    const uint32_t AH = 0, AL = 16384, BH = 32768, BL = 49152;
    uint32_t sbase = smem_to_u32(sm);

    int tid = threadIdx.x;
    int wid = tid >> 5, lane = tid & 31;
    int n0 = blockIdx.x * 128;
    int o0 = blockIdx.y * 128;
    int ib = blockIdx.z;
    int b = ib & 7, inst = ib >> 3;

    if (tid < 128) s_msk[tid] = g_mask[(b*NI + inst)*HWN + n0 + tid];
    else           s_bias[tid-128] = g_b3[o0 + tid - 128];

    float acc[2][8][4];
    #pragma unroll
    for (int mt = 0; mt < 2; mt++)
        #pragma unroll
        for (int nt = 0; nt < 8; nt++)
            #pragma unroll
            for (int q = 0; q < 4; q++) acc[mt][nt][q] = 0.f;

    const int m0w = (wid & 3) * 32;
    const int n0w = (wid >> 2) * 64;

    #pragma unroll 1
    for (int kc = 0; kc < 4; kc++) {
        __syncthreads();

        const float* wp = g_w3 + (size_t)o0*CC + kc*64;
        #pragma unroll
        for (int i = 0; i < 8; i++) {
            int e = i*256 + tid;
            int m = e >> 4, c = (e & 15) * 4;
            float4 w4 = *(const float4*)&wp[(size_t)m*CC + c];
            uint2 hi, lo;
            split2(w4.x, w4.y, hi.x, lo.x);
            split2(w4.z, w4.w, hi.y, lo.y);
            uint32_t off = (uint32_t)m*128 + (((uint32_t)c*2) ^ (((uint32_t)m & 7) << 4));
            *(uint2*)(sm + AH + off) = hi;
            *(uint2*)(sm + AL + off) = lo;
        }
        const float* xp = x + ((size_t)b*CC + kc*64)*HWN + n0;
        #pragma unroll
        for (int i = 0; i < 8; i++) {
            int e = i*256 + tid;
            int c = e >> 5, n4 = (e & 31) * 4;
            float4 v = *(const float4*)&xp[(size_t)c*HWN + n4];
            v.x *= s_msk[n4+0]; v.y *= s_msk[n4+1];
            v.z *= s_msk[n4+2]; v.w *= s_msk[n4+3];
            uint2 hi, lo;
            split2(v.x, v.y, hi.x, lo.x);
            split2(v.z, v.w, hi.y, lo.y);
            uint32_t off = (uint32_t)c*256 + (((uint32_t)n4*2) ^ (((uint32_t)c & 7) << 4));
            *(uint2*)(sm + BH + off) = hi;
            *(uint2*)(sm + BL + off) = lo;
        }
        __syncthreads();

        #pragma unroll
        for (int ks = 0; ks < 4; ks++) {
            uint32_t ah[2][4], al[2][4];
            #pragma unroll
            for (int mt = 0; mt < 2; mt++) {
                uint32_t row = m0w + mt*16 + (lane & 7) + ((lane >> 3) & 1) * 8;
                uint32_t kb  = (uint32_t)ks*32 + (lane >> 4) * 16;
                uint32_t off = row*128 + (kb ^ ((row & 7) << 4));
                ldsm4(ah[mt], sbase + AH + off);
                ldsm4(al[mt], sbase + AL + off);
            }
            uint32_t bh[4][4], bl[4][4];
            #pragma unroll
            for (int g = 0; g < 4; g++) {
                uint32_t rowc = (uint32_t)ks*16 + (lane & 7) + ((lane >> 3) & 1) * 8;
                uint32_t nb   = ((uint32_t)n0w + g*16 + (lane >> 4) * 8) * 2;
                uint32_t off  = rowc*256 + (nb ^ ((rowc & 7) << 4));
                ldsm4t(bh[g], sbase + BH + off);
                ldsm4t(bl[g], sbase + BL + off);
            }
            #pragma unroll
            for (int mt = 0; mt < 2; mt++)
                #pragma unroll
                for (int nt = 0; nt < 8; nt++) {
                    uint32_t* fh = &bh[nt >> 1][(nt & 1) * 2];
                    uint32_t* fl = &bl[nt >> 1][(nt & 1) * 2];
                    mma_bf16(acc[mt][nt], ah[mt], fh);
                    mma_bf16(acc[mt][nt], ah[mt], fl);
                    mma_bf16(acc[mt][nt], al[mt], fh);
                }
        }
    }

    if (o0 < 512) {
        // q,k rows -> fp32 staging (l2norm consumes)
        #pragma unroll
        for (int mt = 0; mt < 2; mt++) {
            int o_lo = m0w + mt*16 + (lane >> 2);
            float bias0 = s_bias[o_lo];
            float bias8 = s_bias[o_lo + 8];
            float* base = &g_qkv[((size_t)ib*512 + o0)*HWN + n0];
            #pragma unroll
            for (int nt = 0; nt < 8; nt++) {
                int n_col = n0w + nt*8 + (lane & 3)*2;
                float2 v0 = { acc[mt][nt][0] + bias0, acc[mt][nt][1] + bias0 };
                float2 v1 = { acc[mt][nt][2] + bias8, acc[mt][nt][3] + bias8 };
                *(float2*)&base[(size_t)o_lo*HWN + n_col]     = v0;
                *(float2*)&base[(size_t)(o_lo+8)*HWN + n_col] = v1;
            }
        }
    } else {
        // v rows -> fp16 hi/lo directly (no normalization needed)
        int vo = o0 - 512;
        #pragma unroll
        for (int mt = 0; mt < 2; mt++) {
            int o_lo = m0w + mt*16 + (lane >> 2);
            float bias0 = s_bias[o_lo];
            float bias8 = s_bias[o_lo + 8];
            __half* vh_ = &g_v16h[((size_t)ib*CC + vo)*HWN + n0];
            __half* vl_ = &g_v16l[((size_t)ib*CC + vo)*HWN + n0];
            #pragma unroll
            for (int nt = 0; nt < 8; nt++) {
                int n_col = n0w + nt*8 + (lane & 3)*2;
                uint32_t h0, l0, h1, l1;
                split2h(acc[mt][nt][0] + bias0, acc[mt][nt][1] + bias0, h0, l0);
                split2h(acc[mt][nt][2] + bias8, acc[mt][nt][3] + bias8, h1, l1);
                *(uint32_t*)&vh_[(size_t)o_lo*HWN + n_col]     = h0;
                *(uint32_t*)&vl_[(size_t)o_lo*HWN + n_col]     = l0;
                *(uint32_t*)&vh_[(size_t)(o_lo+8)*HWN + n_col] = h1;
                *(uint32_t*)&vl_[(size_t)(o_lo+8)*HWN + n_col] = l1;
            }
        }
    }
}

// ---------------------------------------------------------------------------
// 3) l2-normalize q,k rows, emit single fp16.
//    q rows prescaled by 0.125*log2(e) (attention scale + exp2 folding).
// ---------------------------------------------------------------------------
__global__ __launch_bounds__(256) void l2norm_kernel()
{
    int row = blockIdx.x;                 // NB*512 rows
    int ib = row >> 9;
    int o = row & 511;
    const float* p = &g_qkv[((size_t)ib*512 + o)*HWN];
    int tid = threadIdx.x;
    float4 v = ((const float4*)p)[tid];
    float ss = v.x*v.x + v.y*v.y + v.z*v.z + v.w*v.w;
    #pragma unroll
    for (int off = 16; off; off >>= 1) ss += __shfl_xor_sync(0xffffffffu, ss, off);
    __shared__ float wsum[8];
    if ((tid & 31) == 0) wsum[tid >> 5] = ss;
    __syncthreads();
    float tot = wsum[0]+wsum[1]+wsum[2]+wsum[3]+wsum[4]+wsum[5]+wsum[6]+wsum[7];
    float inv = 1.f / fmaxf(sqrtf(tot), 1e-12f);
    if (o < 256) inv *= 0.18033688011112042f;   // 0.125 * log2(e)
    float s0 = v.x*inv, s1 = v.y*inv, s2 = v.z*inv, s3 = v.w*inv;
    uint2 outw;
    outw.x = packh2(s0, s1);
    outw.y = packh2(s2, s3);
    __half* dst = (o < 256) ? &g_q16[((size_t)ib*CC + o)*HWN]
                            : &g_k16[((size_t)ib*CC + (o - 256))*HWN];
    *(uint2*)&dst[tid*4] = outw;
}

// ---------------------------------------------------------------------------
// 4) flash attention, fp16 mma.sync.
//    S: q16 x k16 single product (scores tiny -> rounding negligible).
//    PV: P single fp16, V fp16 hi/lo (2 products).
//    exp2 domain (log2e folded into q prescale), raw ex2.approx.
// ---------------------------------------------------------------------------
#define FL_SMEM 65536   // Q 16K | K 16K | VH 16K | VL 16K

__global__ __launch_bounds__(256) void flash_mma()
{
    extern __shared__ char sm[];
    const uint32_t Qo = 0, Ko = 16384, VHo = 32768, VLo = 49152;
    uint32_t sbase = smem_to_u32(sm);

    int tid = threadIdx.x, wid = tid >> 5, lane = tid & 31;
    int it = blockIdx.x, h = blockIdx.y, ib = blockIdx.z;
    int i0 = it * 128;
    int m0w = wid * 16;

    const __half* q16 = g_q16  + ((size_t)ib*CC + h*HD)*HWN;
    const __half* k16 = g_k16  + ((size_t)ib*CC + h*HD)*HWN;
    const __half* v6h = g_v16h + ((size_t)ib*CC + h*HD)*HWN;
    const __half* v6l = g_v16l + ((size_t)ib*CC + h*HD)*HWN;

    // Q tile (once): 64 c-rows x 128 tok fp16, swizzled 256B rows
    #pragma unroll
    for (int i = 0; i < 4; i++) {
        int e = i*256 + tid;
        int c = e >> 4, t = (e & 15) * 8;
        uint32_t off = (uint32_t)c*256 + (((uint32_t)t*2) ^ (((uint32_t)c & 7) << 4));
        *(uint4*)(sm + Qo + off) = *(const uint4*)&q16[(size_t)c*HWN + i0 + t];
    }

    float o[8][4];
    #pragma unroll
    for (int n = 0; n < 8; n++)
        #pragma unroll
        for (int q = 0; q < 4; q++) o[n][q] = 0.f;
    float mr0 = -1e30f, mr1 = -1e30f, lr0 = 0.f, lr1 = 0.f;

    #pragma unroll 1
    for (int j0 = 0; j0 < HWN; j0 += 128) {
        __syncthreads();
        #pragma unroll
        for (int i = 0; i < 4; i++) {
            int e = i*256 + tid;
            int c = e >> 4, t = (e & 15) * 8;
            uint32_t off = (uint32_t)c*256 + (((uint32_t)t*2) ^ (((uint32_t)c & 7) << 4));
            *(uint4*)(sm + Ko  + off) = *(const uint4*)&k16[(size_t)c*HWN + j0 + t];
            *(uint4*)(sm + VHo + off) = *(const uint4*)&v6h[(size_t)c*HWN + j0 + t];
            *(uint4*)(sm + VLo + off) = *(const uint4*)&v6l[(size_t)c*HWN + j0 + t];
        }
        __syncthreads();

        // ---- S = Q^T K (log2-domain, pre-scaled q), single fp16 product ----
        float s[16][4];
        #pragma unroll
        for (int j = 0; j < 16; j++)
            #pragma unroll
            for (int q = 0; q < 4; q++) s[j][q] = 0.f;

        #pragma unroll
        for (int ks = 0; ks < 4; ks++) {
            uint32_t ah[4];
            {
                // A-from-trans: k-select bit = lane>>4, m-select bit = lane>>3
                uint32_t c = (uint32_t)ks*16 + (lane & 7) + ((lane >> 4) & 1) * 8;
                uint32_t t = (uint32_t)m0w + ((lane >> 3) & 1) * 8;
                uint32_t off = c*256 + ((t*2) ^ ((c & 7) << 4));
                ldsm4t(ah, sbase + Qo + off);
            }
            #pragma unroll
            for (int g = 0; g < 8; g++) {
                uint32_t bh[4];
                // B-from-trans: k-select bit = lane>>3, n-select bit = lane>>4
                uint32_t c = (uint32_t)ks*16 + (lane & 7) + ((lane >> 3) & 1) * 8;
                uint32_t t = (uint32_t)g*16 + ((lane >> 4) & 1) * 8;
                uint32_t off = c*256 + ((t*2) ^ ((c & 7) << 4));
                ldsm4t(bh, sbase + Ko + off);
                mma_f16(s[g*2 + 0], ah, &bh[0]);
                mma_f16(s[g*2 + 1], ah, &bh[2]);
            }
        }

        // ---- online softmax in exp2 domain ----
        float mx0 = -1e30f, mx1 = -1e30f;
        #pragma unroll
        for (int j = 0; j < 16; j++) {
            mx0 = fmaxf(mx0, fmaxf(s[j][0], s[j][1]));
            mx1 = fmaxf(mx1, fmaxf(s[j][2], s[j][3]));
        }
        #pragma unroll
        for (int off = 1; off < 4; off <<= 1) {
            mx0 = fmaxf(mx0, __shfl_xor_sync(0xffffffffu, mx0, off));
            mx1 = fmaxf(mx1, __shfl_xor_sync(0xffffffffu, mx1, off));
        }
        float mn0 = fmaxf(mr0, mx0), mn1 = fmaxf(mr1, mx1);
        float al0 = ex2f(mr0 - mn0), al1 = ex2f(mr1 - mn1);
        mr0 = mn0; mr1 = mn1;
        float rs0 = 0.f, rs1 = 0.f;
        #pragma unroll
        for (int j = 0; j < 16; j++) {
            s[j][0] = ex2f(s[j][0] - mn0);
            s[j][1] = ex2f(s[j][1] - mn0);
            s[j][2] = ex2f(s[j][2] - mn1);
            s[j][3] = ex2f(s[j][3] - mn1);
            rs0 += s[j][0] + s[j][1];
            rs1 += s[j][2] + s[j][3];
        }
        #pragma unroll
        for (int off = 1; off < 4; off <<= 1) {
            rs0 += __shfl_xor_sync(0xffffffffu, rs0, off);
            rs1 += __shfl_xor_sync(0xffffffffu, rs1, off);
        }
        lr0 = lr0*al0 + rs0;
        lr1 = lr1*al1 + rs1;
        #pragma unroll
        for (int n = 0; n < 8; n++) {
            o[n][0] *= al0; o[n][1] *= al0;
            o[n][2] *= al1; o[n][3] *= al1;
        }

        // ---- O += P (Vh + Vl)^T ; P single fp16 (FA2 repack) ----
        #pragma unroll
        for (int ks = 0; ks < 8; ks++) {
            uint32_t ph[4];
            ph[0] = packh2(s[2*ks][0],   s[2*ks][1]);
            ph[1] = packh2(s[2*ks][2],   s[2*ks][3]);
            ph[2] = packh2(s[2*ks+1][0], s[2*ks+1][1]);
            ph[3] = packh2(s[2*ks+1][2], s[2*ks+1][3]);
            #pragma unroll
            for (int g = 0; g < 4; g++) {
                uint32_t bh[4], bl[4];
                // B non-trans from [d][j]: d-select bit = lane>>4, j-select = lane>>3
                uint32_t d  = (uint32_t)g*16 + (lane & 7) + ((lane >> 4) & 1) * 8;
                uint32_t jb = (uint32_t)ks*32 + ((lane >> 3) & 1) * 16;
                uint32_t off = d*256 + (jb ^ ((d & 7) << 4));
                ldsm4(bh, sbase + VHo + off);
                ldsm4(bl, sbase + VLo + off);
                #pragma unroll
                for (int half = 0; half < 2; half++) {
                    float* acc = o[g*2 + half];
                    mma_f16(acc, ph, &bh[half*2]);
                    mma_f16(acc, ph, &bl[half*2]);
                }
            }
        }
    }

    // ---- epilogue: normalize, stage via swizzled smem, coalesced store ----
    __syncthreads();
    float* outs = (float*)sm;   // [64 d][128 tok] fp32, word-XOR swizzle
    float inv0 = 1.f / lr0, inv1 = 1.f / lr1;
    int r = lane >> 2;
    #pragma unroll
    for (int n = 0; n < 8; n++) {
        int d0 = n*8 + (lane & 3)*2;
        int d1 = d0 + 1;
        int tl = m0w + r, th = tl + 8;
        outs[d0*128 + (tl ^ ((d0 & 7) << 2))] = o[n][0]*inv0;
        outs[d1*128 + (tl ^ ((d1 & 7) << 2))] = o[n][1]*inv0;
        outs[d0*128 + (th ^ ((d0 & 7) << 2))] = o[n][2]*inv1;
        outs[d1*128 + (th ^ ((d1 & 7) << 2))] = o[n][3]*inv1;
    }
    __syncthreads();
    float* og = &g_att[((size_t)ib*CC + h*HD)*HWN + i0];
    #pragma unroll
    for (int i = 0; i < 8; i++) {
        int e = i*256 + tid;
        int d = e >> 5, t4 = (e & 31) * 4;
        float4 val = *(const float4*)&outs[d*128 + (t4 ^ ((d & 7) << 2))];
        *(float4*)&og[(size_t)d*HWN + t4] = val;
    }
}

// ---------------------------------------------------------------------------
// 5) out[b,c,n] = sum_i att[i,b,c,n] * mask[b,i,n]  (deterministic order)
// ---------------------------------------------------------------------------
__global__ __launch_bounds__(256) void out_kernel(float* __restrict__ out)
{
    int idx = blockIdx.x*256 + threadIdx.x;   // < B*C*HW = 2^21
    int b = idx >> 18;                        // C*HW = 262144
    int rem = idx & 262143;
    int n = rem & 1023;
    float acc = 0.f;
    #pragma unroll
    for (int i = 0; i < NI; i++) {
        acc = fmaf(g_att[(size_t)(i*BB + b)*262144 + rem],
                   g_mask[(b*NI + i)*HWN + n], acc);
    }
    out[idx] = acc;
}

// ---------------------------------------------------------------------------
extern "C" void kernel_launch(void* const* d_in, const int* in_sizes, int n_in,
                              void* d_out, int out_size)
{
    const float* x      = (const float*)d_in[0];
    const float* w_inst = (const float*)d_in[1];
    const float* b_inst = (const float*)d_in[2];
    const float* w_q    = (const float*)d_in[3];
    const float* b_q    = (const float*)d_in[4];
    const float* w_k    = (const float*)d_in[5];
    const float* b_k    = (const float*)d_in[6];
    const float* w_v    = (const float*)d_in[7];
    const float* b_v    = (const float*)d_in[8];
    float* out = (float*)d_out;

    static bool attr_done = false;
    if (!attr_done) {
        cudaFuncSetAttribute(qkv_mma, cudaFuncAttributeMaxDynamicSharedMemorySize,
                             QKV_SMEM_BYTES);
        cudaFuncSetAttribute(flash_mma, cudaFuncAttributeMaxDynamicSharedMemorySize,
                             FL_SMEM);
        attr_done = true;
    }

    mask_kernel<<<32, 256>>>(x, w_inst, b_inst);
    prep_kernel<<<(CC*CC + 255)/256, 256>>>(w_q, b_q, w_k, b_k, w_v, b_v);
    qkv_mma<<<dim3(8, 6, NB), 256, QKV_SMEM_BYTES>>>(x);
    l2norm_kernel<<<NB*512, 256>>>();
    flash_mma<<<dim3(8, NH, NB), 256, FL_SMEM>>>();
    out_kernel<<<(BB*CC*HWN)/256, 256>>>(out);
}

// round 11
// speedup vs baseline: 4.6643x; 1.2281x over previous
#include <cuda_runtime.h>
#include <cuda_bf16.h>
#include <cuda_fp16.h>
#include <cstdint>

#define BB 8
#define CC 256
#define HWN 1024
#define NI 8
#define NH 4
#define HD 64
#define NB (NI*BB)   // 64 (instance,batch) pairs

// Scratch (static device globals; no allocations anywhere)
__device__ __half g_w16h[3*CC*CC];       // W fp16 hi [768][256]
__device__ __half g_w16l[3*CC*CC];       // W fp16 lo
__device__ float g_b3[3*CC];
__device__ float g_mask[BB*NI*HWN];      // [b][i][n] softmaxed instance masks
__device__ float g_qkv[(size_t)NB*2*CC*HWN];    // fp32 q,k rows only (~134MB)
__device__ __half g_q16[(size_t)NB*CC*HWN];     // fp16 q (prescaled)  (~33MB)
__device__ __half g_k16[(size_t)NB*CC*HWN];     // fp16 k              (~33MB)
__device__ __half g_v16[(size_t)NB*CC*HWN];     // fp16 v              (~33MB)
__device__ float g_att[(size_t)NB*CC*HWN];      // per-instance attention out (~67MB)

// ===========================================================================
// mma.sync / ldmatrix helpers (baseline PTX — works at compute_103 target)
// ===========================================================================
__device__ __forceinline__ uint32_t smem_to_u32(const void* p) {
    uint32_t a;
    asm("{ .reg .u64 t; cvta.to.shared.u64 t, %1; cvt.u32.u64 %0, t; }"
        : "=r"(a) : "l"(p));
    return a;
}
__device__ __forceinline__ void ldsm4(uint32_t* r, uint32_t addr) {
    asm volatile("ldmatrix.sync.aligned.m8n8.x4.shared.b16 {%0,%1,%2,%3}, [%4];"
        : "=r"(r[0]), "=r"(r[1]), "=r"(r[2]), "=r"(r[3]) : "r"(addr));
}
__device__ __forceinline__ void ldsm4t(uint32_t* r, uint32_t addr) {
    asm volatile("ldmatrix.sync.aligned.m8n8.x4.trans.shared.b16 {%0,%1,%2,%3}, [%4];"
        : "=r"(r[0]), "=r"(r[1]), "=r"(r[2]), "=r"(r[3]) : "r"(addr));
}
__device__ __forceinline__ void mma_f16(float* c, const uint32_t* a, const uint32_t* b) {
    asm volatile(
        "mma.sync.aligned.m16n8k16.row.col.f32.f16.f16.f32 "
        "{%0,%1,%2,%3}, {%4,%5,%6,%7}, {%8,%9}, {%0,%1,%2,%3};"
        : "+f"(c[0]), "+f"(c[1]), "+f"(c[2]), "+f"(c[3])
        : "r"(a[0]), "r"(a[1]), "r"(a[2]), "r"(a[3]), "r"(b[0]), "r"(b[1]));
}
__device__ __forceinline__ uint32_t packh2(float a, float b) {
    __half2 h = __floats2half2_rn(a, b);
    return *(uint32_t*)&h;
}
__device__ __forceinline__ float ex2f(float x) {
    float r;
    asm("ex2.approx.f32 %0, %1;" : "=f"(r) : "f"(x));
    return r;
}

// ---------------------------------------------------------------------------
// 1) instance conv + softmax over instance axis
// ---------------------------------------------------------------------------
__global__ __launch_bounds__(256) void mask_kernel(
    const float* __restrict__ x, const float* __restrict__ w_inst,
    const float* __restrict__ b_inst)
{
    __shared__ float ws[NI*CC];
    int tid = threadIdx.x;
    for (int k = tid; k < NI*CC; k += 256) ws[k] = w_inst[k];
    __syncthreads();

    int gid = blockIdx.x*256 + tid;          // 0..8191 = B*HW
    int b = gid >> 10, n = gid & 1023;
    float acc[NI];
    #pragma unroll
    for (int i = 0; i < NI; i++) acc[i] = 0.f;
    const float* xp = x + (size_t)b*CC*HWN + n;
    for (int c = 0; c < CC; c++) {
        float xv = xp[c*HWN];
        #pragma unroll
        for (int i = 0; i < NI; i++) acc[i] = fmaf(ws[i*CC + c], xv, acc[i]);
    }
    float m = -1e30f;
    #pragma unroll
    for (int i = 0; i < NI; i++) { acc[i] += b_inst[i]; m = fmaxf(m, acc[i]); }
    float s = 0.f;
    #pragma unroll
    for (int i = 0; i < NI; i++) { acc[i] = __expf(acc[i] - m); s += acc[i]; }
    float inv = 1.f / s;
    #pragma unroll
    for (int i = 0; i < NI; i++) g_mask[(b*NI + i)*HWN + n] = acc[i]*inv;
}

// ---------------------------------------------------------------------------
// 2a) concat weights into fp16 hi/lo [768][256]; biases fp32
// ---------------------------------------------------------------------------
__global__ __launch_bounds__(256) void prep_kernel(
    const float* __restrict__ wq, const float* __restrict__ bq,
    const float* __restrict__ wk, const float* __restrict__ bk,
    const float* __restrict__ wv, const float* __restrict__ bv)
{
    int idx = blockIdx.x*256 + threadIdx.x;
    if (idx < CC*CC) {
        float w0 = wq[idx], w1 = wk[idx], w2 = wv[idx];
        __half h0 = __float2half_rn(w0);
        __half h1 = __float2half_rn(w1);
        __half h2 = __float2half_rn(w2);
        g_w16h[idx]           = h0;
        g_w16h[CC*CC + idx]   = h1;
        g_w16h[2*CC*CC + idx] = h2;
        g_w16l[idx]           = __float2half_rn(w0 - __half2float(h0));
        g_w16l[CC*CC + idx]   = __float2half_rn(w1 - __half2float(h1));
        g_w16l[2*CC*CC + idx] = __float2half_rn(w2 - __half2float(h2));
    }
    if (idx < CC) { g_b3[idx] = bq[idx]; g_b3[CC+idx] = bk[idx]; g_b3[2*CC+idx] = bv[idx]; }
}

// ---------------------------------------------------------------------------
// 2b) QKV GEMM: A = W fp16 hi/lo (pre-split, pure copy to smem),
//     B = masked x single fp16. 2 MMAs per fragment pair: Ah*B + Al*B.
//     q,k rows (o0<512) -> fp32 g_qkv; v rows (o0>=512) -> fp16 direct.
// ---------------------------------------------------------------------------
#define QKV_SMEM_BYTES 49152   // AH 16K | AL 16K | B 16K

__global__ __launch_bounds__(256) void qkv_mma(const float* __restrict__ x)
{
    extern __shared__ char sm[];
    __shared__ float s_msk[128];
    __shared__ float s_bias[128];

    const uint32_t AH = 0, AL = 16384, BS = 32768;
    uint32_t sbase = smem_to_u32(sm);

    int tid = threadIdx.x;
    int wid = tid >> 5, lane = tid & 31;
    int n0 = blockIdx.x * 128;
    int o0 = blockIdx.y * 128;
    int ib = blockIdx.z;
    int b = ib & 7, inst = ib >> 3;

    if (tid < 128) s_msk[tid] = g_mask[(b*NI + inst)*HWN + n0 + tid];
    else           s_bias[tid-128] = g_b3[o0 + tid - 128];

    float acc[2][8][4];
    #pragma unroll
    for (int mt = 0; mt < 2; mt++)
        #pragma unroll
        for (int nt = 0; nt < 8; nt++)
            #pragma unroll
            for (int q = 0; q < 4; q++) acc[mt][nt][q] = 0.f;

    const int m0w = (wid & 3) * 32;
    const int n0w = (wid >> 2) * 64;

    #pragma unroll 1
    for (int kc = 0; kc < 4; kc++) {
        __syncthreads();

        // ---- A tiles: direct fp16 copy, swizzled [m][k] rows (128B)
        const __half* wph = g_w16h + (size_t)o0*CC + kc*64;
        const __half* wpl = g_w16l + (size_t)o0*CC + kc*64;
        #pragma unroll
        for (int i = 0; i < 4; i++) {
            int e = i*256 + tid;
            int m = e >> 3, cq = (e & 7) * 8;    // 8 halves = 16B per item
            uint32_t off = (uint32_t)m*128 + (((uint32_t)cq*2) ^ (((uint32_t)m & 7) << 4));
            *(uint4*)(sm + AH + off) = *(const uint4*)&wph[(size_t)m*CC + cq];
            *(uint4*)(sm + AL + off) = *(const uint4*)&wpl[(size_t)m*CC + cq];
        }
        // ---- B tile: (x*mask) single fp16, swizzled [c][n] rows (256B)
        const float* xp = x + ((size_t)b*CC + kc*64)*HWN + n0;
        #pragma unroll
        for (int i = 0; i < 8; i++) {
            int e = i*256 + tid;
            int c = e >> 5, n4 = (e & 31) * 4;
            float4 v = *(const float4*)&xp[(size_t)c*HWN + n4];
            uint2 hv;
            hv.x = packh2(v.x * s_msk[n4+0], v.y * s_msk[n4+1]);
            hv.y = packh2(v.z * s_msk[n4+2], v.w * s_msk[n4+3]);
            uint32_t off = (uint32_t)c*256 + (((uint32_t)n4*2) ^ (((uint32_t)c & 7) << 4));
            *(uint2*)(sm + BS + off) = hv;
        }
        __syncthreads();

        #pragma unroll
        for (int ks = 0; ks < 4; ks++) {
            uint32_t ah[2][4], al[2][4];
            #pragma unroll
            for (int mt = 0; mt < 2; mt++) {
                uint32_t row = m0w + mt*16 + (lane & 7) + ((lane >> 3) & 1) * 8;
                uint32_t kb  = (uint32_t)ks*32 + (lane >> 4) * 16;
                uint32_t off = row*128 + (kb ^ ((row & 7) << 4));
                ldsm4(ah[mt], sbase + AH + off);
                ldsm4(al[mt], sbase + AL + off);
            }
            uint32_t bf[4][4];
            #pragma unroll
            for (int g = 0; g < 4; g++) {
                uint32_t rowc = (uint32_t)ks*16 + (lane & 7) + ((lane >> 3) & 1) * 8;
                uint32_t nb   = ((uint32_t)n0w + g*16 + (lane >> 4) * 8) * 2;
                uint32_t off  = rowc*256 + (nb ^ ((rowc & 7) << 4));
                ldsm4t(bf[g], sbase + BS + off);
            }
            #pragma unroll
            for (int mt = 0; mt < 2; mt++)
                #pragma unroll
                for (int nt = 0; nt < 8; nt++) {
                    uint32_t* fb = &bf[nt >> 1][(nt & 1) * 2];
                    mma_f16(acc[mt][nt], ah[mt], fb);
                    mma_f16(acc[mt][nt], al[mt], fb);
                }
        }
    }

    if (o0 < 512) {
        // q,k rows -> fp32 staging (l2norm consumes)
        #pragma unroll
        for (int mt = 0; mt < 2; mt++) {
            int o_lo = m0w + mt*16 + (lane >> 2);
            float bias0 = s_bias[o_lo];
            float bias8 = s_bias[o_lo + 8];
            float* base = &g_qkv[((size_t)ib*512 + o0)*HWN + n0];
            #pragma unroll
            for (int nt = 0; nt < 8; nt++) {
                int n_col = n0w + nt*8 + (lane & 3)*2;
                float2 v0 = { acc[mt][nt][0] + bias0, acc[mt][nt][1] + bias0 };
                float2 v1 = { acc[mt][nt][2] + bias8, acc[mt][nt][3] + bias8 };
                *(float2*)&base[(size_t)o_lo*HWN + n_col]     = v0;
                *(float2*)&base[(size_t)(o_lo+8)*HWN + n_col] = v1;
            }
        }
    } else {
        // v rows -> single fp16 directly
        int vo = o0 - 512;
        #pragma unroll
        for (int mt = 0; mt < 2; mt++) {
            int o_lo = m0w + mt*16 + (lane >> 2);
            float bias0 = s_bias[o_lo];
            float bias8 = s_bias[o_lo + 8];
            __half* vh_ = &g_v16[((size_t)ib*CC + vo)*HWN + n0];
            #pragma unroll
            for (int nt = 0; nt < 8; nt++) {
                int n_col = n0w + nt*8 + (lane & 3)*2;
                *(uint32_t*)&vh_[(size_t)o_lo*HWN + n_col] =
                    packh2(acc[mt][nt][0] + bias0, acc[mt][nt][1] + bias0);
                *(uint32_t*)&vh_[(size_t)(o_lo+8)*HWN + n_col] =
                    packh2(acc[mt][nt][2] + bias8, acc[mt][nt][3] + bias8);
            }
        }
    }
}

// ---------------------------------------------------------------------------
// 3) l2-normalize q,k rows, emit single fp16.
//    q rows prescaled by 0.125*log2(e) (attention scale + exp2 folding).
// ---------------------------------------------------------------------------
__global__ __launch_bounds__(256) void l2norm_kernel()
{
    int row = blockIdx.x;                 // NB*512 rows
    int ib = row >> 9;
    int o = row & 511;
    const float* p = &g_qkv[((size_t)ib*512 + o)*HWN];
    int tid = threadIdx.x;
    float4 v = ((const float4*)p)[tid];
    float ss = v.x*v.x + v.y*v.y + v.z*v.z + v.w*v.w;
    #pragma unroll
    for (int off = 16; off; off >>= 1) ss += __shfl_xor_sync(0xffffffffu, ss, off);
    __shared__ float wsum[8];
    if ((tid & 31) == 0) wsum[tid >> 5] = ss;
    __syncthreads();
    float tot = wsum[0]+wsum[1]+wsum[2]+wsum[3]+wsum[4]+wsum[5]+wsum[6]+wsum[7];
    float inv = 1.f / fmaxf(sqrtf(tot), 1e-12f);
    if (o < 256) inv *= 0.18033688011112042f;   // 0.125 * log2(e)
    float s0 = v.x*inv, s1 = v.y*inv, s2 = v.z*inv, s3 = v.w*inv;
    uint2 outw;
    outw.x = packh2(s0, s1);
    outw.y = packh2(s2, s3);
    __half* dst = (o < 256) ? &g_q16[((size_t)ib*CC + o)*HWN]
                            : &g_k16[((size_t)ib*CC + (o - 256))*HWN];
    *(uint2*)&dst[tid*4] = outw;
}

// ---------------------------------------------------------------------------
// 4) flash attention, fp16 mma.sync. S: 1 MMA; PV: 1 MMA (V single fp16).
//    exp2 domain (log2e folded into q prescale), raw ex2.approx.
// ---------------------------------------------------------------------------
#define FL_SMEM 49152   // Q 16K | K 16K | V 16K

__global__ __launch_bounds__(256) void flash_mma()
{
    extern __shared__ char sm[];
    const uint32_t Qo = 0, Ko = 16384, Vo = 32768;
    uint32_t sbase = smem_to_u32(sm);

    int tid = threadIdx.x, wid = tid >> 5, lane = tid & 31;
    int it = blockIdx.x, h = blockIdx.y, ib = blockIdx.z;
    int i0 = it * 128;
    int m0w = wid * 16;

    const __half* q16 = g_q16 + ((size_t)ib*CC + h*HD)*HWN;
    const __half* k16 = g_k16 + ((size_t)ib*CC + h*HD)*HWN;
    const __half* v16 = g_v16 + ((size_t)ib*CC + h*HD)*HWN;

    // Q tile (once): 64 c-rows x 128 tok fp16, swizzled 256B rows
    #pragma unroll
    for (int i = 0; i < 4; i++) {
        int e = i*256 + tid;
        int c = e >> 4, t = (e & 15) * 8;
        uint32_t off = (uint32_t)c*256 + (((uint32_t)t*2) ^ (((uint32_t)c & 7) << 4));
        *(uint4*)(sm + Qo + off) = *(const uint4*)&q16[(size_t)c*HWN + i0 + t];
    }

    float o[8][4];
    #pragma unroll
    for (int n = 0; n < 8; n++)
        #pragma unroll
        for (int q = 0; q < 4; q++) o[n][q] = 0.f;
    float mr0 = -1e30f, mr1 = -1e30f, lr0 = 0.f, lr1 = 0.f;

    #pragma unroll 1
    for (int j0 = 0; j0 < HWN; j0 += 128) {
        __syncthreads();
        #pragma unroll
        for (int i = 0; i < 4; i++) {
            int e = i*256 + tid;
            int c = e >> 4, t = (e & 15) * 8;
            uint32_t off = (uint32_t)c*256 + (((uint32_t)t*2) ^ (((uint32_t)c & 7) << 4));
            *(uint4*)(sm + Ko + off) = *(const uint4*)&k16[(size_t)c*HWN + j0 + t];
            *(uint4*)(sm + Vo + off) = *(const uint4*)&v16[(size_t)c*HWN + j0 + t];
        }
        __syncthreads();

        // ---- S = Q^T K (log2-domain, pre-scaled q) ----
        float s[16][4];
        #pragma unroll
        for (int j = 0; j < 16; j++)
            #pragma unroll
            for (int q = 0; q < 4; q++) s[j][q] = 0.f;

        #pragma unroll
        for (int ks = 0; ks < 4; ks++) {
            uint32_t ah[4];
            {
                // A-from-trans: k-select bit = lane>>4, m-select bit = lane>>3
                uint32_t c = (uint32_t)ks*16 + (lane & 7) + ((lane >> 4) & 1) * 8;
                uint32_t t = (uint32_t)m0w + ((lane >> 3) & 1) * 8;
                uint32_t off = c*256 + ((t*2) ^ ((c & 7) << 4));
                ldsm4t(ah, sbase + Qo + off);
            }
            #pragma unroll
            for (int g = 0; g < 8; g++) {
                uint32_t bh[4];
                // B-from-trans: k-select bit = lane>>3, n-select bit = lane>>4
                uint32_t c = (uint32_t)ks*16 + (lane & 7) + ((lane >> 3) & 1) * 8;
                uint32_t t = (uint32_t)g*16 + ((lane >> 4) & 1) * 8;
                uint32_t off = c*256 + ((t*2) ^ ((c & 7) << 4));
                ldsm4t(bh, sbase + Ko + off);
                mma_f16(s[g*2 + 0], ah, &bh[0]);
                mma_f16(s[g*2 + 1], ah, &bh[2]);
            }
        }

        // ---- online softmax in exp2 domain ----
        float mx0 = -1e30f, mx1 = -1e30f;
        #pragma unroll
        for (int j = 0; j < 16; j++) {
            mx0 = fmaxf(mx0, fmaxf(s[j][0], s[j][1]));
            mx1 = fmaxf(mx1, fmaxf(s[j][2], s[j][3]));
        }
        #pragma unroll
        for (int off = 1; off < 4; off <<= 1) {
            mx0 = fmaxf(mx0, __shfl_xor_sync(0xffffffffu, mx0, off));
            mx1 = fmaxf(mx1, __shfl_xor_sync(0xffffffffu, mx1, off));
        }
        float mn0 = fmaxf(mr0, mx0), mn1 = fmaxf(mr1, mx1);
        float al0 = ex2f(mr0 - mn0), al1 = ex2f(mr1 - mn1);
        mr0 = mn0; mr1 = mn1;
        float rs0 = 0.f, rs1 = 0.f;
        #pragma unroll
        for (int j = 0; j < 16; j++) {
            s[j][0] = ex2f(s[j][0] - mn0);
            s[j][1] = ex2f(s[j][1] - mn0);
            s[j][2] = ex2f(s[j][2] - mn1);
            s[j][3] = ex2f(s[j][3] - mn1);
            rs0 += s[j][0] + s[j][1];
            rs1 += s[j][2] + s[j][3];
        }
        #pragma unroll
        for (int off = 1; off < 4; off <<= 1) {
            rs0 += __shfl_xor_sync(0xffffffffu, rs0, off);
            rs1 += __shfl_xor_sync(0xffffffffu, rs1, off);
        }
        lr0 = lr0*al0 + rs0;
        lr1 = lr1*al1 + rs1;
        #pragma unroll
        for (int n = 0; n < 8; n++) {
            o[n][0] *= al0; o[n][1] *= al0;
            o[n][2] *= al1; o[n][3] *= al1;
        }

        // ---- O += P V^T ; P single fp16 (FA2 repack), V single fp16 ----
        #pragma unroll
        for (int ks = 0; ks < 8; ks++) {
            uint32_t ph[4];
            ph[0] = packh2(s[2*ks][0],   s[2*ks][1]);
            ph[1] = packh2(s[2*ks][2],   s[2*ks][3]);
            ph[2] = packh2(s[2*ks+1][0], s[2*ks+1][1]);
            ph[3] = packh2(s[2*ks+1][2], s[2*ks+1][3]);
            #pragma unroll
            for (int g = 0; g < 4; g++) {
                uint32_t bh[4];
                // B non-trans from [d][j]: d-select bit = lane>>4, j-select = lane>>3
                uint32_t d  = (uint32_t)g*16 + (lane & 7) + ((lane >> 4) & 1) * 8;
                uint32_t jb = (uint32_t)ks*32 + ((lane >> 3) & 1) * 16;
                uint32_t off = d*256 + (jb ^ ((d & 7) << 4));
                ldsm4(bh, sbase + Vo + off);
                mma_f16(o[g*2 + 0], ph, &bh[0]);
                mma_f16(o[g*2 + 1], ph, &bh[2]);
            }
        }
    }

    // ---- epilogue: normalize, stage via swizzled smem, coalesced store ----
    __syncthreads();
    float* outs = (float*)sm;   // [64 d][128 tok] fp32, word-XOR swizzle
    float inv0 = 1.f / lr0, inv1 = 1.f / lr1;
    int r = lane >> 2;
    #pragma unroll
    for (int n = 0; n < 8; n++) {
        int d0 = n*8 + (lane & 3)*2;
        int d1 = d0 + 1;
        int tl = m0w + r, th = tl + 8;
        outs[d0*128 + (tl ^ ((d0 & 7) << 2))] = o[n][0]*inv0;
        outs[d1*128 + (tl ^ ((d1 & 7) << 2))] = o[n][1]*inv0;
        outs[d0*128 + (th ^ ((d0 & 7) << 2))] = o[n][2]*inv1;
        outs[d1*128 + (th ^ ((d1 & 7) << 2))] = o[n][3]*inv1;
    }
    __syncthreads();
    float* og = &g_att[((size_t)ib*CC + h*HD)*HWN + i0];
    #pragma unroll
    for (int i = 0; i < 8; i++) {
        int e = i*256 + tid;
        int d = e >> 5, t4 = (e & 31) * 4;
        float4 val = *(const float4*)&outs[d*128 + (t4 ^ ((d & 7) << 2))];
        *(float4*)&og[(size_t)d*HWN + t4] = val;
    }
}

// ---------------------------------------------------------------------------
// 5) out[b,c,n] = sum_i att[i,b,c,n] * mask[b,i,n]  (deterministic order)
// ---------------------------------------------------------------------------
__global__ __launch_bounds__(256) void out_kernel(float* __restrict__ out)
{
    int idx = blockIdx.x*256 + threadIdx.x;   // < B*C*HW = 2^21
    int b = idx >> 18;                        // C*HW = 262144
    int rem = idx & 262143;
    int n = rem & 1023;
    float acc = 0.f;
    #pragma unroll
    for (int i = 0; i < NI; i++) {
        acc = fmaf(g_att[(size_t)(i*BB + b)*262144 + rem],
                   g_mask[(b*NI + i)*HWN + n], acc);
    }
    out[idx] = acc;
}

// ---------------------------------------------------------------------------
extern "C" void kernel_launch(void* const* d_in, const int* in_sizes, int n_in,
                              void* d_out, int out_size)
{
    const float* x      = (const float*)d_in[0];
    const float* w_inst = (const float*)d_in[1];
    const float* b_inst = (const float*)d_in[2];
    const float* w_q    = (const float*)d_in[3];
    const float* b_q    = (const float*)d_in[4];
    const float* w_k    = (const float*)d_in[5];
    const float* b_k    = (const float*)d_in[6];
    const float* w_v    = (const float*)d_in[7];
    const float* b_v    = (const float*)d_in[8];
    float* out = (float*)d_out;

    static bool attr_done = false;
    if (!attr_done) {
        cudaFuncSetAttribute(qkv_mma, cudaFuncAttributeMaxDynamicSharedMemorySize,
                             QKV_SMEM_BYTES);
        cudaFuncSetAttribute(flash_mma, cudaFuncAttributeMaxDynamicSharedMemorySize,
                             FL_SMEM);
        attr_done = true;
    }

    mask_kernel<<<32, 256>>>(x, w_inst, b_inst);
    prep_kernel<<<(CC*CC + 255)/256, 256>>>(w_q, b_q, w_k, b_k, w_v, b_v);
    qkv_mma<<<dim3(8, 6, NB), 256, QKV_SMEM_BYTES>>>(x);
    l2norm_kernel<<<NB*512, 256>>>();
    flash_mma<<<dim3(8, NH, NB), 256, FL_SMEM>>>();
    out_kernel<<<(BB*CC*HWN)/256, 256>>>(out);
}

// round 12
// speedup vs baseline: 5.6283x; 1.2067x over previous
#include <cuda_runtime.h>
#include <cuda_bf16.h>
#include <cuda_fp16.h>
#include <cstdint>

#define BB 8
#define CC 256
#define HWN 1024
#define NI 8
#define NH 4
#define HD 64
#define NB (NI*BB)   // 64 (instance,batch) pairs

// Scratch (static device globals; no allocations anywhere)
__device__ __half g_w16h[3*CC*CC];       // W fp16 hi [768][256]
__device__ __half g_w16l[3*CC*CC];       // W fp16 lo
__device__ float g_b3[3*CC];
__device__ float g_mask[BB*NI*HWN];      // [b][i][n] softmaxed instance masks
__device__ __half g_q16[(size_t)NB*CC*HWN];     // fp16 q  (~33MB)
__device__ __half g_k16[(size_t)NB*CC*HWN];     // fp16 k  (~33MB)
__device__ __half g_v16[(size_t)NB*CC*HWN];     // fp16 v  (~33MB)
__device__ float g_att[(size_t)NB*CC*HWN];      // per-instance attention out (~67MB)

// ===========================================================================
// mma.sync / ldmatrix / cp.async helpers (baseline PTX — compute_103 OK)
// ===========================================================================
__device__ __forceinline__ uint32_t smem_to_u32(const void* p) {
    uint32_t a;
    asm("{ .reg .u64 t; cvta.to.shared.u64 t, %1; cvt.u32.u64 %0, t; }"
        : "=r"(a) : "l"(p));
    return a;
}
__device__ __forceinline__ void ldsm4(uint32_t* r, uint32_t addr) {
    asm volatile("ldmatrix.sync.aligned.m8n8.x4.shared.b16 {%0,%1,%2,%3}, [%4];"
        : "=r"(r[0]), "=r"(r[1]), "=r"(r[2]), "=r"(r[3]) : "r"(addr));
}
__device__ __forceinline__ void ldsm4t(uint32_t* r, uint32_t addr) {
    asm volatile("ldmatrix.sync.aligned.m8n8.x4.trans.shared.b16 {%0,%1,%2,%3}, [%4];"
        : "=r"(r[0]), "=r"(r[1]), "=r"(r[2]), "=r"(r[3]) : "r"(addr));
}
__device__ __forceinline__ void mma_f16(float* c, const uint32_t* a, const uint32_t* b) {
    asm volatile(
        "mma.sync.aligned.m16n8k16.row.col.f32.f16.f16.f32 "
        "{%0,%1,%2,%3}, {%4,%5,%6,%7}, {%8,%9}, {%0,%1,%2,%3};"
        : "+f"(c[0]), "+f"(c[1]), "+f"(c[2]), "+f"(c[3])
        : "r"(a[0]), "r"(a[1]), "r"(a[2]), "r"(a[3]), "r"(b[0]), "r"(b[1]));
}
__device__ __forceinline__ uint32_t packh2(float a, float b) {
    __half2 h = __floats2half2_rn(a, b);
    return *(uint32_t*)&h;
}
__device__ __forceinline__ float ex2f(float x) {
    float r;
    asm("ex2.approx.f32 %0, %1;" : "=f"(r) : "f"(x));
    return r;
}
__device__ __forceinline__ void cp_async16(uint32_t dst, const void* src) {
    asm volatile("cp.async.cg.shared.global [%0], [%1], 16;" :: "r"(dst), "l"(src));
}
#define CP_COMMIT() asm volatile("cp.async.commit_group;")
#define CP_WAIT(n)  asm volatile("cp.async.wait_group %0;" :: "n"(n))

// ---------------------------------------------------------------------------
// 1) instance conv + softmax. 128 CTAs, 4-way channel split, smem reduce.
// ---------------------------------------------------------------------------
__global__ __launch_bounds__(256) void mask_kernel(
    const float* __restrict__ x, const float* __restrict__ w_inst,
    const float* __restrict__ b_inst)
{
    __shared__ float ws[NI*CC];          // 8KB
    __shared__ float part[4][64][NI+1];  // padded: stride 9, conflict-free
    int tid = threadIdx.x;
    for (int k = tid; k < NI*CC; k += 256) ws[k] = w_inst[k];
    __syncthreads();

    int pl = tid & 63;
    int chunk = tid >> 6;                 // 0..3, 64 channels each
    int p = blockIdx.x*64 + pl;           // grid 128 -> 8192 positions
    int b = p >> 10, n = p & 1023;

    float acc[NI];
    #pragma unroll
    for (int i = 0; i < NI; i++) acc[i] = 0.f;
    const float* xp = x + ((size_t)b*CC + chunk*64)*HWN + n;
    const float* wsp = ws + chunk*64;
    #pragma unroll 4
    for (int c = 0; c < 64; c++) {
        float xv = xp[(size_t)c*HWN];
        #pragma unroll
        for (int i = 0; i < NI; i++) acc[i] = fmaf(wsp[i*CC + c], xv, acc[i]);
    }
    #pragma unroll
    for (int i = 0; i < NI; i++) part[chunk][pl][i] = acc[i];
    __syncthreads();

    if (tid < 64) {
        int pp = blockIdx.x*64 + tid;
        int bb = pp >> 10, nn = pp & 1023;
        float a[NI];
        float m = -1e30f;
        #pragma unroll
        for (int i = 0; i < NI; i++) {
            a[i] = part[0][tid][i] + part[1][tid][i]
                 + part[2][tid][i] + part[3][tid][i] + b_inst[i];
            m = fmaxf(m, a[i]);
        }
        float s = 0.f;
        #pragma unroll
        for (int i = 0; i < NI; i++) { a[i] = __expf(a[i] - m); s += a[i]; }
        float inv = 1.f / s;
        #pragma unroll
        for (int i = 0; i < NI; i++) g_mask[(bb*NI + i)*HWN + nn] = a[i]*inv;
    }
}

// ---------------------------------------------------------------------------
// 2a) concat weights into fp16 hi/lo [768][256]; biases fp32
// ---------------------------------------------------------------------------
__global__ __launch_bounds__(256) void prep_kernel(
    const float* __restrict__ wq, const float* __restrict__ bq,
    const float* __restrict__ wk, const float* __restrict__ bk,
    const float* __restrict__ wv, const float* __restrict__ bv)
{
    int idx = blockIdx.x*256 + threadIdx.x;
    if (idx < CC*CC) {
        float w0 = wq[idx], w1 = wk[idx], w2 = wv[idx];
        __half h0 = __float2half_rn(w0);
        __half h1 = __float2half_rn(w1);
        __half h2 = __float2half_rn(w2);
        g_w16h[idx]           = h0;
        g_w16h[CC*CC + idx]   = h1;
        g_w16h[2*CC*CC + idx] = h2;
        g_w16l[idx]           = __float2half_rn(w0 - __half2float(h0));
        g_w16l[CC*CC + idx]   = __float2half_rn(w1 - __half2float(h1));
        g_w16l[2*CC*CC + idx] = __float2half_rn(w2 - __half2float(h2));
    }
    if (idx < CC) { g_b3[idx] = bq[idx]; g_b3[CC+idx] = bk[idx]; g_b3[2*CC+idx] = bv[idx]; }
}

// ---------------------------------------------------------------------------
// 2b) QKV GEMM: A = W fp16 hi/lo (pre-split, pure copy), B = masked x fp16.
//     2 MMAs: Ah*B + Al*B. ALL outputs written as fp16 (q/k/v unified).
// ---------------------------------------------------------------------------
#define QKV_SMEM_BYTES 49152   // AH 16K | AL 16K | B 16K

__global__ __launch_bounds__(256) void qkv_mma(const float* __restrict__ x)
{
    extern __shared__ char sm[];
    __shared__ float s_msk[128];
    __shared__ float s_bias[128];

    const uint32_t AH = 0, AL = 16384, BS = 32768;
    uint32_t sbase = smem_to_u32(sm);

    int tid = threadIdx.x;
    int wid = tid >> 5, lane = tid & 31;
    int n0 = blockIdx.x * 128;
    int o0 = blockIdx.y * 128;
    int ib = blockIdx.z;
    int b = ib & 7, inst = ib >> 3;

    if (tid < 128) s_msk[tid] = g_mask[(b*NI + inst)*HWN + n0 + tid];
    else           s_bias[tid-128] = g_b3[o0 + tid - 128];

    float acc[2][8][4];
    #pragma unroll
    for (int mt = 0; mt < 2; mt++)
        #pragma unroll
        for (int nt = 0; nt < 8; nt++)
            #pragma unroll
            for (int q = 0; q < 4; q++) acc[mt][nt][q] = 0.f;

    const int m0w = (wid & 3) * 32;
    const int n0w = (wid >> 2) * 64;

    #pragma unroll 1
    for (int kc = 0; kc < 4; kc++) {
        __syncthreads();

        // ---- A tiles: direct fp16 copy, swizzled [m][k] rows (128B)
        const __half* wph = g_w16h + (size_t)o0*CC + kc*64;
        const __half* wpl = g_w16l + (size_t)o0*CC + kc*64;
        #pragma unroll
        for (int i = 0; i < 4; i++) {
            int e = i*256 + tid;
            int m = e >> 3, cq = (e & 7) * 8;    // 8 halves = 16B per item
            uint32_t off = (uint32_t)m*128 + (((uint32_t)cq*2) ^ (((uint32_t)m & 7) << 4));
            *(uint4*)(sm + AH + off) = *(const uint4*)&wph[(size_t)m*CC + cq];
            *(uint4*)(sm + AL + off) = *(const uint4*)&wpl[(size_t)m*CC + cq];
        }
        // ---- B tile: (x*mask) single fp16, swizzled [c][n] rows (256B)
        const float* xp = x + ((size_t)b*CC + kc*64)*HWN + n0;
        #pragma unroll
        for (int i = 0; i < 8; i++) {
            int e = i*256 + tid;
            int c = e >> 5, n4 = (e & 31) * 4;
            float4 v = *(const float4*)&xp[(size_t)c*HWN + n4];
            uint2 hv;
            hv.x = packh2(v.x * s_msk[n4+0], v.y * s_msk[n4+1]);
            hv.y = packh2(v.z * s_msk[n4+2], v.w * s_msk[n4+3]);
            uint32_t off = (uint32_t)c*256 + (((uint32_t)n4*2) ^ (((uint32_t)c & 7) << 4));
            *(uint2*)(sm + BS + off) = hv;
        }
        __syncthreads();

        #pragma unroll
        for (int ks = 0; ks < 4; ks++) {
            uint32_t ah[2][4], al[2][4];
            #pragma unroll
            for (int mt = 0; mt < 2; mt++) {
                uint32_t row = m0w + mt*16 + (lane & 7) + ((lane >> 3) & 1) * 8;
                uint32_t kb  = (uint32_t)ks*32 + (lane >> 4) * 16;
                uint32_t off = row*128 + (kb ^ ((row & 7) << 4));
                ldsm4(ah[mt], sbase + AH + off);
                ldsm4(al[mt], sbase + AL + off);
            }
            uint32_t bf[4][4];
            #pragma unroll
            for (int g = 0; g < 4; g++) {
                uint32_t rowc = (uint32_t)ks*16 + (lane & 7) + ((lane >> 3) & 1) * 8;
                uint32_t nb   = ((uint32_t)n0w + g*16 + (lane >> 4) * 8) * 2;
                uint32_t off  = rowc*256 + (nb ^ ((rowc & 7) << 4));
                ldsm4t(bf[g], sbase + BS + off);
            }
            #pragma unroll
            for (int mt = 0; mt < 2; mt++)
                #pragma unroll
                for (int nt = 0; nt < 8; nt++) {
                    uint32_t* fb = &bf[nt >> 1][(nt & 1) * 2];
                    mma_f16(acc[mt][nt], ah[mt], fb);
                    mma_f16(acc[mt][nt], al[mt], fb);
                }
        }
    }

    // ---- epilogue: bias + fp16 store, unified q/k/v destinations ----
    __half* dstb;
    {
        int sel = (o0 < 256) ? 0 : (o0 < 512) ? 1 : 2;
        int vo = o0 - sel*256;
        __half* bases = (sel == 0) ? g_q16 : (sel == 1) ? g_k16 : g_v16;
        dstb = bases + ((size_t)ib*CC + vo)*HWN + n0;
    }
    #pragma unroll
    for (int mt = 0; mt < 2; mt++) {
        int o_lo = m0w + mt*16 + (lane >> 2);
        float bias0 = s_bias[o_lo];
        float bias8 = s_bias[o_lo + 8];
        #pragma unroll
        for (int nt = 0; nt < 8; nt++) {
            int n_col = n0w + nt*8 + (lane & 3)*2;
            *(uint32_t*)&dstb[(size_t)o_lo*HWN + n_col] =
                packh2(acc[mt][nt][0] + bias0, acc[mt][nt][1] + bias0);
            *(uint32_t*)&dstb[(size_t)(o_lo+8)*HWN + n_col] =
                packh2(acc[mt][nt][2] + bias8, acc[mt][nt][3] + bias8);
        }
    }
}

// ---------------------------------------------------------------------------
// 3) l2-normalize q,k rows IN PLACE (fp16 read-modify-write).
//    q rows additionally scaled by 0.125*log2(e).
// ---------------------------------------------------------------------------
__global__ __launch_bounds__(256) void l2norm_kernel()
{
    int row = blockIdx.x;                 // NB*512 rows
    int ib = row >> 9;
    int o = row & 511;
    __half* p = (o < 256) ? &g_q16[((size_t)ib*CC + o)*HWN]
                          : &g_k16[((size_t)ib*CC + (o - 256))*HWN];
    int tid = threadIdx.x;
    uint2 w = *(uint2*)&p[tid*4];
    __half2 h01 = *(__half2*)&w.x, h23 = *(__half2*)&w.y;
    float v0 = __low2float(h01), v1 = __high2float(h01);
    float v2 = __low2float(h23), v3 = __high2float(h23);
    float ss = v0*v0 + v1*v1 + v2*v2 + v3*v3;
    #pragma unroll
    for (int off = 16; off; off >>= 1) ss += __shfl_xor_sync(0xffffffffu, ss, off);
    __shared__ float wsum[8];
    if ((tid & 31) == 0) wsum[tid >> 5] = ss;
    __syncthreads();
    float tot = wsum[0]+wsum[1]+wsum[2]+wsum[3]+wsum[4]+wsum[5]+wsum[6]+wsum[7];
    float inv = 1.f / fmaxf(sqrtf(tot), 1e-12f);
    if (o < 256) inv *= 0.18033688011112042f;   // 0.125 * log2(e)
    w.x = packh2(v0*inv, v1*inv);
    w.y = packh2(v2*inv, v3*inv);
    *(uint2*)&p[tid*4] = w;
}

// ---------------------------------------------------------------------------
// 4) flash attention, fp16 mma.sync, cp.async double-buffered K/V.
// ---------------------------------------------------------------------------
#define FL_SMEM 81920   // Q 16K | K0 16K | V0 16K | K1 16K | V1 16K

__global__ __launch_bounds__(256) void flash_mma()
{
    extern __shared__ char sm[];
    const uint32_t Qo = 0;
    const uint32_t Kb[2] = {16384, 49152};
    const uint32_t Vb[2] = {32768, 65536};
    uint32_t sbase = smem_to_u32(sm);

    int tid = threadIdx.x, wid = tid >> 5, lane = tid & 31;
    int it = blockIdx.x, h = blockIdx.y, ib = blockIdx.z;
    int i0 = it * 128;
    int m0w = wid * 16;

    const __half* q16 = g_q16 + ((size_t)ib*CC + h*HD)*HWN;
    const __half* k16 = g_k16 + ((size_t)ib*CC + h*HD)*HWN;
    const __half* v16 = g_v16 + ((size_t)ib*CC + h*HD)*HWN;

    // Q tile (once): 64 c-rows x 128 tok fp16, swizzled 256B rows
    #pragma unroll
    for (int i = 0; i < 4; i++) {
        int e = i*256 + tid;
        int c = e >> 4, t = (e & 15) * 8;
        uint32_t off = (uint32_t)c*256 + (((uint32_t)t*2) ^ (((uint32_t)c & 7) << 4));
        *(uint4*)(sm + Qo + off) = *(const uint4*)&q16[(size_t)c*HWN + i0 + t];
    }

    // async K/V tile issue
    auto issue_tile = [&](int buf, int j0) {
        #pragma unroll
        for (int i = 0; i < 4; i++) {
            int e = i*256 + tid;
            int c = e >> 4, t = (e & 15) * 8;
            uint32_t off = (uint32_t)c*256 + (((uint32_t)t*2) ^ (((uint32_t)c & 7) << 4));
            cp_async16(sbase + Kb[buf] + off, &k16[(size_t)c*HWN + j0 + t]);
            cp_async16(sbase + Vb[buf] + off, &v16[(size_t)c*HWN + j0 + t]);
        }
    };

    float o[8][4];
    #pragma unroll
    for (int n = 0; n < 8; n++)
        #pragma unroll
        for (int q = 0; q < 4; q++) o[n][q] = 0.f;
    float mr0 = -1e30f, mr1 = -1e30f, lr0 = 0.f, lr1 = 0.f;

    issue_tile(0, 0);
    CP_COMMIT();

    #pragma unroll 1
    for (int jt = 0; jt < 8; jt++) {
        int buf = jt & 1;
        if (jt < 7) {
            issue_tile(buf ^ 1, (jt + 1) * 128);
            CP_COMMIT();
            CP_WAIT(1);
        } else {
            CP_WAIT(0);
        }
        __syncthreads();

        uint32_t Ko = Kb[buf], Vo = Vb[buf];

        // ---- S = Q^T K (log2-domain, pre-scaled q) ----
        float s[16][4];
        #pragma unroll
        for (int j = 0; j < 16; j++)
            #pragma unroll
            for (int q = 0; q < 4; q++) s[j][q] = 0.f;

        #pragma unroll
        for (int ks = 0; ks < 4; ks++) {
            uint32_t ah[4];
            {
                // A-from-trans: k-select bit = lane>>4, m-select bit = lane>>3
                uint32_t c = (uint32_t)ks*16 + (lane & 7) + ((lane >> 4) & 1) * 8;
                uint32_t t = (uint32_t)m0w + ((lane >> 3) & 1) * 8;
                uint32_t off = c*256 + ((t*2) ^ ((c & 7) << 4));
                ldsm4t(ah, sbase + Qo + off);
            }
            #pragma unroll
            for (int g = 0; g < 8; g++) {
                uint32_t bh[4];
                // B-from-trans: k-select bit = lane>>3, n-select bit = lane>>4
                uint32_t c = (uint32_t)ks*16 + (lane & 7) + ((lane >> 3) & 1) * 8;
                uint32_t t = (uint32_t)g*16 + ((lane >> 4) & 1) * 8;
                uint32_t off = c*256 + ((t*2) ^ ((c & 7) << 4));
                ldsm4t(bh, sbase + Ko + off);
                mma_f16(s[g*2 + 0], ah, &bh[0]);
                mma_f16(s[g*2 + 1], ah, &bh[2]);
            }
        }

        // ---- online softmax in exp2 domain ----
        float mx0 = -1e30f, mx1 = -1e30f;
        #pragma unroll
        for (int j = 0; j < 16; j++) {
            mx0 = fmaxf(mx0, fmaxf(s[j][0], s[j][1]));
            mx1 = fmaxf(mx1, fmaxf(s[j][2], s[j][3]));
        }
        #pragma unroll
        for (int off = 1; off < 4; off <<= 1) {
            mx0 = fmaxf(mx0, __shfl_xor_sync(0xffffffffu, mx0, off));
            mx1 = fmaxf(mx1, __shfl_xor_sync(0xffffffffu, mx1, off));
        }
        float mn0 = fmaxf(mr0, mx0), mn1 = fmaxf(mr1, mx1);
        float al0 = ex2f(mr0 - mn0), al1 = ex2f(mr1 - mn1);
        mr0 = mn0; mr1 = mn1;
        float rs0 = 0.f, rs1 = 0.f;
        #pragma unroll
        for (int j = 0; j < 16; j++) {
            s[j][0] = ex2f(s[j][0] - mn0);
            s[j][1] = ex2f(s[j][1] - mn0);
            s[j][2] = ex2f(s[j][2] - mn1);
            s[j][3] = ex2f(s[j][3] - mn1);
            rs0 += s[j][0] + s[j][1];
            rs1 += s[j][2] + s[j][3];
        }
        #pragma unroll
        for (int off = 1; off < 4; off <<= 1) {
            rs0 += __shfl_xor_sync(0xffffffffu, rs0, off);
            rs1 += __shfl_xor_sync(0xffffffffu, rs1, off);
        }
        lr0 = lr0*al0 + rs0;
        lr1 = lr1*al1 + rs1;
        #pragma unroll
        for (int n = 0; n < 8; n++) {
            o[n][0] *= al0; o[n][1] *= al0;
            o[n][2] *= al1; o[n][3] *= al1;
        }

        // ---- O += P V^T ; P single fp16 (FA2 repack), V single fp16 ----
        #pragma unroll
        for (int ks = 0; ks < 8; ks++) {
            uint32_t ph[4];
            ph[0] = packh2(s[2*ks][0],   s[2*ks][1]);
            ph[1] = packh2(s[2*ks][2],   s[2*ks][3]);
            ph[2] = packh2(s[2*ks+1][0], s[2*ks+1][1]);
            ph[3] = packh2(s[2*ks+1][2], s[2*ks+1][3]);
            #pragma unroll
            for (int g = 0; g < 4; g++) {
                uint32_t bh[4];
                // B non-trans from [d][j]: d-select bit = lane>>4, j-select = lane>>3
                uint32_t d  = (uint32_t)g*16 + (lane & 7) + ((lane >> 4) & 1) * 8;
                uint32_t jb = (uint32_t)ks*32 + ((lane >> 3) & 1) * 16;
                uint32_t off = d*256 + (jb ^ ((d & 7) << 4));
                ldsm4(bh, sbase + Vo + off);
                mma_f16(o[g*2 + 0], ph, &bh[0]);
                mma_f16(o[g*2 + 1], ph, &bh[2]);
            }
        }
        __syncthreads();   // all warps done with buf before next issue overwrites peer
    }

    // ---- epilogue: normalize, stage via swizzled smem, coalesced store ----
    float* outs = (float*)sm;   // [64 d][128 tok] fp32, word-XOR swizzle
    float inv0 = 1.f / lr0, inv1 = 1.f / lr1;
    int r = lane >> 2;
    #pragma unroll
    for (int n = 0; n < 8; n++) {
        int d0 = n*8 + (lane & 3)*2;
        int d1 = d0 + 1;
        int tl = m0w + r, th = tl + 8;
        outs[d0*128 + (tl ^ ((d0 & 7) << 2))] = o[n][0]*inv0;
        outs[d1*128 + (tl ^ ((d1 & 7) << 2))] = o[n][1]*inv0;
        outs[d0*128 + (th ^ ((d0 & 7) << 2))] = o[n][2]*inv1;
        outs[d1*128 + (th ^ ((d1 & 7) << 2))] = o[n][3]*inv1;
    }
    __syncthreads();
    float* og = &g_att[((size_t)ib*CC + h*HD)*HWN + i0];
    #pragma unroll
    for (int i = 0; i < 8; i++) {
        int e = i*256 + tid;
        int d = e >> 5, t4 = (e & 31) * 4;
        float4 val = *(const float4*)&outs[d*128 + (t4 ^ ((d & 7) << 2))];
        *(float4*)&og[(size_t)d*HWN + t4] = val;
    }
}

// ---------------------------------------------------------------------------
// 5) out[b,c,n] = sum_i att[i,b,c,n] * mask[b,i,n]  (deterministic order)
// ---------------------------------------------------------------------------
__global__ __launch_bounds__(256) void out_kernel(float* __restrict__ out)
{
    int idx = blockIdx.x*256 + threadIdx.x;   // < B*C*HW = 2^21
    int b = idx >> 18;                        // C*HW = 262144
    int rem = idx & 262143;
    int n = rem & 1023;
    float acc = 0.f;
    #pragma unroll
    for (int i = 0; i < NI; i++) {
        acc = fmaf(g_att[(size_t)(i*BB + b)*262144 + rem],
                   g_mask[(b*NI + i)*HWN + n], acc);
    }
    out[idx] = acc;
}

// ---------------------------------------------------------------------------
extern "C" void kernel_launch(void* const* d_in, const int* in_sizes, int n_in,
                              void* d_out, int out_size)
{
    const float* x      = (const float*)d_in[0];
    const float* w_inst = (const float*)d_in[1];
    const float* b_inst = (const float*)d_in[2];
    const float* w_q    = (const float*)d_in[3];
    const float* b_q    = (const float*)d_in[4];
    const float* w_k    = (const float*)d_in[5];
    const float* b_k    = (const float*)d_in[6];
    const float* w_v    = (const float*)d_in[7];
    const float* b_v    = (const float*)d_in[8];
    float* out = (float*)d_out;

    static bool attr_done = false;
    if (!attr_done) {
        cudaFuncSetAttribute(qkv_mma, cudaFuncAttributeMaxDynamicSharedMemorySize,
                             QKV_SMEM_BYTES);
        cudaFuncSetAttribute(flash_mma, cudaFuncAttributeMaxDynamicSharedMemorySize,
                             FL_SMEM);
        attr_done = true;
    }

    mask_kernel<<<128, 256>>>(x, w_inst, b_inst);
    prep_kernel<<<(CC*CC + 255)/256, 256>>>(w_q, b_q, w_k, b_k, w_v, b_v);
    qkv_mma<<<dim3(8, 6, NB), 256, QKV_SMEM_BYTES>>>(x);
    l2norm_kernel<<<NB*512, 256>>>();
    flash_mma<<<dim3(8, NH, NB), 256, FL_SMEM>>>();
    out_kernel<<<(BB*CC*HWN)/256, 256>>>(out);
}

// round 14
// speedup vs baseline: 6.4442x; 1.1450x over previous
#include <cuda_runtime.h>
#include <cuda_bf16.h>
#include <cuda_fp16.h>
#include <cstdint>

#define BB 8
#define CC 256
#define HWN 1024
#define NI 8
#define NH 4
#define HD 64
#define NB (NI*BB)   // 64 (instance,batch) pairs

// Scratch (static device globals; no allocations anywhere)
__device__ __half g_w16h[3*CC*CC];       // W fp16 hi [768][256]
__device__ __half g_w16l[3*CC*CC];       // W fp16 lo
__device__ float g_b3[3*CC];
__device__ float g_mask[BB*NI*HWN];      // [b][i][n] softmaxed instance masks
__device__ __half g_xm16[(size_t)NB*CC*HWN];    // fp16 masked x per (ib) (~33MB)
__device__ __half g_q16[(size_t)NB*CC*HWN];     // fp16 q  (~33MB)
__device__ __half g_k16[(size_t)NB*CC*HWN];     // fp16 k  (~33MB)
__device__ __half g_v16[(size_t)NB*CC*HWN];     // fp16 v  (~33MB)
__device__ float g_att[(size_t)NB*CC*HWN];      // per-instance attention out (~67MB)

// ===========================================================================
// mma.sync / ldmatrix / cp.async helpers (baseline PTX — compute_103 OK)
// ===========================================================================
__device__ __forceinline__ uint32_t smem_to_u32(const void* p) {
    uint32_t a;
    asm("{ .reg .u64 t; cvta.to.shared.u64 t, %1; cvt.u32.u64 %0, t; }"
        : "=r"(a) : "l"(p));
    return a;
}
__device__ __forceinline__ void ldsm4(uint32_t* r, uint32_t addr) {
    asm volatile("ldmatrix.sync.aligned.m8n8.x4.shared.b16 {%0,%1,%2,%3}, [%4];"
        : "=r"(r[0]), "=r"(r[1]), "=r"(r[2]), "=r"(r[3]) : "r"(addr));
}
__device__ __forceinline__ void ldsm4t(uint32_t* r, uint32_t addr) {
    asm volatile("ldmatrix.sync.aligned.m8n8.x4.trans.shared.b16 {%0,%1,%2,%3}, [%4];"
        : "=r"(r[0]), "=r"(r[1]), "=r"(r[2]), "=r"(r[3]) : "r"(addr));
}
__device__ __forceinline__ void mma_f16(float* c, const uint32_t* a, const uint32_t* b) {
    asm volatile(
        "mma.sync.aligned.m16n8k16.row.col.f32.f16.f16.f32 "
        "{%0,%1,%2,%3}, {%4,%5,%6,%7}, {%8,%9}, {%0,%1,%2,%3};"
        : "+f"(c[0]), "+f"(c[1]), "+f"(c[2]), "+f"(c[3])
        : "r"(a[0]), "r"(a[1]), "r"(a[2]), "r"(a[3]), "r"(b[0]), "r"(b[1]));
}
__device__ __forceinline__ uint32_t packh2(float a, float b) {
    __half2 h = __floats2half2_rn(a, b);
    return *(uint32_t*)&h;
}
__device__ __forceinline__ float ex2f(float x) {
    float r;
    asm("ex2.approx.f32 %0, %1;" : "=f"(r) : "f"(x));
    return r;
}
__device__ __forceinline__ void cp_async16(uint32_t dst, const void* src) {
    asm volatile("cp.async.cg.shared.global [%0], [%1], 16;" :: "r"(dst), "l"(src));
}
#define CP_COMMIT() asm volatile("cp.async.commit_group;")
#define CP_WAIT(n)  asm volatile("cp.async.wait_group %0;" :: "n"(n))

// ---------------------------------------------------------------------------
// 1) instance conv + softmax. 128 CTAs, 4-way channel split, smem reduce.
// ---------------------------------------------------------------------------
__global__ __launch_bounds__(256) void mask_kernel(
    const float* __restrict__ x, const float* __restrict__ w_inst,
    const float* __restrict__ b_inst)
{
    __shared__ float ws[NI*CC];          // 8KB
    __shared__ float part[4][64][NI+1];  // padded: stride 9, conflict-free
    int tid = threadIdx.x;
    for (int k = tid; k < NI*CC; k += 256) ws[k] = w_inst[k];
    __syncthreads();

    int pl = tid & 63;
    int chunk = tid >> 6;                 // 0..3, 64 channels each
    int p = blockIdx.x*64 + pl;           // grid 128 -> 8192 positions
    int b = p >> 10, n = p & 1023;

    float acc[NI];
    #pragma unroll
    for (int i = 0; i < NI; i++) acc[i] = 0.f;
    const float* xp = x + ((size_t)b*CC + chunk*64)*HWN + n;
    const float* wsp = ws + chunk*64;
    #pragma unroll 4
    for (int c = 0; c < 64; c++) {
        float xv = xp[(size_t)c*HWN];
        #pragma unroll
        for (int i = 0; i < NI; i++) acc[i] = fmaf(wsp[i*CC + c], xv, acc[i]);
    }
    #pragma unroll
    for (int i = 0; i < NI; i++) part[chunk][pl][i] = acc[i];
    __syncthreads();

    if (tid < 64) {
        int pp = blockIdx.x*64 + tid;
        int bb = pp >> 10, nn = pp & 1023;
        float a[NI];
        float m = -1e30f;
        #pragma unroll
        for (int i = 0; i < NI; i++) {
            a[i] = part[0][tid][i] + part[1][tid][i]
                 + part[2][tid][i] + part[3][tid][i] + b_inst[i];
            m = fmaxf(m, a[i]);
        }
        float s = 0.f;
        #pragma unroll
        for (int i = 0; i < NI; i++) { a[i] = __expf(a[i] - m); s += a[i]; }
        float inv = 1.f / s;
        #pragma unroll
        for (int i = 0; i < NI; i++) g_mask[(bb*NI + i)*HWN + nn] = a[i]*inv;
    }
}

// ---------------------------------------------------------------------------
// 1b) materialize masked x as fp16 per (ib): xm16[ib][c][n] = x[b][c][n]*mask
// ---------------------------------------------------------------------------
__global__ __launch_bounds__(256) void xmask_kernel(const float* __restrict__ x)
{
    int idx = blockIdx.x*256 + threadIdx.x;       // 2^21 threads, 8 halves each
    size_t e = (size_t)idx * 8;
    int ib = (int)(e >> 18);
    int rem = (int)(e & 262143);
    int c = rem >> 10, n = rem & 1023;
    int b = ib & 7, inst = ib >> 3;

    const float* xp = &x[((size_t)b*CC + c)*HWN + n];
    const float* mp = &g_mask[(b*NI + inst)*HWN + n];
    float4 x0 = *(const float4*)&xp[0];
    float4 x1 = *(const float4*)&xp[4];
    float4 m0 = *(const float4*)&mp[0];
    float4 m1 = *(const float4*)&mp[4];
    uint4 o;
    o.x = packh2(x0.x*m0.x, x0.y*m0.y);
    o.y = packh2(x0.z*m0.z, x0.w*m0.w);
    o.z = packh2(x1.x*m1.x, x1.y*m1.y);
    o.w = packh2(x1.z*m1.z, x1.w*m1.w);
    *(uint4*)&g_xm16[e] = o;
}

// ---------------------------------------------------------------------------
// 2a) concat weights into fp16 hi/lo [768][256]; biases fp32
// ---------------------------------------------------------------------------
__global__ __launch_bounds__(256) void prep_kernel(
    const float* __restrict__ wq, const float* __restrict__ bq,
    const float* __restrict__ wk, const float* __restrict__ bk,
    const float* __restrict__ wv, const float* __restrict__ bv)
{
    int idx = blockIdx.x*256 + threadIdx.x;
    if (idx < CC*CC) {
        float w0 = wq[idx], w1 = wk[idx], w2 = wv[idx];
        __half h0 = __float2half_rn(w0);
        __half h1 = __float2half_rn(w1);
        __half h2 = __float2half_rn(w2);
        g_w16h[idx]           = h0;
        g_w16h[CC*CC + idx]   = h1;
        g_w16h[2*CC*CC + idx] = h2;
        g_w16l[idx]           = __float2half_rn(w0 - __half2float(h0));
        g_w16l[CC*CC + idx]   = __float2half_rn(w1 - __half2float(h1));
        g_w16l[2*CC*CC + idx] = __float2half_rn(w2 - __half2float(h2));
    }
    if (idx < CC) { g_b3[idx] = bq[idx]; g_b3[CC+idx] = bk[idx]; g_b3[2*CC+idx] = bv[idx]; }
}

// ---------------------------------------------------------------------------
// 2b) QKV GEMM: A = W fp16 hi/lo, B = xm16, all loads cp.async double-buffered.
//     2 MMAs: Ah*B + Al*B.
// ---------------------------------------------------------------------------
#define QKV_SMEM_BYTES 98304   // 2 stages x (AH 16K | AL 16K | B 16K)

__global__ __launch_bounds__(256) void qkv_mma()
{
    extern __shared__ char sm[];
    __shared__ float s_bias[128];

    // stage s at offset s*49152: AH +0, AL +16384, B +32768
    uint32_t sbase = smem_to_u32(sm);

    int tid = threadIdx.x;
    int wid = tid >> 5, lane = tid & 31;
    int n0 = blockIdx.x * 128;
    int o0 = blockIdx.y * 128;
    int ib = blockIdx.z;

    if (tid < 128) s_bias[tid] = g_b3[o0 + tid];

    const __half* xm = g_xm16 + (size_t)ib*CC*HWN + n0;

    auto issue_stage = [&](int st, int kc) {
        uint32_t base = (uint32_t)st * 49152u;
        const __half* wph = g_w16h + (size_t)o0*CC + kc*64;
        const __half* wpl = g_w16l + (size_t)o0*CC + kc*64;
        // A tiles: 128m x 64c fp16, swizzled [m][k] rows (128B)
        #pragma unroll
        for (int i = 0; i < 4; i++) {
            int e = i*256 + tid;
            int m = e >> 3, cq = (e & 7) * 8;    // 16B per item
            uint32_t off = (uint32_t)m*128 + (((uint32_t)cq*2) ^ (((uint32_t)m & 7) << 4));
            cp_async16(sbase + base + off,        &wph[(size_t)m*CC + cq]);
            cp_async16(sbase + base + 16384 + off, &wpl[(size_t)m*CC + cq]);
        }
        // B tile: 64c x 128n fp16, swizzled [c][n] rows (256B)
        #pragma unroll
        for (int i = 0; i < 4; i++) {
            int e = i*256 + tid;
            int c = e >> 4, n8 = (e & 15) * 8;
            uint32_t off = (uint32_t)c*256 + (((uint32_t)n8*2) ^ (((uint32_t)c & 7) << 4));
            cp_async16(sbase + base + 32768 + off, &xm[(size_t)(kc*64 + c)*HWN + n8]);
        }
    };

    float acc[2][8][4];
    #pragma unroll
    for (int mt = 0; mt < 2; mt++)
        #pragma unroll
        for (int nt = 0; nt < 8; nt++)
            #pragma unroll
            for (int q = 0; q < 4; q++) acc[mt][nt][q] = 0.f;

    const int m0w = (wid & 3) * 32;
    const int n0w = (wid >> 2) * 64;

    issue_stage(0, 0);
    CP_COMMIT();

    #pragma unroll 1
    for (int kc = 0; kc < 4; kc++) {
        int st = kc & 1;
        if (kc < 3) {
            issue_stage(st ^ 1, kc + 1);
            CP_COMMIT();
            CP_WAIT(1);
        } else {
            CP_WAIT(0);
        }
        __syncthreads();

        uint32_t AH = (uint32_t)st*49152u, AL = AH + 16384, BS = AH + 32768;

        #pragma unroll
        for (int ks = 0; ks < 4; ks++) {
            uint32_t ah[2][4], al[2][4];
            #pragma unroll
            for (int mt = 0; mt < 2; mt++) {
                uint32_t row = m0w + mt*16 + (lane & 7) + ((lane >> 3) & 1) * 8;
                uint32_t kb  = (uint32_t)ks*32 + (lane >> 4) * 16;
                uint32_t off = row*128 + (kb ^ ((row & 7) << 4));
                ldsm4(ah[mt], sbase + AH + off);
                ldsm4(al[mt], sbase + AL + off);
            }
            uint32_t bf[4][4];
            #pragma unroll
            for (int g = 0; g < 4; g++) {
                uint32_t rowc = (uint32_t)ks*16 + (lane & 7) + ((lane >> 3) & 1) * 8;
                uint32_t nb   = ((uint32_t)n0w + g*16 + (lane >> 4) * 8) * 2;
                uint32_t off  = rowc*256 + (nb ^ ((rowc & 7) << 4));
                ldsm4t(bf[g], sbase + BS + off);
            }
            #pragma unroll
            for (int mt = 0; mt < 2; mt++)
                #pragma unroll
                for (int nt = 0; nt < 8; nt++) {
                    uint32_t* fb = &bf[nt >> 1][(nt & 1) * 2];
                    mma_f16(acc[mt][nt], ah[mt], fb);
                    mma_f16(acc[mt][nt], al[mt], fb);
                }
        }
        __syncthreads();   // MMAs done before next issue overwrites this stage's peer
    }

    // ---- epilogue: bias + fp16 store, unified q/k/v destinations ----
    __half* dstb;
    {
        int sel = (o0 < 256) ? 0 : (o0 < 512) ? 1 : 2;
        int vo = o0 - sel*256;
        __half* bases = (sel == 0) ? g_q16 : (sel == 1) ? g_k16 : g_v16;
        dstb = bases + ((size_t)ib*CC + vo)*HWN + n0;
    }
    #pragma unroll
    for (int mt = 0; mt < 2; mt++) {
        int o_lo = m0w + mt*16 + (lane >> 2);
        float bias0 = s_bias[o_lo];
        float bias8 = s_bias[o_lo + 8];
        #pragma unroll
        for (int nt = 0; nt < 8; nt++) {
            int n_col = n0w + nt*8 + (lane & 3)*2;
            *(uint32_t*)&dstb[(size_t)o_lo*HWN + n_col] =
                packh2(acc[mt][nt][0] + bias0, acc[mt][nt][1] + bias0);
            *(uint32_t*)&dstb[(size_t)(o_lo+8)*HWN + n_col] =
                packh2(acc[mt][nt][2] + bias8, acc[mt][nt][3] + bias8);
        }
    }
}

// ---------------------------------------------------------------------------
// 3) l2-normalize q,k rows IN PLACE, warp-per-row (no block barrier).
//    q rows additionally scaled by 0.125*log2(e).
// ---------------------------------------------------------------------------
__global__ __launch_bounds__(256) void l2norm_kernel()
{
    int row = blockIdx.x*8 + (threadIdx.x >> 5);  // grid 4096 -> NB*512 rows
    int lane = threadIdx.x & 31;
    int ib = row >> 9;
    int o = row & 511;
    __half* p = (o < 256) ? &g_q16[((size_t)ib*CC + o)*HWN]
                          : &g_k16[((size_t)ib*CC + (o - 256))*HWN];
    uint4 w[4];
    float ss = 0.f;
    #pragma unroll
    for (int j = 0; j < 4; j++) {
        w[j] = *(uint4*)&p[j*256 + lane*8];
        const uint32_t* u = (const uint32_t*)&w[j];
        #pragma unroll
        for (int q = 0; q < 4; q++) {
            float2 f = __half22float2(*(const __half2*)&u[q]);
            ss = fmaf(f.x, f.x, fmaf(f.y, f.y, ss));
        }
    }
    #pragma unroll
    for (int off = 16; off; off >>= 1) ss += __shfl_xor_sync(0xffffffffu, ss, off);
    float inv = 1.f / fmaxf(sqrtf(ss), 1e-12f);
    if (o < 256) inv *= 0.18033688011112042f;   // 0.125 * log2(e)
    #pragma unroll
    for (int j = 0; j < 4; j++) {
        uint32_t* u = (uint32_t*)&w[j];
        #pragma unroll
        for (int q = 0; q < 4; q++) {
            float2 f = __half22float2(*(const __half2*)&u[q]);
            u[q] = packh2(f.x*inv, f.y*inv);
        }
        *(uint4*)&p[j*256 + lane*8] = w[j];
    }
}

// ---------------------------------------------------------------------------
// 4) flash attention, fp16 mma.sync, cp.async double-buffered K/V.
// ---------------------------------------------------------------------------
#define FL_SMEM 81920   // Q 16K | K0 16K | V0 16K | K1 16K | V1 16K

__global__ __launch_bounds__(256) void flash_mma()
{
    extern __shared__ char sm[];
    const uint32_t Qo = 0;
    const uint32_t Kb[2] = {16384, 49152};
    const uint32_t Vb[2] = {32768, 65536};
    uint32_t sbase = smem_to_u32(sm);

    int tid = threadIdx.x, wid = tid >> 5, lane = tid & 31;
    int it = blockIdx.x, h = blockIdx.y, ib = blockIdx.z;
    int i0 = it * 128;
    int m0w = wid * 16;

    const __half* q16 = g_q16 + ((size_t)ib*CC + h*HD)*HWN;
    const __half* k16 = g_k16 + ((size_t)ib*CC + h*HD)*HWN;
    const __half* v16 = g_v16 + ((size_t)ib*CC + h*HD)*HWN;

    // Q tile (once): 64 c-rows x 128 tok fp16, swizzled 256B rows
    #pragma unroll
    for (int i = 0; i < 4; i++) {
        int e = i*256 + tid;
        int c = e >> 4, t = (e & 15) * 8;
        uint32_t off = (uint32_t)c*256 + (((uint32_t)t*2) ^ (((uint32_t)c & 7) << 4));
        *(uint4*)(sm + Qo + off) = *(const uint4*)&q16[(size_t)c*HWN + i0 + t];
    }

    auto issue_tile = [&](int buf, int j0) {
        #pragma unroll
        for (int i = 0; i < 4; i++) {
            int e = i*256 + tid;
            int c = e >> 4, t = (e & 15) * 8;
            uint32_t off = (uint32_t)c*256 + (((uint32_t)t*2) ^ (((uint32_t)c & 7) << 4));
            cp_async16(sbase + Kb[buf] + off, &k16[(size_t)c*HWN + j0 + t]);
            cp_async16(sbase + Vb[buf] + off, &v16[(size_t)c*HWN + j0 + t]);
        }
    };

    float o[8][4];
    #pragma unroll
    for (int n = 0; n < 8; n++)
        #pragma unroll
        for (int q = 0; q < 4; q++) o[n][q] = 0.f;
    float mr0 = -1e30f, mr1 = -1e30f, lr0 = 0.f, lr1 = 0.f;

    issue_tile(0, 0);
    CP_COMMIT();

    #pragma unroll 1
    for (int jt = 0; jt < 8; jt++) {
        int buf = jt & 1;
        if (jt < 7) {
            issue_tile(buf ^ 1, (jt + 1) * 128);
            CP_COMMIT();
            CP_WAIT(1);
        } else {
            CP_WAIT(0);
        }
        __syncthreads();

        uint32_t Ko = Kb[buf], Vo = Vb[buf];

        // ---- S = Q^T K (log2-domain, pre-scaled q) ----
        float s[16][4];
        #pragma unroll
        for (int j = 0; j < 16; j++)
            #pragma unroll
            for (int q = 0; q < 4; q++) s[j][q] = 0.f;

        #pragma unroll
        for (int ks = 0; ks < 4; ks++) {
            uint32_t ah[4];
            {
                // A-from-trans: k-select bit = lane>>4, m-select bit = lane>>3
                uint32_t c = (uint32_t)ks*16 + (lane & 7) + ((lane >> 4) & 1) * 8;
                uint32_t t = (uint32_t)m0w + ((lane >> 3) & 1) * 8;
                uint32_t off = c*256 + ((t*2) ^ ((c & 7) << 4));
                ldsm4t(ah, sbase + Qo + off);
            }
            #pragma unroll
            for (int g = 0; g < 8; g++) {
                uint32_t bh[4];
                // B-from-trans: k-select bit = lane>>3, n-select bit = lane>>4
                uint32_t c = (uint32_t)ks*16 + (lane & 7) + ((lane >> 3) & 1) * 8;
                uint32_t t = (uint32_t)g*16 + ((lane >> 4) & 1) * 8;
                uint32_t off = c*256 + ((t*2) ^ ((c & 7) << 4));
                ldsm4t(bh, sbase + Ko + off);
                mma_f16(s[g*2 + 0], ah, &bh[0]);
                mma_f16(s[g*2 + 1], ah, &bh[2]);
            }
        }

        // ---- online softmax in exp2 domain ----
        float mx0 = -1e30f, mx1 = -1e30f;
        #pragma unroll
        for (int j = 0; j < 16; j++) {
            mx0 = fmaxf(mx0, fmaxf(s[j][0], s[j][1]));
            mx1 = fmaxf(mx1, fmaxf(s[j][2], s[j][3]));
        }
        #pragma unroll
        for (int off = 1; off < 4; off <<= 1) {
            mx0 = fmaxf(mx0, __shfl_xor_sync(0xffffffffu, mx0, off));
            mx1 = fmaxf(mx1, __shfl_xor_sync(0xffffffffu, mx1, off));
        }
        float mn0 = fmaxf(mr0, mx0), mn1 = fmaxf(mr1, mx1);
        float al0 = ex2f(mr0 - mn0), al1 = ex2f(mr1 - mn1);
        mr0 = mn0; mr1 = mn1;
        float rs0 = 0.f, rs1 = 0.f;
        #pragma unroll
        for (int j = 0; j < 16; j++) {
            s[j][0] = ex2f(s[j][0] - mn0);
            s[j][1] = ex2f(s[j][1] - mn0);
            s[j][2] = ex2f(s[j][2] - mn1);
            s[j][3] = ex2f(s[j][3] - mn1);
            rs0 += s[j][0] + s[j][1];
            rs1 += s[j][2] + s[j][3];
        }
        #pragma unroll
        for (int off = 1; off < 4; off <<= 1) {
            rs0 += __shfl_xor_sync(0xffffffffu, rs0, off);
            rs1 += __shfl_xor_sync(0xffffffffu, rs1, off);
        }
        lr0 = lr0*al0 + rs0;
        lr1 = lr1*al1 + rs1;
        #pragma unroll
        for (int n = 0; n < 8; n++) {
            o[n][0] *= al0; o[n][1] *= al0;
            o[n][2] *= al1; o[n][3] *= al1;
        }

        // ---- O += P V^T ; P single fp16 (FA2 repack), V single fp16 ----
        #pragma unroll
        for (int ks = 0; ks < 8; ks++) {
            uint32_t ph[4];
            ph[0] = packh2(s[2*ks][0],   s[2*ks][1]);
            ph[1] = packh2(s[2*ks][2],   s[2*ks][3]);
            ph[2] = packh2(s[2*ks+1][0], s[2*ks+1][1]);
            ph[3] = packh2(s[2*ks+1][2], s[2*ks+1][3]);
            #pragma unroll
            for (int g = 0; g < 4; g++) {
                uint32_t bh[4];
                // B non-trans from [d][j]: d-select bit = lane>>4, j-select = lane>>3
                uint32_t d  = (uint32_t)g*16 + (lane & 7) + ((lane >> 4) & 1) * 8;
                uint32_t jb = (uint32_t)ks*32 + ((lane >> 3) & 1) * 16;
                uint32_t off = d*256 + (jb ^ ((d & 7) << 4));
                ldsm4(bh, sbase + Vo + off);
                mma_f16(o[g*2 + 0], ph, &bh[0]);
                mma_f16(o[g*2 + 1], ph, &bh[2]);
            }
        }
        __syncthreads();   // all warps done with buf before next issue overwrites peer
    }

    // ---- epilogue: normalize, stage via swizzled smem, coalesced store ----
    float* outs = (float*)sm;   // [64 d][128 tok] fp32, word-XOR swizzle
    float inv0 = 1.f / lr0, inv1 = 1.f / lr1;
    int r = lane >> 2;
    #pragma unroll
    for (int n = 0; n < 8; n++) {
        int d0 = n*8 + (lane & 3)*2;
        int d1 = d0 + 1;
        int tl = m0w + r, th = tl + 8;
        outs[d0*128 + (tl ^ ((d0 & 7) << 2))] = o[n][0]*inv0;
        outs[d1*128 + (tl ^ ((d1 & 7) << 2))] = o[n][1]*inv0;
        outs[d0*128 + (th ^ ((d0 & 7) << 2))] = o[n][2]*inv1;
        outs[d1*128 + (th ^ ((d1 & 7) << 2))] = o[n][3]*inv1;
    }
    __syncthreads();
    float* og = &g_att[((size_t)ib*CC + h*HD)*HWN + i0];
    #pragma unroll
    for (int i = 0; i < 8; i++) {
        int e = i*256 + tid;
        int d = e >> 5, t4 = (e & 31) * 4;
        float4 val = *(const float4*)&outs[d*128 + (t4 ^ ((d & 7) << 2))];
        *(float4*)&og[(size_t)d*HWN + t4] = val;
    }
}

// ---------------------------------------------------------------------------
// 5) out[b,c,n] = sum_i att[i,b,c,n] * mask[b,i,n]  (deterministic order)
// ---------------------------------------------------------------------------
__global__ __launch_bounds__(256) void out_kernel(float* __restrict__ out)
{
    int idx = blockIdx.x*256 + threadIdx.x;   // < B*C*HW = 2^21
    int b = idx >> 18;                        // C*HW = 262144
    int rem = idx & 262143;
    int n = rem & 1023;
    float acc = 0.f;
    #pragma unroll
    for (int i = 0; i < NI; i++) {
        acc = fmaf(g_att[(size_t)(i*BB + b)*262144 + rem],
                   g_mask[(b*NI + i)*HWN + n], acc);
    }
    out[idx] = acc;
}

// ---------------------------------------------------------------------------
extern "C" void kernel_launch(void* const* d_in, const int* in_sizes, int n_in,
                              void* d_out, int out_size)
{
    const float* x      = (const float*)d_in[0];
    const float* w_inst = (const float*)d_in[1];
    const float* b_inst = (const float*)d_in[2];
    const float* w_q    = (const float*)d_in[3];
    const float* b_q    = (const float*)d_in[4];
    const float* w_k    = (const float*)d_in[5];
    const float* b_k    = (const float*)d_in[6];
    const float* w_v    = (const float*)d_in[7];
    const float* b_v    = (const float*)d_in[8];
    float* out = (float*)d_out;

    static bool attr_done = false;
    if (!attr_done) {
        cudaFuncSetAttribute(qkv_mma, cudaFuncAttributeMaxDynamicSharedMemorySize,
                             QKV_SMEM_BYTES);
        cudaFuncSetAttribute(flash_mma, cudaFuncAttributeMaxDynamicSharedMemorySize,
                             FL_SMEM);
        attr_done = true;
    }

    mask_kernel<<<128, 256>>>(x, w_inst, b_inst);
    prep_kernel<<<(CC*CC + 255)/256, 256>>>(w_q, b_q, w_k, b_k, w_v, b_v);
    xmask_kernel<<<8192, 256>>>(x);
    qkv_mma<<<dim3(8, 6, NB), 256, QKV_SMEM_BYTES>>>();
    l2norm_kernel<<<4096, 256>>>();
    flash_mma<<<dim3(8, NH, NB), 256, FL_SMEM>>>();
    out_kernel<<<(BB*CC*HWN)/256, 256>>>(out);
}

// round 16
// speedup vs baseline: 8.9968x; 1.3961x over previous
#include <cuda_runtime.h>
#include <cuda_bf16.h>
#include <cuda_fp16.h>
#include <cstdint>

#define BB 8
#define CC 256
#define HWN 1024
#define NI 8
#define NH 4
#define HD 64
#define NB (NI*BB)   // 64 (instance,batch) pairs

// Scratch (static device globals; no allocations anywhere)
__device__ __half g_w16[3*CC*CC];        // W fp16 [768][256]
__device__ float g_b3[3*CC];
__device__ float g_mask[BB*NI*HWN];      // [b][i][n] softmaxed instance masks
__device__ __half g_xm16[(size_t)NB*CC*HWN];    // fp16 masked x per (ib) (~33MB)
__device__ __half g_q16[(size_t)NB*CC*HWN];     // fp16 q  (~33MB)
__device__ __half g_k16[(size_t)NB*CC*HWN];     // fp16 k  (~33MB)
__device__ __half g_v16[(size_t)NB*CC*HWN];     // fp16 v  (~33MB)
__device__ float g_att[(size_t)NB*CC*HWN];      // per-instance attention out (~67MB)

// ===========================================================================
// mma.sync / ldmatrix / cp.async helpers (baseline PTX — compute_103 OK)
// ===========================================================================
__device__ __forceinline__ uint32_t smem_to_u32(const void* p) {
    uint32_t a;
    asm("{ .reg .u64 t; cvta.to.shared.u64 t, %1; cvt.u32.u64 %0, t; }"
        : "=r"(a) : "l"(p));
    return a;
}
__device__ __forceinline__ void ldsm4(uint32_t* r, uint32_t addr) {
    asm volatile("ldmatrix.sync.aligned.m8n8.x4.shared.b16 {%0,%1,%2,%3}, [%4];"
        : "=r"(r[0]), "=r"(r[1]), "=r"(r[2]), "=r"(r[3]) : "r"(addr));
}
__device__ __forceinline__ void ldsm4t(uint32_t* r, uint32_t addr) {
    asm volatile("ldmatrix.sync.aligned.m8n8.x4.trans.shared.b16 {%0,%1,%2,%3}, [%4];"
        : "=r"(r[0]), "=r"(r[1]), "=r"(r[2]), "=r"(r[3]) : "r"(addr));
}
__device__ __forceinline__ void mma_f16(float* c, const uint32_t* a, const uint32_t* b) {
    asm volatile(
        "mma.sync.aligned.m16n8k16.row.col.f32.f16.f16.f32 "
        "{%0,%1,%2,%3}, {%4,%5,%6,%7}, {%8,%9}, {%0,%1,%2,%3};"
        : "+f"(c[0]), "+f"(c[1]), "+f"(c[2]), "+f"(c[3])
        : "r"(a[0]), "r"(a[1]), "r"(a[2]), "r"(a[3]), "r"(b[0]), "r"(b[1]));
}
__device__ __forceinline__ uint32_t packh2(float a, float b) {
    __half2 h = __floats2half2_rn(a, b);
    return *(uint32_t*)&h;
}
__device__ __forceinline__ uint32_t ex2h2(uint32_t x) {
    uint32_t r;
    asm("ex2.approx.f16x2 %0, %1;" : "=r"(r) : "r"(x));
    return r;
}
__device__ __forceinline__ void cp_async16(uint32_t dst, const void* src) {
    asm volatile("cp.async.cg.shared.global [%0], [%1], 16;" :: "r"(dst), "l"(src));
}
#define CP_COMMIT() asm volatile("cp.async.commit_group;")
#define CP_WAIT(n)  asm volatile("cp.async.wait_group %0;" :: "n"(n))

// ---------------------------------------------------------------------------
// 1) instance conv + softmax. 128 CTAs, 4-way channel split, smem reduce.
// ---------------------------------------------------------------------------
__global__ __launch_bounds__(256) void mask_kernel(
    const float* __restrict__ x, const float* __restrict__ w_inst,
    const float* __restrict__ b_inst)
{
    __shared__ float ws[NI*CC];          // 8KB
    __shared__ float part[4][64][NI+1];  // padded: stride 9, conflict-free
    int tid = threadIdx.x;
    for (int k = tid; k < NI*CC; k += 256) ws[k] = w_inst[k];
    __syncthreads();

    int pl = tid & 63;
    int chunk = tid >> 6;                 // 0..3, 64 channels each
    int p = blockIdx.x*64 + pl;           // grid 128 -> 8192 positions
    int b = p >> 10, n = p & 1023;

    float acc[NI];
    #pragma unroll
    for (int i = 0; i < NI; i++) acc[i] = 0.f;
    const float* xp = x + ((size_t)b*CC + chunk*64)*HWN + n;
    const float* wsp = ws + chunk*64;
    #pragma unroll 4
    for (int c = 0; c < 64; c++) {
        float xv = xp[(size_t)c*HWN];
        #pragma unroll
        for (int i = 0; i < NI; i++) acc[i] = fmaf(wsp[i*CC + c], xv, acc[i]);
    }
    #pragma unroll
    for (int i = 0; i < NI; i++) part[chunk][pl][i] = acc[i];
    __syncthreads();

    if (tid < 64) {
        int pp = blockIdx.x*64 + tid;
        int bb = pp >> 10, nn = pp & 1023;
        float a[NI];
        float m = -1e30f;
        #pragma unroll
        for (int i = 0; i < NI; i++) {
            a[i] = part[0][tid][i] + part[1][tid][i]
                 + part[2][tid][i] + part[3][tid][i] + b_inst[i];
            m = fmaxf(m, a[i]);
        }
        float s = 0.f;
        #pragma unroll
        for (int i = 0; i < NI; i++) { a[i] = __expf(a[i] - m); s += a[i]; }
        float inv = 1.f / s;
        #pragma unroll
        for (int i = 0; i < NI; i++) g_mask[(bb*NI + i)*HWN + nn] = a[i]*inv;
    }
}

// ---------------------------------------------------------------------------
// 1b) materialize masked x as fp16 per (ib): xm16[ib][c][n] = x[b][c][n]*mask
// ---------------------------------------------------------------------------
__global__ __launch_bounds__(256) void xmask_kernel(const float* __restrict__ x)
{
    int idx = blockIdx.x*256 + threadIdx.x;       // 2^21 threads, 8 halves each
    size_t e = (size_t)idx * 8;
    int ib = (int)(e >> 18);
    int rem = (int)(e & 262143);
    int c = rem >> 10, n = rem & 1023;
    int b = ib & 7, inst = ib >> 3;

    const float* xp = &x[((size_t)b*CC + c)*HWN + n];
    const float* mp = &g_mask[(b*NI + inst)*HWN + n];
    float4 x0 = *(const float4*)&xp[0];
    float4 x1 = *(const float4*)&xp[4];
    float4 m0 = *(const float4*)&mp[0];
    float4 m1 = *(const float4*)&mp[4];
    uint4 o;
    o.x = packh2(x0.x*m0.x, x0.y*m0.y);
    o.y = packh2(x0.z*m0.z, x0.w*m0.w);
    o.z = packh2(x1.x*m1.x, x1.y*m1.y);
    o.w = packh2(x1.z*m1.z, x1.w*m1.w);
    *(uint4*)&g_xm16[e] = o;
}

// ---------------------------------------------------------------------------
// 2a) concat weights into fp16 [768][256]; biases fp32
// ---------------------------------------------------------------------------
__global__ __launch_bounds__(256) void prep_kernel(
    const float* __restrict__ wq, const float* __restrict__ bq,
    const float* __restrict__ wk, const float* __restrict__ bk,
    const float* __restrict__ wv, const float* __restrict__ bv)
{
    int idx = blockIdx.x*256 + threadIdx.x;
    if (idx < CC*CC) {
        g_w16[idx]           = __float2half_rn(wq[idx]);
        g_w16[CC*CC + idx]   = __float2half_rn(wk[idx]);
        g_w16[2*CC*CC + idx] = __float2half_rn(wv[idx]);
    }
    if (idx < CC) { g_b3[idx] = bq[idx]; g_b3[CC+idx] = bk[idx]; g_b3[2*CC+idx] = bv[idx]; }
}

// ---------------------------------------------------------------------------
// 2b) QKV GEMM: A = W fp16 (single), B = xm16, cp.async double-buffered.
//     1 MMA per fragment pair.
// ---------------------------------------------------------------------------
#define QKV_SMEM_BYTES 65536   // 2 stages x (A 16K | B 16K)

__global__ __launch_bounds__(256) void qkv_mma()
{
    extern __shared__ char sm[];
    __shared__ float s_bias[128];

    // stage s at offset s*32768: A +0, B +16384
    uint32_t sbase = smem_to_u32(sm);

    int tid = threadIdx.x;
    int wid = tid >> 5, lane = tid & 31;
    int n0 = blockIdx.x * 128;
    int o0 = blockIdx.y * 128;
    int ib = blockIdx.z;

    if (tid < 128) s_bias[tid] = g_b3[o0 + tid];

    const __half* xm = g_xm16 + (size_t)ib*CC*HWN + n0;

    auto issue_stage = [&](int st, int kc) {
        uint32_t base = (uint32_t)st * 32768u;
        const __half* wp = g_w16 + (size_t)o0*CC + kc*64;
        // A tile: 128m x 64c fp16, swizzled [m][k] rows (128B)
        #pragma unroll
        for (int i = 0; i < 4; i++) {
            int e = i*256 + tid;
            int m = e >> 3, cq = (e & 7) * 8;    // 16B per item
            uint32_t off = (uint32_t)m*128 + (((uint32_t)cq*2) ^ (((uint32_t)m & 7) << 4));
            cp_async16(sbase + base + off, &wp[(size_t)m*CC + cq]);
        }
        // B tile: 64c x 128n fp16, swizzled [c][n] rows (256B)
        #pragma unroll
        for (int i = 0; i < 4; i++) {
            int e = i*256 + tid;
            int c = e >> 4, n8 = (e & 15) * 8;
            uint32_t off = (uint32_t)c*256 + (((uint32_t)n8*2) ^ (((uint32_t)c & 7) << 4));
            cp_async16(sbase + base + 16384 + off, &xm[(size_t)(kc*64 + c)*HWN + n8]);
        }
    };

    float acc[2][8][4];
    #pragma unroll
    for (int mt = 0; mt < 2; mt++)
        #pragma unroll
        for (int nt = 0; nt < 8; nt++)
            #pragma unroll
            for (int q = 0; q < 4; q++) acc[mt][nt][q] = 0.f;

    const int m0w = (wid & 3) * 32;
    const int n0w = (wid >> 2) * 64;

    issue_stage(0, 0);
    CP_COMMIT();

    #pragma unroll 1
    for (int kc = 0; kc < 4; kc++) {
        int st = kc & 1;
        if (kc < 3) {
            issue_stage(st ^ 1, kc + 1);
            CP_COMMIT();
            CP_WAIT(1);
        } else {
            CP_WAIT(0);
        }
        __syncthreads();

        uint32_t AS = (uint32_t)st*32768u, BS = AS + 16384;

        #pragma unroll
        for (int ks = 0; ks < 4; ks++) {
            uint32_t ah[2][4];
            #pragma unroll
            for (int mt = 0; mt < 2; mt++) {
                uint32_t row = m0w + mt*16 + (lane & 7) + ((lane >> 3) & 1) * 8;
                uint32_t kb  = (uint32_t)ks*32 + (lane >> 4) * 16;
                uint32_t off = row*128 + (kb ^ ((row & 7) << 4));
                ldsm4(ah[mt], sbase + AS + off);
            }
            uint32_t bf[4][4];
            #pragma unroll
            for (int g = 0; g < 4; g++) {
                uint32_t rowc = (uint32_t)ks*16 + (lane & 7) + ((lane >> 3) & 1) * 8;
                uint32_t nb   = ((uint32_t)n0w + g*16 + (lane >> 4) * 8) * 2;
                uint32_t off  = rowc*256 + (nb ^ ((rowc & 7) << 4));
                ldsm4t(bf[g], sbase + BS + off);
            }
            #pragma unroll
            for (int mt = 0; mt < 2; mt++)
                #pragma unroll
                for (int nt = 0; nt < 8; nt++)
                    mma_f16(acc[mt][nt], ah[mt], &bf[nt >> 1][(nt & 1) * 2]);
        }
        __syncthreads();   // MMAs done before next issue overwrites this stage's peer
    }

    // ---- epilogue: bias + fp16 store, unified q/k/v destinations ----
    __half* dstb;
    {
        int sel = (o0 < 256) ? 0 : (o0 < 512) ? 1 : 2;
        int vo = o0 - sel*256;
        __half* bases = (sel == 0) ? g_q16 : (sel == 1) ? g_k16 : g_v16;
        dstb = bases + ((size_t)ib*CC + vo)*HWN + n0;
    }
    #pragma unroll
    for (int mt = 0; mt < 2; mt++) {
        int o_lo = m0w + mt*16 + (lane >> 2);
        float bias0 = s_bias[o_lo];
        float bias8 = s_bias[o_lo + 8];
        #pragma unroll
        for (int nt = 0; nt < 8; nt++) {
            int n_col = n0w + nt*8 + (lane & 3)*2;
            *(uint32_t*)&dstb[(size_t)o_lo*HWN + n_col] =
                packh2(acc[mt][nt][0] + bias0, acc[mt][nt][1] + bias0);
            *(uint32_t*)&dstb[(size_t)(o_lo+8)*HWN + n_col] =
                packh2(acc[mt][nt][2] + bias8, acc[mt][nt][3] + bias8);
        }
    }
}

// ---------------------------------------------------------------------------
// 3) l2-normalize q,k rows IN PLACE, warp-per-row (no block barrier).
//    q rows additionally scaled by 0.125*log2(e).
// ---------------------------------------------------------------------------
__global__ __launch_bounds__(256) void l2norm_kernel()
{
    int row = blockIdx.x*8 + (threadIdx.x >> 5);  // grid 4096 -> NB*512 rows
    int lane = threadIdx.x & 31;
    int ib = row >> 9;
    int o = row & 511;
    __half* p = (o < 256) ? &g_q16[((size_t)ib*CC + o)*HWN]
                          : &g_k16[((size_t)ib*CC + (o - 256))*HWN];
    uint4 w[4];
    float ss = 0.f;
    #pragma unroll
    for (int j = 0; j < 4; j++) {
        w[j] = *(uint4*)&p[j*256 + lane*8];
        const uint32_t* u = (const uint32_t*)&w[j];
        #pragma unroll
        for (int q = 0; q < 4; q++) {
            float2 f = __half22float2(*(const __half2*)&u[q]);
            ss = fmaf(f.x, f.x, fmaf(f.y, f.y, ss));
        }
    }
    #pragma unroll
    for (int off = 16; off; off >>= 1) ss += __shfl_xor_sync(0xffffffffu, ss, off);
    float inv = 1.f / fmaxf(sqrtf(ss), 1e-12f);
    if (o < 256) inv *= 0.18033688011112042f;   // 0.125 * log2(e)
    #pragma unroll
    for (int j = 0; j < 4; j++) {
        uint32_t* u = (uint32_t*)&w[j];
        #pragma unroll
        for (int q = 0; q < 4; q++) {
            float2 f = __half22float2(*(const __half2*)&u[q]);
            u[q] = packh2(f.x*inv, f.y*inv);
        }
        *(uint4*)&p[j*256 + lane*8] = w[j];
    }
}

// ---------------------------------------------------------------------------
// 4) flash attention, fp16 mma.sync, cp.async double-buffered K/V.
//    No max subtraction (|s|<=0.18*||q||*||k|| bound, exp2 can't overflow).
//    exp2 via ex2.approx.f16x2; row sums via ones-column MMA (fp32 accum).
// ---------------------------------------------------------------------------
#define FL_SMEM 81920   // Q 16K | K0 16K | V0 16K | K1 16K | V1 16K

__global__ __launch_bounds__(256) void flash_mma()
{
    extern __shared__ char sm[];
    const uint32_t Qo = 0;
    const uint32_t Kb[2] = {16384, 49152};
    const uint32_t Vb[2] = {32768, 65536};
    uint32_t sbase = smem_to_u32(sm);

    int tid = threadIdx.x, wid = tid >> 5, lane = tid & 31;
    int it = blockIdx.x, h = blockIdx.y, ib = blockIdx.z;
    int i0 = it * 128;
    int m0w = wid * 16;

    const __half* q16 = g_q16 + ((size_t)ib*CC + h*HD)*HWN;
    const __half* k16 = g_k16 + ((size_t)ib*CC + h*HD)*HWN;
    const __half* v16 = g_v16 + ((size_t)ib*CC + h*HD)*HWN;

    // Q tile (once): 64 c-rows x 128 tok fp16, swizzled 256B rows
    #pragma unroll
    for (int i = 0; i < 4; i++) {
        int e = i*256 + tid;
        int c = e >> 4, t = (e & 15) * 8;
        uint32_t off = (uint32_t)c*256 + (((uint32_t)t*2) ^ (((uint32_t)c & 7) << 4));
        *(uint4*)(sm + Qo + off) = *(const uint4*)&q16[(size_t)c*HWN + i0 + t];
    }

    auto issue_tile = [&](int buf, int j0) {
        #pragma unroll
        for (int i = 0; i < 4; i++) {
            int e = i*256 + tid;
            int c = e >> 4, t = (e & 15) * 8;
            uint32_t off = (uint32_t)c*256 + (((uint32_t)t*2) ^ (((uint32_t)c & 7) << 4));
            cp_async16(sbase + Kb[buf] + off, &k16[(size_t)c*HWN + j0 + t]);
            cp_async16(sbase + Vb[buf] + off, &v16[(size_t)c*HWN + j0 + t]);
        }
    };

    float o[8][4];
    #pragma unroll
    for (int n = 0; n < 8; n++)
        #pragma unroll
        for (int q = 0; q < 4; q++) o[n][q] = 0.f;
    float psum[4] = {0.f, 0.f, 0.f, 0.f};
    const uint32_t ones2[2] = {0x3C003C00u, 0x3C003C00u};

    issue_tile(0, 0);
    CP_COMMIT();

    #pragma unroll 1
    for (int jt = 0; jt < 8; jt++) {
        int buf = jt & 1;
        if (jt < 7) {
            issue_tile(buf ^ 1, (jt + 1) * 128);
            CP_COMMIT();
            CP_WAIT(1);
        } else {
            CP_WAIT(0);
        }
        __syncthreads();

        uint32_t Ko = Kb[buf], Vo = Vb[buf];

        // ---- S = Q^T K (log2-domain, pre-scaled q) ----
        float s[16][4];
        #pragma unroll
        for (int j = 0; j < 16; j++)
            #pragma unroll
            for (int q = 0; q < 4; q++) s[j][q] = 0.f;

        #pragma unroll
        for (int ks = 0; ks < 4; ks++) {
            uint32_t ah[4];
            {
                // A-from-trans: k-select bit = lane>>4, m-select bit = lane>>3
                uint32_t c = (uint32_t)ks*16 + (lane & 7) + ((lane >> 4) & 1) * 8;
                uint32_t t = (uint32_t)m0w + ((lane >> 3) & 1) * 8;
                uint32_t off = c*256 + ((t*2) ^ ((c & 7) << 4));
                ldsm4t(ah, sbase + Qo + off);
            }
            #pragma unroll
            for (int g = 0; g < 8; g++) {
                uint32_t bh[4];
                // B-from-trans: k-select bit = lane>>3, n-select bit = lane>>4
                uint32_t c = (uint32_t)ks*16 + (lane & 7) + ((lane >> 3) & 1) * 8;
                uint32_t t = (uint32_t)g*16 + ((lane >> 4) & 1) * 8;
                uint32_t off = c*256 + ((t*2) ^ ((c & 7) << 4));
                ldsm4t(bh, sbase + Ko + off);
                mma_f16(s[g*2 + 0], ah, &bh[0]);
                mma_f16(s[g*2 + 1], ah, &bh[2]);
            }
        }

        // ---- P = exp2(S) directly in fp16x2 (no max subtraction needed) ----
        uint32_t hx[16][2];
        #pragma unroll
        for (int j = 0; j < 16; j++) {
            hx[j][0] = ex2h2(packh2(s[j][0], s[j][1]));
            hx[j][1] = ex2h2(packh2(s[j][2], s[j][3]));
        }

        // ---- O += P V^T ; row sums via ones-column MMA ----
        #pragma unroll
        for (int ks = 0; ks < 8; ks++) {
            uint32_t ph[4] = { hx[2*ks][0], hx[2*ks][1], hx[2*ks+1][0], hx[2*ks+1][1] };
            mma_f16(psum, ph, ones2);
            #pragma unroll
            for (int g = 0; g < 4; g++) {
                uint32_t bh[4];
                // B non-trans from [d][j]: d-select bit = lane>>4, j-select = lane>>3
                uint32_t d  = (uint32_t)g*16 + (lane & 7) + ((lane >> 4) & 1) * 8;
                uint32_t jb = (uint32_t)ks*32 + ((lane >> 3) & 1) * 16;
                uint32_t off = d*256 + (jb ^ ((d & 7) << 4));
                ldsm4(bh, sbase + Vo + off);
                mma_f16(o[g*2 + 0], ph, &bh[0]);
                mma_f16(o[g*2 + 1], ph, &bh[2]);
            }
        }
        __syncthreads();   // all warps done with buf before next issue overwrites peer
    }

    // ---- epilogue: normalize, stage via swizzled smem, coalesced store ----
    float* outs = (float*)sm;   // [64 d][128 tok] fp32, word-XOR swizzle
    float inv0 = 1.f / psum[0], inv1 = 1.f / psum[2];
    int r = lane >> 2;
    #pragma unroll
    for (int n = 0; n < 8; n++) {
        int d0 = n*8 + (lane & 3)*2;
        int d1 = d0 + 1;
        int tl = m0w + r, th = tl + 8;
        outs[d0*128 + (tl ^ ((d0 & 7) << 2))] = o[n][0]*inv0;
        outs[d1*128 + (tl ^ ((d1 & 7) << 2))] = o[n][1]*inv0;
        outs[d0*128 + (th ^ ((d0 & 7) << 2))] = o[n][2]*inv1;
        outs[d1*128 + (th ^ ((d1 & 7) << 2))] = o[n][3]*inv1;
    }
    __syncthreads();
    float* og = &g_att[((size_t)ib*CC + h*HD)*HWN + i0];
    #pragma unroll
    for (int i = 0; i < 8; i++) {
        int e = i*256 + tid;
        int d = e >> 5, t4 = (e & 31) * 4;
        float4 val = *(const float4*)&outs[d*128 + (t4 ^ ((d & 7) << 2))];
        *(float4*)&og[(size_t)d*HWN + t4] = val;
    }
}

// ---------------------------------------------------------------------------
// 5) out[b,c,n] = sum_i att[i,b,c,n] * mask[b,i,n]  (deterministic order)
// ---------------------------------------------------------------------------
__global__ __launch_bounds__(256) void out_kernel(float* __restrict__ out)
{
    int idx = blockIdx.x*256 + threadIdx.x;   // < B*C*HW = 2^21
    int b = idx >> 18;                        // C*HW = 262144
    int rem = idx & 262143;
    int n = rem & 1023;
    float acc = 0.f;
    #pragma unroll
    for (int i = 0; i < NI; i++) {
        acc = fmaf(g_att[(size_t)(i*BB + b)*262144 + rem],
                   g_mask[(b*NI + i)*HWN + n], acc);
    }
    out[idx] = acc;
}

// ---------------------------------------------------------------------------
extern "C" void kernel_launch(void* const* d_in, const int* in_sizes, int n_in,
                              void* d_out, int out_size)
{
    const float* x      = (const float*)d_in[0];
    const float* w_inst = (const float*)d_in[1];
    const float* b_inst = (const float*)d_in[2];
    const float* w_q    = (const float*)d_in[3];
    const float* b_q    = (const float*)d_in[4];
    const float* w_k    = (const float*)d_in[5];
    const float* b_k    = (const float*)d_in[6];
    const float* w_v    = (const float*)d_in[7];
    const float* b_v    = (const float*)d_in[8];
    float* out = (float*)d_out;

    static bool attr_done = false;
    if (!attr_done) {
        cudaFuncSetAttribute(qkv_mma, cudaFuncAttributeMaxDynamicSharedMemorySize,
                             QKV_SMEM_BYTES);
        cudaFuncSetAttribute(flash_mma, cudaFuncAttributeMaxDynamicSharedMemorySize,
                             FL_SMEM);
        attr_done = true;
    }

    mask_kernel<<<128, 256>>>(x, w_inst, b_inst);
    prep_kernel<<<(CC*CC + 255)/256, 256>>>(w_q, b_q, w_k, b_k, w_v, b_v);
    xmask_kernel<<<8192, 256>>>(x);
    qkv_mma<<<dim3(8, 6, NB), 256, QKV_SMEM_BYTES>>>();
    l2norm_kernel<<<4096, 256>>>();
    flash_mma<<<dim3(8, NH, NB), 256, FL_SMEM>>>();
    out_kernel<<<(BB*CC*HWN)/256, 256>>>(out);
}

// round 17
// speedup vs baseline: 9.1600x; 1.0181x over previous
#include <cuda_runtime.h>
#include <cuda_bf16.h>
#include <cuda_fp16.h>
#include <cstdint>

#define BB 8
#define CC 256
#define HWN 1024
#define NI 8
#define NH 4
#define HD 64
#define NB (NI*BB)   // 64 (instance,batch) pairs

// Scratch (static device globals; no allocations anywhere)
__device__ __half g_w16[3*CC*CC];        // W fp16 [768][256]
__device__ float g_b3[3*CC];
__device__ float g_mask[BB*NI*HWN];      // [b][i][n] softmaxed instance masks
__device__ __half g_xm16[(size_t)NB*CC*HWN];    // fp16 masked x per (ib) (~33MB)
__device__ __half g_q16[(size_t)NB*CC*HWN];     // fp16 q  (~33MB)
__device__ __half g_k16[(size_t)NB*CC*HWN];     // fp16 k  (~33MB)
__device__ __half g_v16[(size_t)NB*CC*HWN];     // fp16 v  (~33MB)
__device__ __half g_att16[(size_t)NB*CC*HWN];   // fp16 att*mask/psum (~33MB)

// ===========================================================================
// mma.sync / ldmatrix / cp.async helpers (baseline PTX — compute_103 OK)
// ===========================================================================
__device__ __forceinline__ uint32_t smem_to_u32(const void* p) {
    uint32_t a;
    asm("{ .reg .u64 t; cvta.to.shared.u64 t, %1; cvt.u32.u64 %0, t; }"
        : "=r"(a) : "l"(p));
    return a;
}
__device__ __forceinline__ void ldsm4(uint32_t* r, uint32_t addr) {
    asm volatile("ldmatrix.sync.aligned.m8n8.x4.shared.b16 {%0,%1,%2,%3}, [%4];"
        : "=r"(r[0]), "=r"(r[1]), "=r"(r[2]), "=r"(r[3]) : "r"(addr));
}
__device__ __forceinline__ void ldsm4t(uint32_t* r, uint32_t addr) {
    asm volatile("ldmatrix.sync.aligned.m8n8.x4.trans.shared.b16 {%0,%1,%2,%3}, [%4];"
        : "=r"(r[0]), "=r"(r[1]), "=r"(r[2]), "=r"(r[3]) : "r"(addr));
}
__device__ __forceinline__ void mma_f16(float* c, const uint32_t* a, const uint32_t* b) {
    asm volatile(
        "mma.sync.aligned.m16n8k16.row.col.f32.f16.f16.f32 "
        "{%0,%1,%2,%3}, {%4,%5,%6,%7}, {%8,%9}, {%0,%1,%2,%3};"
        : "+f"(c[0]), "+f"(c[1]), "+f"(c[2]), "+f"(c[3])
        : "r"(a[0]), "r"(a[1]), "r"(a[2]), "r"(a[3]), "r"(b[0]), "r"(b[1]));
}
__device__ __forceinline__ uint32_t packh2(float a, float b) {
    __half2 h = __floats2half2_rn(a, b);
    return *(uint32_t*)&h;
}
__device__ __forceinline__ uint32_t ex2h2(uint32_t x) {
    uint32_t r;
    asm("ex2.approx.f16x2 %0, %1;" : "=r"(r) : "r"(x));
    return r;
}
__device__ __forceinline__ void cp_async16(uint32_t dst, const void* src) {
    asm volatile("cp.async.cg.shared.global [%0], [%1], 16;" :: "r"(dst), "l"(src));
}
#define CP_COMMIT() asm volatile("cp.async.commit_group;")
#define CP_WAIT(n)  asm volatile("cp.async.wait_group %0;" :: "n"(n))

// ---------------------------------------------------------------------------
// 1) instance conv + softmax. 128 CTAs, 4-way channel split, smem reduce.
// ---------------------------------------------------------------------------
__global__ __launch_bounds__(256) void mask_kernel(
    const float* __restrict__ x, const float* __restrict__ w_inst,
    const float* __restrict__ b_inst)
{
    __shared__ float ws[NI*CC];          // 8KB
    __shared__ float part[4][64][NI+1];  // padded: stride 9, conflict-free
    int tid = threadIdx.x;
    for (int k = tid; k < NI*CC; k += 256) ws[k] = w_inst[k];
    __syncthreads();

    int pl = tid & 63;
    int chunk = tid >> 6;                 // 0..3, 64 channels each
    int p = blockIdx.x*64 + pl;           // grid 128 -> 8192 positions
    int b = p >> 10, n = p & 1023;

    float acc[NI];
    #pragma unroll
    for (int i = 0; i < NI; i++) acc[i] = 0.f;
    const float* xp = x + ((size_t)b*CC + chunk*64)*HWN + n;
    const float* wsp = ws + chunk*64;
    #pragma unroll 4
    for (int c = 0; c < 64; c++) {
        float xv = xp[(size_t)c*HWN];
        #pragma unroll
        for (int i = 0; i < NI; i++) acc[i] = fmaf(wsp[i*CC + c], xv, acc[i]);
    }
    #pragma unroll
    for (int i = 0; i < NI; i++) part[chunk][pl][i] = acc[i];
    __syncthreads();

    if (tid < 64) {
        int pp = blockIdx.x*64 + tid;
        int bb = pp >> 10, nn = pp & 1023;
        float a[NI];
        float m = -1e30f;
        #pragma unroll
        for (int i = 0; i < NI; i++) {
            a[i] = part[0][tid][i] + part[1][tid][i]
                 + part[2][tid][i] + part[3][tid][i] + b_inst[i];
            m = fmaxf(m, a[i]);
        }
        float s = 0.f;
        #pragma unroll
        for (int i = 0; i < NI; i++) { a[i] = __expf(a[i] - m); s += a[i]; }
        float inv = 1.f / s;
        #pragma unroll
        for (int i = 0; i < NI; i++) g_mask[(bb*NI + i)*HWN + nn] = a[i]*inv;
    }
}

// ---------------------------------------------------------------------------
// 1b) materialize masked x as fp16 per (ib): xm16[ib][c][n] = x[b][c][n]*mask
// ---------------------------------------------------------------------------
__global__ __launch_bounds__(256) void xmask_kernel(const float* __restrict__ x)
{
    int idx = blockIdx.x*256 + threadIdx.x;       // 2^21 threads, 8 halves each
    size_t e = (size_t)idx * 8;
    int ib = (int)(e >> 18);
    int rem = (int)(e & 262143);
    int c = rem >> 10, n = rem & 1023;
    int b = ib & 7, inst = ib >> 3;

    const float* xp = &x[((size_t)b*CC + c)*HWN + n];
    const float* mp = &g_mask[(b*NI + inst)*HWN + n];
    float4 x0 = *(const float4*)&xp[0];
    float4 x1 = *(const float4*)&xp[4];
    float4 m0 = *(const float4*)&mp[0];
    float4 m1 = *(const float4*)&mp[4];
    uint4 o;
    o.x = packh2(x0.x*m0.x, x0.y*m0.y);
    o.y = packh2(x0.z*m0.z, x0.w*m0.w);
    o.z = packh2(x1.x*m1.x, x1.y*m1.y);
    o.w = packh2(x1.z*m1.z, x1.w*m1.w);
    *(uint4*)&g_xm16[e] = o;
}

// ---------------------------------------------------------------------------
// 2a) concat weights into fp16 [768][256]; biases fp32
// ---------------------------------------------------------------------------
__global__ __launch_bounds__(256) void prep_kernel(
    const float* __restrict__ wq, const float* __restrict__ bq,
    const float* __restrict__ wk, const float* __restrict__ bk,
    const float* __restrict__ wv, const float* __restrict__ bv)
{
    int idx = blockIdx.x*256 + threadIdx.x;
    if (idx < CC*CC) {
        g_w16[idx]           = __float2half_rn(wq[idx]);
        g_w16[CC*CC + idx]   = __float2half_rn(wk[idx]);
        g_w16[2*CC*CC + idx] = __float2half_rn(wv[idx]);
    }
    if (idx < CC) { g_b3[idx] = bq[idx]; g_b3[CC+idx] = bk[idx]; g_b3[2*CC+idx] = bv[idx]; }
}

// ---------------------------------------------------------------------------
// 2b) QKV GEMM: A = W fp16, B = xm16, 3-stage cp.async (1 barrier/iter).
// ---------------------------------------------------------------------------
#define QKV_SMEM_BYTES 98304   // 3 stages x (A 16K | B 16K)

__global__ __launch_bounds__(256) void qkv_mma()
{
    extern __shared__ char sm[];
    __shared__ float s_bias[128];

    uint32_t sbase = smem_to_u32(sm);

    int tid = threadIdx.x;
    int wid = tid >> 5, lane = tid & 31;
    int n0 = blockIdx.x * 128;
    int o0 = blockIdx.y * 128;
    int ib = blockIdx.z;

    if (tid < 128) s_bias[tid] = g_b3[o0 + tid];

    const __half* xm = g_xm16 + (size_t)ib*CC*HWN + n0;

    auto issue_stage = [&](int st, int kc) {
        uint32_t base = (uint32_t)st * 32768u;
        const __half* wp = g_w16 + (size_t)o0*CC + kc*64;
        #pragma unroll
        for (int i = 0; i < 4; i++) {
            int e = i*256 + tid;
            int m = e >> 3, cq = (e & 7) * 8;
            uint32_t off = (uint32_t)m*128 + (((uint32_t)cq*2) ^ (((uint32_t)m & 7) << 4));
            cp_async16(sbase + base + off, &wp[(size_t)m*CC + cq]);
        }
        #pragma unroll
        for (int i = 0; i < 4; i++) {
            int e = i*256 + tid;
            int c = e >> 4, n8 = (e & 15) * 8;
            uint32_t off = (uint32_t)c*256 + (((uint32_t)n8*2) ^ (((uint32_t)c & 7) << 4));
            cp_async16(sbase + base + 16384 + off, &xm[(size_t)(kc*64 + c)*HWN + n8]);
        }
    };

    float acc[2][8][4];
    #pragma unroll
    for (int mt = 0; mt < 2; mt++)
        #pragma unroll
        for (int nt = 0; nt < 8; nt++)
            #pragma unroll
            for (int q = 0; q < 4; q++) acc[mt][nt][q] = 0.f;

    const int m0w = (wid & 3) * 32;
    const int n0w = (wid >> 2) * 64;

    issue_stage(0, 0); CP_COMMIT();
    issue_stage(1, 1); CP_COMMIT();

    #pragma unroll 1
    for (int kc = 0; kc < 4; kc++) {
        int st = kc % 3;
        if (kc < 3) { CP_WAIT(1); } else { CP_WAIT(0); }
        __syncthreads();
        if (kc < 2) { issue_stage((kc + 2) % 3, kc + 2); CP_COMMIT(); }

        uint32_t AS = (uint32_t)st*32768u, BS = AS + 16384;

        #pragma unroll
        for (int ks = 0; ks < 4; ks++) {
            uint32_t ah[2][4];
            #pragma unroll
            for (int mt = 0; mt < 2; mt++) {
                uint32_t row = m0w + mt*16 + (lane & 7) + ((lane >> 3) & 1) * 8;
                uint32_t kb  = (uint32_t)ks*32 + (lane >> 4) * 16;
                uint32_t off = row*128 + (kb ^ ((row & 7) << 4));
                ldsm4(ah[mt], sbase + AS + off);
            }
            uint32_t bf[4][4];
            #pragma unroll
            for (int g = 0; g < 4; g++) {
                uint32_t rowc = (uint32_t)ks*16 + (lane & 7) + ((lane >> 3) & 1) * 8;
                uint32_t nb   = ((uint32_t)n0w + g*16 + (lane >> 4) * 8) * 2;
                uint32_t off  = rowc*256 + (nb ^ ((rowc & 7) << 4));
                ldsm4t(bf[g], sbase + BS + off);
            }
            #pragma unroll
            for (int mt = 0; mt < 2; mt++)
                #pragma unroll
                for (int nt = 0; nt < 8; nt++)
                    mma_f16(acc[mt][nt], ah[mt], &bf[nt >> 1][(nt & 1) * 2]);
        }
    }

    // ---- epilogue: bias + fp16 store, unified q/k/v destinations ----
    __half* dstb;
    {
        int sel = (o0 < 256) ? 0 : (o0 < 512) ? 1 : 2;
        int vo = o0 - sel*256;
        __half* bases = (sel == 0) ? g_q16 : (sel == 1) ? g_k16 : g_v16;
        dstb = bases + ((size_t)ib*CC + vo)*HWN + n0;
    }
    #pragma unroll
    for (int mt = 0; mt < 2; mt++) {
        int o_lo = m0w + mt*16 + (lane >> 2);
        float bias0 = s_bias[o_lo];
        float bias8 = s_bias[o_lo + 8];
        #pragma unroll
        for (int nt = 0; nt < 8; nt++) {
            int n_col = n0w + nt*8 + (lane & 3)*2;
            *(uint32_t*)&dstb[(size_t)o_lo*HWN + n_col] =
                packh2(acc[mt][nt][0] + bias0, acc[mt][nt][1] + bias0);
            *(uint32_t*)&dstb[(size_t)(o_lo+8)*HWN + n_col] =
                packh2(acc[mt][nt][2] + bias8, acc[mt][nt][3] + bias8);
        }
    }
}

// ---------------------------------------------------------------------------
// 3) l2-normalize q,k rows IN PLACE, warp-per-row (no block barrier).
//    q rows additionally scaled by 0.125*log2(e).
// ---------------------------------------------------------------------------
__global__ __launch_bounds__(256) void l2norm_kernel()
{
    int row = blockIdx.x*8 + (threadIdx.x >> 5);  // grid 4096 -> NB*512 rows
    int lane = threadIdx.x & 31;
    int ib = row >> 9;
    int o = row & 511;
    __half* p = (o < 256) ? &g_q16[((size_t)ib*CC + o)*HWN]
                          : &g_k16[((size_t)ib*CC + (o - 256))*HWN];
    uint4 w[4];
    float ss = 0.f;
    #pragma unroll
    for (int j = 0; j < 4; j++) {
        w[j] = *(uint4*)&p[j*256 + lane*8];
        const uint32_t* u = (const uint32_t*)&w[j];
        #pragma unroll
        for (int q = 0; q < 4; q++) {
            float2 f = __half22float2(*(const __half2*)&u[q]);
            ss = fmaf(f.x, f.x, fmaf(f.y, f.y, ss));
        }
    }
    #pragma unroll
    for (int off = 16; off; off >>= 1) ss += __shfl_xor_sync(0xffffffffu, ss, off);
    float inv = 1.f / fmaxf(sqrtf(ss), 1e-12f);
    if (o < 256) inv *= 0.18033688011112042f;   // 0.125 * log2(e)
    #pragma unroll
    for (int j = 0; j < 4; j++) {
        uint32_t* u = (uint32_t*)&w[j];
        #pragma unroll
        for (int q = 0; q < 4; q++) {
            float2 f = __half22float2(*(const __half2*)&u[q]);
            u[q] = packh2(f.x*inv, f.y*inv);
        }
        *(uint4*)&p[j*256 + lane*8] = w[j];
    }
}

// ---------------------------------------------------------------------------
// 4) flash attention, fp16 mma.sync, 3-buffer cp.async (1 barrier/iter).
//    Max-free exp2 softmax; row sums via ones-column MMA.
//    Epilogue folds instance mask into normalization; fp16 output.
// ---------------------------------------------------------------------------
#define FL_SMEM 114688   // Q 16K | 3 x (K 16K | V 16K)

__global__ __launch_bounds__(256) void flash_mma()
{
    extern __shared__ char sm[];
    __shared__ float s_mask[128];
    const uint32_t Qo = 0;
    const uint32_t Kb[3] = {16384, 49152, 81920};
    const uint32_t Vb[3] = {32768, 65536, 98304};
    uint32_t sbase = smem_to_u32(sm);

    int tid = threadIdx.x, wid = tid >> 5, lane = tid & 31;
    int it = blockIdx.x, h = blockIdx.y, ib = blockIdx.z;
    int i0 = it * 128;
    int m0w = wid * 16;
    int b = ib & 7, inst = ib >> 3;

    const __half* q16 = g_q16 + ((size_t)ib*CC + h*HD)*HWN;
    const __half* k16 = g_k16 + ((size_t)ib*CC + h*HD)*HWN;
    const __half* v16 = g_v16 + ((size_t)ib*CC + h*HD)*HWN;

    // Q tile (once) + mask row for this i-tile
    #pragma unroll
    for (int i = 0; i < 4; i++) {
        int e = i*256 + tid;
        int c = e >> 4, t = (e & 15) * 8;
        uint32_t off = (uint32_t)c*256 + (((uint32_t)t*2) ^ (((uint32_t)c & 7) << 4));
        *(uint4*)(sm + Qo + off) = *(const uint4*)&q16[(size_t)c*HWN + i0 + t];
    }
    if (tid < 128) s_mask[tid] = g_mask[(b*NI + inst)*HWN + i0 + tid];

    auto issue_tile = [&](int buf, int j0) {
        #pragma unroll
        for (int i = 0; i < 4; i++) {
            int e = i*256 + tid;
            int c = e >> 4, t = (e & 15) * 8;
            uint32_t off = (uint32_t)c*256 + (((uint32_t)t*2) ^ (((uint32_t)c & 7) << 4));
            cp_async16(sbase + Kb[buf] + off, &k16[(size_t)c*HWN + j0 + t]);
            cp_async16(sbase + Vb[buf] + off, &v16[(size_t)c*HWN + j0 + t]);
        }
    };

    float o[8][4];
    #pragma unroll
    for (int n = 0; n < 8; n++)
        #pragma unroll
        for (int q = 0; q < 4; q++) o[n][q] = 0.f;
    float psum[4] = {0.f, 0.f, 0.f, 0.f};
    const uint32_t ones2[2] = {0x3C003C00u, 0x3C003C00u};

    issue_tile(0, 0);   CP_COMMIT();
    issue_tile(1, 128); CP_COMMIT();

    #pragma unroll 1
    for (int jt = 0; jt < 8; jt++) {
        int buf = jt % 3;
        if (jt < 7) { CP_WAIT(1); } else { CP_WAIT(0); }
        __syncthreads();
        if (jt < 6) { issue_tile((jt + 2) % 3, (jt + 2) * 128); CP_COMMIT(); }

        uint32_t Ko = Kb[buf], Vo = Vb[buf];

        // ---- S = Q^T K (log2-domain, pre-scaled q) ----
        float s[16][4];
        #pragma unroll
        for (int j = 0; j < 16; j++)
            #pragma unroll
            for (int q = 0; q < 4; q++) s[j][q] = 0.f;

        #pragma unroll
        for (int ks = 0; ks < 4; ks++) {
            uint32_t ah[4];
            {
                uint32_t c = (uint32_t)ks*16 + (lane & 7) + ((lane >> 4) & 1) * 8;
                uint32_t t = (uint32_t)m0w + ((lane >> 3) & 1) * 8;
                uint32_t off = c*256 + ((t*2) ^ ((c & 7) << 4));
                ldsm4t(ah, sbase + Qo + off);
            }
            #pragma unroll
            for (int g = 0; g < 8; g++) {
                uint32_t bh[4];
                uint32_t c = (uint32_t)ks*16 + (lane & 7) + ((lane >> 3) & 1) * 8;
                uint32_t t = (uint32_t)g*16 + ((lane >> 4) & 1) * 8;
                uint32_t off = c*256 + ((t*2) ^ ((c & 7) << 4));
                ldsm4t(bh, sbase + Ko + off);
                mma_f16(s[g*2 + 0], ah, &bh[0]);
                mma_f16(s[g*2 + 1], ah, &bh[2]);
            }
        }

        // ---- P = exp2(S) directly in fp16x2 ----
        uint32_t hx[16][2];
        #pragma unroll
        for (int j = 0; j < 16; j++) {
            hx[j][0] = ex2h2(packh2(s[j][0], s[j][1]));
            hx[j][1] = ex2h2(packh2(s[j][2], s[j][3]));
        }

        // ---- O += P V^T ; row sums via ones-column MMA ----
        #pragma unroll
        for (int ks = 0; ks < 8; ks++) {
            uint32_t ph[4] = { hx[2*ks][0], hx[2*ks][1], hx[2*ks+1][0], hx[2*ks+1][1] };
            mma_f16(psum, ph, ones2);
            #pragma unroll
            for (int g = 0; g < 4; g++) {
                uint32_t bh[4];
                uint32_t d  = (uint32_t)g*16 + (lane & 7) + ((lane >> 4) & 1) * 8;
                uint32_t jb = (uint32_t)ks*32 + ((lane >> 3) & 1) * 16;
                uint32_t off = d*256 + (jb ^ ((d & 7) << 4));
                ldsm4(bh, sbase + Vo + off);
                mma_f16(o[g*2 + 0], ph, &bh[0]);
                mma_f16(o[g*2 + 1], ph, &bh[2]);
            }
        }
    }

    // ---- epilogue: mask/psum normalize, stage swizzled, fp16 store ----
    __syncthreads();    // all warps done with last tile before smem reuse
    float* outs = (float*)sm;   // [64 d][128 tok] fp32, word-XOR swizzle
    int r = lane >> 2;
    int tl = m0w + r, th = tl + 8;
    float inv0 = s_mask[tl] / psum[0];
    float inv1 = s_mask[th] / psum[2];
    #pragma unroll
    for (int n = 0; n < 8; n++) {
        int d0 = n*8 + (lane & 3)*2;
        int d1 = d0 + 1;
        outs[d0*128 + (tl ^ ((d0 & 7) << 2))] = o[n][0]*inv0;
        outs[d1*128 + (tl ^ ((d1 & 7) << 2))] = o[n][1]*inv0;
        outs[d0*128 + (th ^ ((d0 & 7) << 2))] = o[n][2]*inv1;
        outs[d1*128 + (th ^ ((d1 & 7) << 2))] = o[n][3]*inv1;
    }
    __syncthreads();
    __half* og = &g_att16[((size_t)ib*CC + h*HD)*HWN + i0];
    #pragma unroll
    for (int i = 0; i < 8; i++) {
        int e = i*256 + tid;
        int d = e >> 5, t4 = (e & 31) * 4;
        float4 val = *(const float4*)&outs[d*128 + (t4 ^ ((d & 7) << 2))];
        uint2 w;
        w.x = packh2(val.x, val.y);
        w.y = packh2(val.z, val.w);
        *(uint2*)&og[(size_t)d*HWN + t4] = w;
    }
}

// ---------------------------------------------------------------------------
// 5) out[b,c,n] = sum_i att16[i,b,c,n]  (mask already folded in)
// ---------------------------------------------------------------------------
__global__ __launch_bounds__(256) void out_kernel(float* __restrict__ out)
{
    int idx = blockIdx.x*256 + threadIdx.x;   // 2^19 threads x 4 elems
    size_t e = (size_t)idx * 4;               // < B*C*HW = 2^21
    int b = (int)(e >> 18);
    int rem = (int)(e & 262143);
    float a0 = 0.f, a1 = 0.f, a2 = 0.f, a3 = 0.f;
    #pragma unroll
    for (int i = 0; i < NI; i++) {
        uint2 w = *(const uint2*)&g_att16[(size_t)(i*BB + b)*262144 + rem];
        float2 f0 = __half22float2(*(const __half2*)&w.x);
        float2 f1 = __half22float2(*(const __half2*)&w.y);
        a0 += f0.x; a1 += f0.y; a2 += f1.x; a3 += f1.y;
    }
    float4 o = {a0, a1, a2, a3};
    *(float4*)&out[e] = o;
}

// ---------------------------------------------------------------------------
extern "C" void kernel_launch(void* const* d_in, const int* in_sizes, int n_in,
                              void* d_out, int out_size)
{
    const float* x      = (const float*)d_in[0];
    const float* w_inst = (const float*)d_in[1];
    const float* b_inst = (const float*)d_in[2];
    const float* w_q    = (const float*)d_in[3];
    const float* b_q    = (const float*)d_in[4];
    const float* w_k    = (const float*)d_in[5];
    const float* b_k    = (const float*)d_in[6];
    const float* w_v    = (const float*)d_in[7];
    const float* b_v    = (const float*)d_in[8];
    float* out = (float*)d_out;

    static bool attr_done = false;
    if (!attr_done) {
        cudaFuncSetAttribute(qkv_mma, cudaFuncAttributeMaxDynamicSharedMemorySize,
                             QKV_SMEM_BYTES);
        cudaFuncSetAttribute(flash_mma, cudaFuncAttributeMaxDynamicSharedMemorySize,
                             FL_SMEM);
        attr_done = true;
    }

    mask_kernel<<<128, 256>>>(x, w_inst, b_inst);
    prep_kernel<<<(CC*CC + 255)/256, 256>>>(w_q, b_q, w_k, b_k, w_v, b_v);
    xmask_kernel<<<8192, 256>>>(x);
    qkv_mma<<<dim3(8, 6, NB), 256, QKV_SMEM_BYTES>>>();
    l2norm_kernel<<<4096, 256>>>();
    flash_mma<<<dim3(8, NH, NB), 256, FL_SMEM>>>();
    out_kernel<<<2048, 256>>>(out);
}